// round 6
// baseline (speedup 1.0000x reference)
#include <cuda_runtime.h>
#include <cstdint>

// Problem dims
#define Vv 32000
#define Ee 128
#define Hh 128
#define Bb 32
#define Ss 32
#define RR 64                  // 64 fused rows: 0..31 teacher, 32..63 generation
#define NBLK 148               // persistent grid (1 block/SM, all resident)
#define NTHR 512
#define HS_STRIDE 80           // h_s row stride (floats): 320B = 16-mult, 2-way conflicts

static const int PRED_OFF = 2048;           // gen_x[1024] + gen_o[1024]
static const int PRED_N   = Bb * Ss * Vv;   // 32,768,000

// ---------------- persistent device scratch (no allocations allowed) -------
__device__ float               g_hbuf[2][RR * Hh];      // double-buffered h
__device__ float               g_c[RR * Hh];
__device__ float               g_xg[Ss * Bb * 4 * Hh];  // teacher x-gates (with bias)
__device__ float               g_sumexp[Ss * RR];
__device__ unsigned long long  g_packmax[Ss * Bb];
__device__ float               g_invse[Ss * Bb];        // indexed by b*S + t
__device__ float               g_loss;                  // sum of logit at target
__device__ int                 g_bar[2 * Ss];           // grid barrier counters

// ---------------- shared-memory layout (floats) ----------------------------
#define SM_HS    0                         // h_s[128][HS_STRIDE] transposed h
#define SM_XE    (SM_HS + 128 * HS_STRIDE)          // xe[32][129] gen embeddings
#define SM_WSM   (SM_XE + 32 * 129)                 // wsm[4][257] cell weights+bias
#define SM_GS    (SM_WSM + 4 * 257)                 // gs[4*64] gates
#define SM_WSUM  (SM_GS + 256)                      // wsum[16][64]
#define SM_WKEY  (SM_WSUM + 16 * 64)                // wkey[16][32] (ull, 8B-aligned)
#define SM_TGT   (SM_WKEY + 16 * 32 * 2)            // tgt[32] ints
#define SM_TOK   (SM_TGT + 32)                      // tok[32] ints
#define SM_FLOATS (SM_TOK + 32)
#define SMEM_BYTES (SM_FLOATS * 4)

// ---------------- helpers --------------------------------------------------
__device__ __forceinline__ float sigm(float x) { return 1.0f / (1.0f + expf(-x)); }

__device__ __forceinline__ unsigned f2ord(float f) {
    unsigned u = __float_as_uint(f);
    return (u & 0x80000000u) ? ~u : (u | 0x80000000u);
}
__device__ __forceinline__ float ord2f(unsigned o) {
    return __uint_as_float((o & 0x80000000u) ? (o ^ 0x80000000u) : ~o);
}

__device__ __forceinline__ unsigned long long fma2(unsigned long long a,
                                                   unsigned long long b,
                                                   unsigned long long c) {
    unsigned long long d;
    asm("fma.rn.f32x2 %0, %1, %2, %3;" : "=l"(d) : "l"(a), "l"(b), "l"(c));
    return d;
}
__device__ __forceinline__ unsigned long long pack2(float w) {
    unsigned long long d;
    unsigned u = __float_as_uint(w);
    asm("mov.b64 %0, {%1, %1};" : "=l"(d) : "r"(u));
    return d;
}
__device__ __forceinline__ void unpack2(unsigned long long a, float& lo, float& hi) {
    unsigned l, h;
    asm("mov.b64 {%0, %1}, %2;" : "=r"(l), "=r"(h) : "l"(a));
    lo = __uint_as_float(l);
    hi = __uint_as_float(h);
}

// grid-wide barrier: counter k, zeroed by prologue each launch
__device__ __forceinline__ void gbar(int k) {
    __syncthreads();
    if (threadIdx.x == 0) {
        __threadfence();
        atomicAdd(&g_bar[k], 1);
        while (*(volatile int*)&g_bar[k] < NBLK) { }
        __threadfence();
    }
    __syncthreads();
}

// v-span for GEMM phase: 32000 = 32*217 + 116*216
__device__ __forceinline__ void vspan(int bid, int& v0, int& n) {
    if (bid < 32) { v0 = bid * 217; n = 217; }
    else          { v0 = 6944 + (bid - 32) * 216; n = 216; }
}

// ---------------- prologue: teacher x-gates + barrier reset ----------------
__global__ void __launch_bounds__(512)
k_prologue(const int* __restrict__ x, const float* __restrict__ emb,
           const float* __restrict__ Wi, const float* __restrict__ bi,
           const float* __restrict__ Wf, const float* __restrict__ bf,
           const float* __restrict__ Wog, const float* __restrict__ bog,
           const float* __restrict__ Wc, const float* __restrict__ bc) {
    int p0 = blockIdx.x * 16;
    int tid = threadIdx.x;
    int g = tid >> 7, j = tid & 127;

    __shared__ int   tok_s[16];
    __shared__ float xe[16][Ee];

    if (blockIdx.x == 0) {
        if (tid < 2 * Ss) g_bar[tid] = 0;
        if (tid == 0) g_loss = 0.0f;
    }
    if (tid < 16) {
        int p = p0 + tid;
        int t = p >> 5, b = p & 31;
        tok_s[tid] = (t == 0) ? 0 : x[b * Ss + (t - 1)];
    }
    __syncthreads();
    for (int idx = tid; idx < 16 * Ee; idx += 512) {
        int pp = idx >> 7, kk = idx & 127;
        xe[pp][kk] = emb[tok_s[pp] * Ee + kk];
    }
    __syncthreads();

    const float* W = (g == 0) ? Wi : (g == 1) ? Wf : (g == 2) ? Wog : Wc;
    float bias = ((g == 0) ? bi : (g == 1) ? bf : (g == 2) ? bog : bc)[j];

    float acc[16];
#pragma unroll
    for (int pp = 0; pp < 16; ++pp) acc[pp] = bias;

#pragma unroll 4
    for (int k = 0; k < Ee; ++k) {
        float w = W[k * Hh + j];
#pragma unroll
        for (int pp = 0; pp < 16; ++pp) acc[pp] += xe[pp][k] * w;
    }
#pragma unroll
    for (int pp = 0; pp < 16; ++pp)
        g_xg[(p0 + pp) * 4 * Hh + tid] = acc[pp];
}

// ---------------- persistent fused recurrence ------------------------------
#define KB_STEP(KK, WREG)                                                       \
    {                                                                           \
        const ulonglong2* hp = (const ulonglong2*)(smf + SM_HS + (KK) * HS_STRIDE); \
        unsigned long long ww = pack2(WREG);                                    \
        _Pragma("unroll")                                                       \
        for (int p = 0; p < 16; ++p) {                                          \
            ulonglong2 hv = hp[p];                                              \
            acc[2 * p]     = fma2(hv.x, ww, acc[2 * p]);                        \
            acc[2 * p + 1] = fma2(hv.y, ww, acc[2 * p + 1]);                    \
        }                                                                       \
    }

__global__ void __launch_bounds__(NTHR, 1)
k_persist(const int* __restrict__ x, const float* __restrict__ emb,
          const float* __restrict__ Wi, const float* __restrict__ Ui, const float* __restrict__ bi,
          const float* __restrict__ Wf, const float* __restrict__ Uf, const float* __restrict__ bf,
          const float* __restrict__ Wog, const float* __restrict__ Uog, const float* __restrict__ bog,
          const float* __restrict__ Wc, const float* __restrict__ Uc, const float* __restrict__ bc,
          const float* __restrict__ Wo, const float* __restrict__ bo,
          float* __restrict__ out) {
    extern __shared__ float smf[];
    int tid = threadIdx.x, bid = blockIdx.x;
    int lane = tid & 31, wz = tid >> 5;
    const unsigned FULL = 0xFFFFFFFFu;
    bool iscell = (bid < 128);
    int j = bid;                          // cell column for cell blocks
    float* pred = out + PRED_OFF;
    int* tgt_s = (int*)(smf + SM_TGT);
    int* tok_s = (int*)(smf + SM_TOK);
    unsigned long long* wkey = (unsigned long long*)(smf + SM_WKEY);

    // one-time: cell blocks load their W/U column slice + bias into SMEM
    if (iscell) {
        for (int idx = tid; idx < 1024; idx += NTHR) {
            int g = idx >> 8, k = idx & 255;
            const float* W = (g == 0) ? Wi : (g == 1) ? Wf : (g == 2) ? Wog : Wc;
            const float* U = (g == 0) ? Ui : (g == 1) ? Uf : (g == 2) ? Uog : Uc;
            smf[SM_WSM + g * 257 + k] =
                (k < 128) ? W[k * Hh + j] : U[(k - 128) * Hh + j];
        }
        if (tid < 4) {
            const float* bv = (tid == 0) ? bi : (tid == 1) ? bf : (tid == 2) ? bog : bc;
            smf[SM_WSM + tid * 257 + 256] = bv[j];
        }
    }

    for (int t = 0; t < Ss; ++t) {
        int pb = t & 1;                   // h_prev buffer index

        // ================= cell phase =================
        if (iscell) {
            if (t == 0) {
                // h_s := 0 (h0 = 0); later steps reuse h_s staged by prev GEMM
                for (int idx = tid; idx < RR * Hh; idx += NTHR) {
                    int r = idx >> 7, k = idx & 127;
                    smf[SM_HS + k * HS_STRIDE + r] = 0.0f;
                }
                if (tid < Bb) tok_s[tid] = 0;
            } else if (tid < Bb) {
                unsigned long long key = g_packmax[(t - 1) * Bb + tid];
                tok_s[tid] = (int)(0xFFFFFFFFu - (unsigned)(key & 0xFFFFFFFFull));
            }
            __syncthreads();
            // stage gen embeddings
            for (int idx = tid; idx < Bb * Ee; idx += NTHR) {
                int r = idx >> 7, k = idx & 127;
                smf[SM_XE + r * 129 + k] = emb[tok_s[r] * Ee + k];
            }
            __syncthreads();

            if (tid < 256) {
                int g = tid >> 6, r = tid & 63;
                const float* wrow = smf + SM_WSM + g * 257;
                float a0 = 0.f, a1 = 0.f, a2 = 0.f, a3 = 0.f;
                if (r >= Bb) {
                    const float* xr = smf + SM_XE + (r - Bb) * 129;
#pragma unroll 8
                    for (int k = 0; k < 128; k += 4) {
                        a0 = fmaf(xr[k + 0], wrow[k + 0], a0);
                        a1 = fmaf(xr[k + 1], wrow[k + 1], a1);
                        a2 = fmaf(xr[k + 2], wrow[k + 2], a2);
                        a3 = fmaf(xr[k + 3], wrow[k + 3], a3);
                    }
                }
                const float* hc = smf + SM_HS + r;
#pragma unroll 8
                for (int k = 0; k < 128; k += 4) {
                    a0 = fmaf(hc[(k + 0) * HS_STRIDE], wrow[128 + k + 0], a0);
                    a1 = fmaf(hc[(k + 1) * HS_STRIDE], wrow[128 + k + 1], a1);
                    a2 = fmaf(hc[(k + 2) * HS_STRIDE], wrow[128 + k + 2], a2);
                    a3 = fmaf(hc[(k + 3) * HS_STRIDE], wrow[128 + k + 3], a3);
                }
                float base = (r < Bb)
                    ? g_xg[(t * Bb + r) * 4 * Hh + g * Hh + j]  // bias folded in
                    : wrow[256];                                 // bias
                smf[SM_GS + g * 64 + r] = base + ((a0 + a1) + (a2 + a3));
            }
            __syncthreads();
            if (tid < RR) {
                int r = tid;
                float cp = (t == 0) ? 0.0f : g_c[r * Hh + j];
                float ig = sigm(smf[SM_GS + 0 * 64 + r]);
                float fg = sigm(smf[SM_GS + 1 * 64 + r]);
                float og = sigm(smf[SM_GS + 2 * 64 + r]);
                float cn = fg * cp + ig * tanhf(smf[SM_GS + 3 * 64 + r]);
                float hn = og * tanhf(cn);
                g_c[r * Hh + j] = cn;
                g_hbuf[1 - pb][r * Hh + j] = hn;
            }
        } else if (bid == 128) {
            // zero this step's reduction accumulators
            if (tid < RR) g_sumexp[t * RR + tid] = 0.0f;
            else if (tid < RR + Bb) g_packmax[t * Bb + (tid - RR)] = 0ull;
        } else if (bid == 129 && t > 0) {
            // write gen_x/gen_o for step t-1
            if (tid < Bb) {
                unsigned long long key = g_packmax[(t - 1) * Bb + tid];
                int tok = (int)(0xFFFFFFFFu - (unsigned)(key & 0xFFFFFFFFull));
                out[tid * Ss + (t - 1)] = (float)tok;
                float lg = ord2f((unsigned)(key >> 32));
                out[Bb * Ss + tid * Ss + (t - 1)] =
                    expf(lg) / g_sumexp[(t - 1) * RR + Bb + tid];
            }
        }
        gbar(2 * t);

        // ================= GEMM phase (all blocks) =================
        // stage h_new transposed (this also pre-stages h for next cell phase)
        for (int idx = tid; idx < RR * Hh; idx += NTHR) {
            int r = idx >> 7, k = idx & 127;
            smf[SM_HS + k * HS_STRIDE + r] = g_hbuf[1 - pb][idx];
        }
        if (tid < Bb) tgt_s[tid] = x[tid * Ss + t];
        __syncthreads();

        int v0, span;
        vspan(bid, v0, span);
        bool act = (tid < span);
        int v = v0 + (act ? tid : 0);

        unsigned long long acc[32];
#pragma unroll
        for (int p = 0; p < 32; ++p) acc[p] = 0ull;

        if (act) {
            const float* Wp = Wo + v;
#pragma unroll 1
            for (int k0 = 0; k0 < Hh; k0 += 4) {
                float w0 = Wp[(k0 + 0) * Vv];
                float w1 = Wp[(k0 + 1) * Vv];
                float w2 = Wp[(k0 + 2) * Vv];
                float w3 = Wp[(k0 + 3) * Vv];
                KB_STEP(k0 + 0, w0)
                KB_STEP(k0 + 1, w1)
                KB_STEP(k0 + 2, w2)
                KB_STEP(k0 + 3, w3)
            }
        }

        float bo_v = act ? bo[v] : 0.0f;

        // teacher rows 0..31 (pairs q=0..15)
#pragma unroll
        for (int q = 0; q < 16; ++q) {
            float l0, l1;
            unpack2(acc[q], l0, l1);
#pragma unroll
            for (int h = 0; h < 2; ++h) {
                int b = 2 * q + h;
                float logit = (h == 0 ? l0 : l1) + bo_v;
                float e = 0.0f;
                if (act) {
                    pred[(b * Ss + t) * Vv + v] = logit;
                    if (v == tgt_s[b]) atomicAdd(&g_loss, logit);
                    e = expf(logit);
                }
                e += __shfl_down_sync(FULL, e, 16);
                e += __shfl_down_sync(FULL, e, 8);
                e += __shfl_down_sync(FULL, e, 4);
                e += __shfl_down_sync(FULL, e, 2);
                e += __shfl_down_sync(FULL, e, 1);
                if (lane == 0) smf[SM_WSUM + wz * 64 + b] = e;
            }
        }
        // gen rows 32..63 (pairs q=16..31)
#pragma unroll
        for (int q = 16; q < 32; ++q) {
            float l0, l1;
            unpack2(acc[q], l0, l1);
#pragma unroll
            for (int h = 0; h < 2; ++h) {
                int r = 2 * q + h;
                float logit = (h == 0 ? l0 : l1) + bo_v;
                float e = act ? expf(logit) : 0.0f;
                e += __shfl_down_sync(FULL, e, 16);
                e += __shfl_down_sync(FULL, e, 8);
                e += __shfl_down_sync(FULL, e, 4);
                e += __shfl_down_sync(FULL, e, 2);
                e += __shfl_down_sync(FULL, e, 1);
                if (lane == 0) smf[SM_WSUM + wz * 64 + r] = e;

                unsigned long long key = act
                    ? (((unsigned long long)f2ord(logit) << 32) |
                       (unsigned long long)(0xFFFFFFFFu - (unsigned)v))
                    : 0ull;
#pragma unroll
                for (int off = 16; off > 0; off >>= 1) {
                    unsigned long long o = __shfl_down_sync(FULL, key, off);
                    key = (o > key) ? o : key;
                }
                if (lane == 0) wkey[wz * 32 + (r - Bb)] = key;
            }
        }
        __syncthreads();

        if (tid < RR) {
            float s = 0.0f;
#pragma unroll
            for (int w = 0; w < 16; ++w) s += smf[SM_WSUM + w * 64 + tid];
            atomicAdd(&g_sumexp[t * RR + tid], s);
        } else if (tid < RR + Bb) {
            int gr = tid - RR;
            unsigned long long m = 0ull;
#pragma unroll
            for (int w = 0; w < 16; ++w) {
                unsigned long long k = wkey[w * 32 + gr];
                m = (k > m) ? k : m;
            }
            atomicMax(&g_packmax[t * Bb + gr], m);
        }
        gbar(2 * t + 1);
    }
}

// ---------------- epilogue 1: last gen outputs, loss, 1/sumexp -------------
__global__ void k_fin1(float* __restrict__ out) {
    __shared__ float red[1024];
    int tid = threadIdx.x;
    int t = tid >> 5, b = tid & 31;

    float se = g_sumexp[t * RR + b];            // teacher row b, step t
    red[tid] = logf(se);
    g_invse[b * Ss + t] = 1.0f / se;

    if (tid < Bb) {
        unsigned long long key = g_packmax[(Ss - 1) * Bb + tid];
        int tok = (int)(0xFFFFFFFFu - (unsigned)(key & 0xFFFFFFFFull));
        out[tid * Ss + (Ss - 1)] = (float)tok;
        float lg = ord2f((unsigned)(key >> 32));
        out[Bb * Ss + tid * Ss + (Ss - 1)] =
            expf(lg) / g_sumexp[(Ss - 1) * RR + Bb + tid];
    }
    __syncthreads();
    for (int s = 512; s > 0; s >>= 1) {
        if (tid < s) red[tid] += red[tid + s];
        __syncthreads();
    }
    if (tid == 0)
        out[PRED_OFF + PRED_N] = (red[0] - g_loss) / (float)(Ss * Bb);
}

// ---------------- epilogue 2: logits -> probs (in place, bulk) -------------
__global__ void k_probs(float* __restrict__ out) {
    int i = blockIdx.x * blockDim.x + threadIdx.x;       // 0 .. PRED_N/4-1
    int row = i / (Vv / 4);                              // = b*S + t
    float inv = g_invse[row];
    float4* p = ((float4*)(out + PRED_OFF)) + i;
    float4 l = *p;
    l.x = expf(l.x) * inv;
    l.y = expf(l.y) * inv;
    l.z = expf(l.z) * inv;
    l.w = expf(l.w) * inv;
    *p = l;
}

// ---------------- launch ---------------------------------------------------
extern "C" void kernel_launch(void* const* d_in, const int* in_sizes, int n_in,
                              void* d_out, int out_size) {
    const int*   x   = (const int*)d_in[0];
    const float* emb = (const float*)d_in[1];
    const float* Wi  = (const float*)d_in[2];
    const float* Ui  = (const float*)d_in[3];
    const float* bi  = (const float*)d_in[4];
    const float* Wf  = (const float*)d_in[5];
    const float* Uf  = (const float*)d_in[6];
    const float* bf  = (const float*)d_in[7];
    const float* Wog = (const float*)d_in[8];
    const float* Uog = (const float*)d_in[9];
    const float* bog = (const float*)d_in[10];
    const float* Wc  = (const float*)d_in[11];
    const float* Uc  = (const float*)d_in[12];
    const float* bc  = (const float*)d_in[13];
    const float* Wo  = (const float*)d_in[14];
    const float* bo  = (const float*)d_in[15];
    float* out = (float*)d_out;

    static int smem_set = 0;
    if (!smem_set) {
        cudaFuncSetAttribute(k_persist,
                             cudaFuncAttributeMaxDynamicSharedMemorySize,
                             SMEM_BYTES);
        smem_set = 1;
    }

    k_prologue<<<Ss * Bb / 16, 512>>>(x, emb, Wi, bi, Wf, bf, Wog, bog, Wc, bc);
    k_persist<<<NBLK, NTHR, SMEM_BYTES>>>(x, emb,
                                          Wi, Ui, bi, Wf, Uf, bf,
                                          Wog, Uog, bog, Wc, Uc, bc,
                                          Wo, bo, out);
    k_fin1<<<1, 1024>>>(out);
    k_probs<<<PRED_N / (256 * 4), 256>>>(out);
}

// round 7
// speedup vs baseline: 1.2482x; 1.2482x over previous
#include <cuda_runtime.h>
#include <cstdint>

// Problem dims
#define Vv 32000
#define Ee 128
#define Hh 128
#define Bb 32
#define Ss 32
#define RR 64                  // 64 fused rows: 0..31 teacher, 32..63 generation
#define NBLK 148               // persistent grid (1 block/SM, all resident)
#define NTHR 512
#define HS_STRIDE 68           // h_s row stride: 272B (16B-mult), 4-way conflicts

static const int PRED_OFF = 2048;           // gen_x[1024] + gen_o[1024]
static const int PRED_N   = Bb * Ss * Vv;   // 32,768,000

// ---------------- persistent device scratch (no allocations allowed) -------
__device__ float               g_hbuf[2][RR * Hh];      // double-buffered h
__device__ float               g_c[RR * Hh];
__device__ float               g_xg[Ss * Bb * 4 * Hh];  // teacher x-gates (with bias)
__device__ float               g_sumexp[Ss * RR];
__device__ unsigned long long  g_packmax[Ss * Bb];
__device__ float               g_invse[Ss * Bb];        // indexed by b*S + t
__device__ float               g_loss;                  // sum of logit at target
__device__ int                 g_bar[2 * Ss];           // grid barrier counters

// ---------------- shared-memory layout (floats) ----------------------------
#define SM_HS    0                                  // h_s[128][HS_STRIDE] transposed h
#define SM_XE    (SM_HS + 128 * HS_STRIDE)          // xe[32][129] gen embeddings
#define SM_WSM   (SM_XE + 32 * 129)                 // wsm[4][257] cell weights+bias
#define SM_GS    (SM_WSM + 4 * 257)                 // gs[4*64] gates
#define SM_WSUM  (SM_GS + 256)                      // wsum[16][64]
#define SM_WKEY  (SM_WSUM + 16 * 64)                // wkey[8][32] ull (8B-aligned)
#define SM_TGT   (SM_WKEY + 8 * 32 * 2)             // tgt[32] ints
#define SM_TOK   (SM_TGT + 32)                      // tok[32] ints
#define SM_FLOATS (SM_TOK + 32)
#define SMEM_BYTES (SM_FLOATS * 4)

// ---------------- helpers --------------------------------------------------
__device__ __forceinline__ float sigm(float x) { return 1.0f / (1.0f + expf(-x)); }

__device__ __forceinline__ unsigned f2ord(float f) {
    unsigned u = __float_as_uint(f);
    return (u & 0x80000000u) ? ~u : (u | 0x80000000u);
}
__device__ __forceinline__ float ord2f(unsigned o) {
    return __uint_as_float((o & 0x80000000u) ? (o ^ 0x80000000u) : ~o);
}

__device__ __forceinline__ unsigned long long fma2(unsigned long long a,
                                                   unsigned long long b,
                                                   unsigned long long c) {
    unsigned long long d;
    asm("fma.rn.f32x2 %0, %1, %2, %3;" : "=l"(d) : "l"(a), "l"(b), "l"(c));
    return d;
}
__device__ __forceinline__ unsigned long long pack2(float w) {
    unsigned long long d;
    unsigned u = __float_as_uint(w);
    asm("mov.b64 %0, {%1, %1};" : "=l"(d) : "r"(u));
    return d;
}
__device__ __forceinline__ void unpack2(unsigned long long a, float& lo, float& hi) {
    unsigned l, h;
    asm("mov.b64 {%0, %1}, %2;" : "=r"(l), "=r"(h) : "l"(a));
    lo = __uint_as_float(l);
    hi = __uint_as_float(h);
}

// grid-wide barrier: counter k, zeroed by prologue each launch
__device__ __forceinline__ void gbar(int k) {
    __syncthreads();
    if (threadIdx.x == 0) {
        __threadfence();
        atomicAdd(&g_bar[k], 1);
        while (*(volatile int*)&g_bar[k] < NBLK) { }
        __threadfence();
    }
    __syncthreads();
}

// v-span for GEMM phase: 32000 = 32*217 + 116*216
__device__ __forceinline__ void vspan(int bid, int& v0, int& n) {
    if (bid < 32) { v0 = bid * 217; n = 217; }
    else          { v0 = 6944 + (bid - 32) * 216; n = 216; }
}

// ---------------- prologue: teacher x-gates + barrier reset ----------------
__global__ void __launch_bounds__(512)
k_prologue(const int* __restrict__ x, const float* __restrict__ emb,
           const float* __restrict__ Wi, const float* __restrict__ bi,
           const float* __restrict__ Wf, const float* __restrict__ bf,
           const float* __restrict__ Wog, const float* __restrict__ bog,
           const float* __restrict__ Wc, const float* __restrict__ bc) {
    int p0 = blockIdx.x * 16;
    int tid = threadIdx.x;
    int g = tid >> 7, j = tid & 127;

    __shared__ int   tok_s[16];
    __shared__ float xe[16][Ee];

    if (blockIdx.x == 0) {
        if (tid < 2 * Ss) g_bar[tid] = 0;
        if (tid == 0) g_loss = 0.0f;
    }
    if (tid < 16) {
        int p = p0 + tid;
        int t = p >> 5, b = p & 31;
        tok_s[tid] = (t == 0) ? 0 : x[b * Ss + (t - 1)];
    }
    __syncthreads();
    for (int idx = tid; idx < 16 * Ee; idx += 512) {
        int pp = idx >> 7, kk = idx & 127;
        xe[pp][kk] = emb[tok_s[pp] * Ee + kk];
    }
    __syncthreads();

    const float* W = (g == 0) ? Wi : (g == 1) ? Wf : (g == 2) ? Wog : Wc;
    float bias = ((g == 0) ? bi : (g == 1) ? bf : (g == 2) ? bog : bc)[j];

    float acc[16];
#pragma unroll
    for (int pp = 0; pp < 16; ++pp) acc[pp] = bias;

#pragma unroll 4
    for (int k = 0; k < Ee; ++k) {
        float w = W[k * Hh + j];
#pragma unroll
        for (int pp = 0; pp < 16; ++pp) acc[pp] += xe[pp][k] * w;
    }
#pragma unroll
    for (int pp = 0; pp < 16; ++pp)
        g_xg[(p0 + pp) * 4 * Hh + tid] = acc[pp];
}

// ---------------- persistent fused recurrence ------------------------------
// GEMM phase row-tile: each thread covers 32 rows (its half), 16 ull accs.
#define KB_STEP(KK, WREG)                                                       \
    {                                                                           \
        const ulonglong2* hp =                                                  \
            (const ulonglong2*)(smf + SM_HS + (KK) * HS_STRIDE + half * 32);    \
        unsigned long long ww = pack2(WREG);                                    \
        _Pragma("unroll")                                                       \
        for (int p = 0; p < 8; ++p) {                                           \
            ulonglong2 hv = hp[p];                                              \
            acc[2 * p]     = fma2(hv.x, ww, acc[2 * p]);                        \
            acc[2 * p + 1] = fma2(hv.y, ww, acc[2 * p + 1]);                    \
        }                                                                       \
    }

__global__ void __launch_bounds__(NTHR, 1)
k_persist(const int* __restrict__ x, const float* __restrict__ emb,
          const float* __restrict__ Wi, const float* __restrict__ Ui, const float* __restrict__ bi,
          const float* __restrict__ Wf, const float* __restrict__ Uf, const float* __restrict__ bf,
          const float* __restrict__ Wog, const float* __restrict__ Uog, const float* __restrict__ bog,
          const float* __restrict__ Wc, const float* __restrict__ Uc, const float* __restrict__ bc,
          const float* __restrict__ Wo, const float* __restrict__ bo,
          float* __restrict__ out) {
    extern __shared__ float smf[];
    int tid = threadIdx.x, bid = blockIdx.x;
    int lane = tid & 31, wz = tid >> 5;
    const unsigned FULL = 0xFFFFFFFFu;
    bool iscell = (bid < 128);
    int j = bid;                          // cell column for cell blocks
    float* pred = out + PRED_OFF;
    int* tgt_s = (int*)(smf + SM_TGT);
    int* tok_s = (int*)(smf + SM_TOK);
    unsigned long long* wkey = (unsigned long long*)(smf + SM_WKEY);

    int half = tid >> 8;                  // GEMM: 0 = teacher rows, 1 = gen rows
    int lt = tid & 255;                   // lane within half

    // one-time: cell blocks load their W/U column slice + bias into SMEM
    if (iscell) {
        for (int idx = tid; idx < 1024; idx += NTHR) {
            int g = idx >> 8, k = idx & 255;
            const float* W = (g == 0) ? Wi : (g == 1) ? Wf : (g == 2) ? Wog : Wc;
            const float* U = (g == 0) ? Ui : (g == 1) ? Uf : (g == 2) ? Uog : Uc;
            smf[SM_WSM + g * 257 + k] =
                (k < 128) ? W[k * Hh + j] : U[(k - 128) * Hh + j];
        }
        if (tid < 4) {
            const float* bv = (tid == 0) ? bi : (tid == 1) ? bf : (tid == 2) ? bog : bc;
            smf[SM_WSM + tid * 257 + 256] = bv[j];
        }
    }

    for (int t = 0; t < Ss; ++t) {
        int pb = t & 1;                   // h_prev buffer index

        // ================= cell phase =================
        if (iscell) {
            if (t == 0) {
                // h_s := 0 (h0 = 0); later steps reuse h_s staged by prev GEMM
                for (int idx = tid; idx < RR * Hh; idx += NTHR) {
                    int k = idx & 127, r = idx >> 7;
                    smf[SM_HS + k * HS_STRIDE + r] = 0.0f;
                }
                if (tid < Bb) tok_s[tid] = 0;
            } else if (tid < Bb) {
                unsigned long long key = g_packmax[(t - 1) * Bb + tid];
                tok_s[tid] = (int)(0xFFFFFFFFu - (unsigned)(key & 0xFFFFFFFFull));
            }
            __syncthreads();
            // stage gen embeddings
            for (int idx = tid; idx < Bb * Ee; idx += NTHR) {
                int r = idx >> 7, k = idx & 127;
                smf[SM_XE + r * 129 + k] = emb[tok_s[r] * Ee + k];
            }
            __syncthreads();

            if (tid < 256) {
                int g = tid >> 6, r = tid & 63;
                const float* wrow = smf + SM_WSM + g * 257;
                float a0 = 0.f, a1 = 0.f, a2 = 0.f, a3 = 0.f;
                if (r >= Bb) {
                    const float* xr = smf + SM_XE + (r - Bb) * 129;
#pragma unroll 8
                    for (int k = 0; k < 128; k += 4) {
                        a0 = fmaf(xr[k + 0], wrow[k + 0], a0);
                        a1 = fmaf(xr[k + 1], wrow[k + 1], a1);
                        a2 = fmaf(xr[k + 2], wrow[k + 2], a2);
                        a3 = fmaf(xr[k + 3], wrow[k + 3], a3);
                    }
                }
                const float* hc = smf + SM_HS + r;
#pragma unroll 8
                for (int k = 0; k < 128; k += 4) {
                    a0 = fmaf(hc[(k + 0) * HS_STRIDE], wrow[128 + k + 0], a0);
                    a1 = fmaf(hc[(k + 1) * HS_STRIDE], wrow[128 + k + 1], a1);
                    a2 = fmaf(hc[(k + 2) * HS_STRIDE], wrow[128 + k + 2], a2);
                    a3 = fmaf(hc[(k + 3) * HS_STRIDE], wrow[128 + k + 3], a3);
                }
                float base = (r < Bb)
                    ? g_xg[(t * Bb + r) * 4 * Hh + g * Hh + j]  // bias folded in
                    : wrow[256];                                 // bias
                smf[SM_GS + g * 64 + r] = base + ((a0 + a1) + (a2 + a3));
            }
            __syncthreads();
            if (tid < RR) {
                int r = tid;
                float cp = (t == 0) ? 0.0f : g_c[r * Hh + j];
                float ig = sigm(smf[SM_GS + 0 * 64 + r]);
                float fg = sigm(smf[SM_GS + 1 * 64 + r]);
                float og = sigm(smf[SM_GS + 2 * 64 + r]);
                float cn = fg * cp + ig * tanhf(smf[SM_GS + 3 * 64 + r]);
                float hn = og * tanhf(cn);
                g_c[r * Hh + j] = cn;
                g_hbuf[1 - pb][r * Hh + j] = hn;
            }
        } else if (bid == 128) {
            // zero this step's reduction accumulators
            if (tid < RR) g_sumexp[t * RR + tid] = 0.0f;
            else if (tid < RR + Bb) g_packmax[t * Bb + (tid - RR)] = 0ull;
        } else if (bid == 129 && t > 0) {
            // write gen_x/gen_o for step t-1
            if (tid < Bb) {
                unsigned long long key = g_packmax[(t - 1) * Bb + tid];
                int tok = (int)(0xFFFFFFFFu - (unsigned)(key & 0xFFFFFFFFull));
                out[tid * Ss + (t - 1)] = (float)tok;
                float lg = ord2f((unsigned)(key >> 32));
                out[Bb * Ss + tid * Ss + (t - 1)] =
                    expf(lg) / g_sumexp[(t - 1) * RR + Bb + tid];
            }
        }
        gbar(2 * t);

        // ================= GEMM phase (all blocks) =================
        // stage h_new transposed (also pre-stages h for next cell phase)
        for (int idx = tid; idx < RR * Hh; idx += NTHR) {
            int k = idx & 127, r = idx >> 7;
            smf[SM_HS + k * HS_STRIDE + r] = g_hbuf[1 - pb][r * Hh + k];
        }
        if (tid < Bb) tgt_s[tid] = x[tid * Ss + t];
        __syncthreads();

        int v0, span;
        vspan(bid, v0, span);
        bool act = (lt < span);
        int v = v0 + (act ? lt : 0);

        unsigned long long acc[16];
#pragma unroll
        for (int p = 0; p < 16; ++p) acc[p] = 0ull;

        if (act) {
            const float* Wp = Wo + v;
#pragma unroll 1
            for (int k0 = 0; k0 < Hh; k0 += 4) {
                float w0 = Wp[(k0 + 0) * Vv];
                float w1 = Wp[(k0 + 1) * Vv];
                float w2 = Wp[(k0 + 2) * Vv];
                float w3 = Wp[(k0 + 3) * Vv];
                KB_STEP(k0 + 0, w0)
                KB_STEP(k0 + 1, w1)
                KB_STEP(k0 + 2, w2)
                KB_STEP(k0 + 3, w3)
            }
        }

        float bo_v = act ? bo[v] : 0.0f;

        if (half == 0) {
            // teacher rows 0..31: acc[q] = rows (2q, 2q+1)
#pragma unroll
            for (int q = 0; q < 16; ++q) {
                float l0, l1;
                unpack2(acc[q], l0, l1);
#pragma unroll
                for (int h = 0; h < 2; ++h) {
                    int b = 2 * q + h;
                    float logit = (h == 0 ? l0 : l1) + bo_v;
                    float e = 0.0f;
                    if (act) {
                        pred[(b * Ss + t) * Vv + v] = logit;
                        if (v == tgt_s[b]) atomicAdd(&g_loss, logit);
                        e = expf(logit);
                    }
                    e += __shfl_down_sync(FULL, e, 16);
                    e += __shfl_down_sync(FULL, e, 8);
                    e += __shfl_down_sync(FULL, e, 4);
                    e += __shfl_down_sync(FULL, e, 2);
                    e += __shfl_down_sync(FULL, e, 1);
                    if (lane == 0) smf[SM_WSUM + wz * 64 + b] = e;   // wz 0..7
                }
            }
        } else {
            // gen rows 32..63: acc[q] = rows (32+2q, 32+2q+1)
#pragma unroll
            for (int q = 0; q < 16; ++q) {
                float l0, l1;
                unpack2(acc[q], l0, l1);
#pragma unroll
                for (int h = 0; h < 2; ++h) {
                    int r = Bb + 2 * q + h;
                    float logit = (h == 0 ? l0 : l1) + bo_v;
                    float e = act ? expf(logit) : 0.0f;
                    e += __shfl_down_sync(FULL, e, 16);
                    e += __shfl_down_sync(FULL, e, 8);
                    e += __shfl_down_sync(FULL, e, 4);
                    e += __shfl_down_sync(FULL, e, 2);
                    e += __shfl_down_sync(FULL, e, 1);
                    if (lane == 0) smf[SM_WSUM + wz * 64 + r] = e;   // wz 8..15

                    unsigned long long key = act
                        ? (((unsigned long long)f2ord(logit) << 32) |
                           (unsigned long long)(0xFFFFFFFFu - (unsigned)v))
                        : 0ull;
#pragma unroll
                    for (int off = 16; off > 0; off >>= 1) {
                        unsigned long long o = __shfl_down_sync(FULL, key, off);
                        key = (o > key) ? o : key;
                    }
                    if (lane == 0) wkey[(wz - 8) * 32 + (r - Bb)] = key;
                }
            }
        }
        __syncthreads();

        if (tid < Bb) {
            // teacher sumexp: contributions live in warps 0..7
            float s = 0.0f;
#pragma unroll
            for (int w = 0; w < 8; ++w) s += smf[SM_WSUM + w * 64 + tid];
            atomicAdd(&g_sumexp[t * RR + tid], s);
        } else if (tid < RR) {
            // gen sumexp: warps 8..15
            float s = 0.0f;
#pragma unroll
            for (int w = 8; w < 16; ++w) s += smf[SM_WSUM + w * 64 + tid];
            atomicAdd(&g_sumexp[t * RR + tid], s);
        } else if (tid < RR + Bb) {
            int gr = tid - RR;
            unsigned long long m = 0ull;
#pragma unroll
            for (int w = 0; w < 8; ++w) {
                unsigned long long k = wkey[w * 32 + gr];
                m = (k > m) ? k : m;
            }
            atomicMax(&g_packmax[t * Bb + gr], m);
        }
        gbar(2 * t + 1);
    }
}

// ---------------- epilogue 1: last gen outputs, loss, 1/sumexp -------------
__global__ void k_fin1(float* __restrict__ out) {
    __shared__ float red[1024];
    int tid = threadIdx.x;
    int t = tid >> 5, b = tid & 31;

    float se = g_sumexp[t * RR + b];            // teacher row b, step t
    red[tid] = logf(se);
    g_invse[b * Ss + t] = 1.0f / se;

    if (tid < Bb) {
        unsigned long long key = g_packmax[(Ss - 1) * Bb + tid];
        int tok = (int)(0xFFFFFFFFu - (unsigned)(key & 0xFFFFFFFFull));
        out[tid * Ss + (Ss - 1)] = (float)tok;
        float lg = ord2f((unsigned)(key >> 32));
        out[Bb * Ss + tid * Ss + (Ss - 1)] =
            expf(lg) / g_sumexp[(Ss - 1) * RR + Bb + tid];
    }
    __syncthreads();
    for (int s = 512; s > 0; s >>= 1) {
        if (tid < s) red[tid] += red[tid + s];
        __syncthreads();
    }
    if (tid == 0)
        out[PRED_OFF + PRED_N] = (red[0] - g_loss) / (float)(Ss * Bb);
}

// ---------------- epilogue 2: logits -> probs (in place, bulk) -------------
__global__ void k_probs(float* __restrict__ out) {
    int i = blockIdx.x * blockDim.x + threadIdx.x;       // 0 .. PRED_N/4-1
    int row = i / (Vv / 4);                              // = b*S + t
    float inv = g_invse[row];
    float4* p = ((float4*)(out + PRED_OFF)) + i;
    float4 l = *p;
    l.x = expf(l.x) * inv;
    l.y = expf(l.y) * inv;
    l.z = expf(l.z) * inv;
    l.w = expf(l.w) * inv;
    *p = l;
}

// ---------------- launch ---------------------------------------------------
extern "C" void kernel_launch(void* const* d_in, const int* in_sizes, int n_in,
                              void* d_out, int out_size) {
    const int*   x   = (const int*)d_in[0];
    const float* emb = (const float*)d_in[1];
    const float* Wi  = (const float*)d_in[2];
    const float* Ui  = (const float*)d_in[3];
    const float* bi  = (const float*)d_in[4];
    const float* Wf  = (const float*)d_in[5];
    const float* Uf  = (const float*)d_in[6];
    const float* bf  = (const float*)d_in[7];
    const float* Wog = (const float*)d_in[8];
    const float* Uog = (const float*)d_in[9];
    const float* bog = (const float*)d_in[10];
    const float* Wc  = (const float*)d_in[11];
    const float* Uc  = (const float*)d_in[12];
    const float* bc  = (const float*)d_in[13];
    const float* Wo  = (const float*)d_in[14];
    const float* bo  = (const float*)d_in[15];
    float* out = (float*)d_out;

    cudaFuncSetAttribute(k_persist,
                         cudaFuncAttributeMaxDynamicSharedMemorySize,
                         SMEM_BYTES);

    k_prologue<<<Ss * Bb / 16, 512>>>(x, emb, Wi, bi, Wf, bf, Wog, bog, Wc, bc);
    k_persist<<<NBLK, NTHR, SMEM_BYTES>>>(x, emb,
                                          Wi, Ui, bi, Wf, Uf, bf,
                                          Wog, Uog, bog, Wc, Uc, bc,
                                          Wo, bo, out);
    k_fin1<<<1, 1024>>>(out);
    k_probs<<<PRED_N / (256 * 4), 256>>>(out);
}

// round 11
// speedup vs baseline: 1.7335x; 1.3888x over previous
#include <cuda_runtime.h>
#include <cuda_fp16.h>
#include <cstdint>

// Problem dims
#define Vv 32000
#define Ee 128
#define Hh 128
#define Bb 32
#define Ss 32
#define RR 64                  // 64 fused rows: 0..31 teacher, 32..63 generation
#define NBLK 148               // persistent grid (1 block/SM, all resident)
#define NTHR 512
#define HS_STRIDE 68           // h_s row stride
#define HP_STRIDE 72           // packed-h row stride (conflict-free B loads)
#define DS_STRIDE 66           // D staging row stride

static const int PRED_OFF = 2048;           // gen_x[1024] + gen_o[1024]
static const int PRED_N   = Bb * Ss * Vv;   // 32,768,000

// ---------------- persistent device scratch (no allocations allowed) -------
__device__ float               g_hbuf[2][RR * Hh];      // double-buffered h
__device__ float               g_c[RR * Hh];
__device__ float               g_xg[Ss * Bb * 4 * Hh];  // teacher x-gates (with bias)
__device__ float               g_sumexp[Ss * RR];
__device__ unsigned long long  g_packmax[Ss * Bb];
__device__ float               g_invse[Ss * Bb];        // indexed by b*S + t
__device__ float               g_loss;                  // sum of logit at target
__device__ int                 g_bar[2 * Ss];           // grid barrier counters
__device__ unsigned            g_w16h[64 * Vv];         // Wo fp16-hi pairs, [p][v]
__device__ unsigned            g_w16l[64 * Vv];         // Wo fp16-lo pairs, [p][v]

// ---------------- shared-memory layout (float words) -----------------------
#define SM_HS    0                          // h_s[128][HS_STRIDE] (8704)
#define SM_DS    8704                       // D staging [256][DS_STRIDE] (16896)
#define SM_XE    8704                       // alias: xe[32][129] (cell phase only)
#define SM_BHI   25600                      // hp_hi[64][HP_STRIDE] (4608)
#define SM_BLO   30208                      // hp_lo (4608)
#define SM_WSM   34816                      // wsm[4][257] cell weights+bias (1028)
#define SM_GS    35844                      // gates (256)
#define SM_WSUM  36100                      // wsum[16][64] (1024)
#define SM_WKEY  37124                      // wkey[8][32] ull (512 w, 8B-aligned)
#define SM_TGT   37636                      // tgt[32] ints
#define SM_TOK   37668                      // tok[32] ints
#define SM_FLOATS 37700
#define SMEM_BYTES (SM_FLOATS * 4)          // 150,800 B (< 227KB opt-in cap)

// ---------------- generic helpers ------------------------------------------
__device__ __forceinline__ float sigm(float x) { return 1.0f / (1.0f + __expf(-x)); }

__device__ __forceinline__ unsigned f2ord(float f) {
    unsigned u = __float_as_uint(f);
    return (u & 0x80000000u) ? ~u : (u | 0x80000000u);
}
__device__ __forceinline__ float ord2f(unsigned o) {
    return __uint_as_float((o & 0x80000000u) ? (o ^ 0x80000000u) : ~o);
}

// m16n8k16 f32.f16.f16.f32 (row.col), accumulate in place
__device__ __forceinline__ void mma16816(float& c0, float& c1, float& c2, float& c3,
                                         unsigned a0, unsigned a1, unsigned a2, unsigned a3,
                                         unsigned b0, unsigned b1) {
    asm volatile(
        "mma.sync.aligned.m16n8k16.row.col.f32.f16.f16.f32 "
        "{%0,%1,%2,%3}, {%4,%5,%6,%7}, {%8,%9}, {%0,%1,%2,%3};"
        : "+f"(c0), "+f"(c1), "+f"(c2), "+f"(c3)
        : "r"(a0), "r"(a1), "r"(a2), "r"(a3), "r"(b0), "r"(b1));
}

// grid-wide barrier: counter k, zeroed by prologue each launch
__device__ __forceinline__ void gbar(int k) {
    __syncthreads();
    if (threadIdx.x == 0) {
        __threadfence();
        atomicAdd(&g_bar[k], 1);
        while (*(volatile int*)&g_bar[k] < NBLK) { }
        __threadfence();
    }
    __syncthreads();
}

// v-span: 32000 = 32*217 + 116*216
__device__ __forceinline__ void vspan(int bid, int& v0, int& n) {
    if (bid < 32) { v0 = bid * 217; n = 217; }
    else          { v0 = 6944 + (bid - 32) * 216; n = 216; }
}

// ---------------- Wo fp16 split precompute ----------------------------------
// W16h/W16l[p*Vv + v] = packed fp16x2 of Wo[2p..2p+1][v] (hi) and residual (lo)
__global__ void __launch_bounds__(512)
k_split(const float* __restrict__ Wo) {
    int idx = blockIdx.x * 512 + threadIdx.x;   // = p*Vv + v
    int p = idx / Vv, v = idx - p * Vv;
    float w0 = Wo[(2 * p) * Vv + v];
    float w1 = Wo[(2 * p + 1) * Vv + v];
    __half h0 = __float2half_rn(w0), h1 = __float2half_rn(w1);
    __half l0 = __float2half_rn(w0 - __half2float(h0));
    __half l1 = __float2half_rn(w1 - __half2float(h1));
    g_w16h[idx] = ((unsigned)__half_as_ushort(h1) << 16) | __half_as_ushort(h0);
    g_w16l[idx] = ((unsigned)__half_as_ushort(l1) << 16) | __half_as_ushort(l0);
}

// ---------------- prologue: teacher x-gates + barrier reset ----------------
__global__ void __launch_bounds__(512)
k_prologue(const int* __restrict__ x, const float* __restrict__ emb,
           const float* __restrict__ Wi, const float* __restrict__ bi,
           const float* __restrict__ Wf, const float* __restrict__ bf,
           const float* __restrict__ Wog, const float* __restrict__ bog,
           const float* __restrict__ Wc, const float* __restrict__ bc) {
    int p0 = blockIdx.x * 16;
    int tid = threadIdx.x;
    int g = tid >> 7, j = tid & 127;

    __shared__ int   tok_s[16];
    __shared__ float xe[16][Ee];

    if (blockIdx.x == 0) {
        if (tid < 2 * Ss) g_bar[tid] = 0;
        if (tid == 0) g_loss = 0.0f;
    }
    if (tid < 16) {
        int p = p0 + tid;
        int t = p >> 5, b = p & 31;
        tok_s[tid] = (t == 0) ? 0 : x[b * Ss + (t - 1)];
    }
    __syncthreads();
    for (int idx = tid; idx < 16 * Ee; idx += 512) {
        int pp = idx >> 7, kk = idx & 127;
        xe[pp][kk] = emb[tok_s[pp] * Ee + kk];
    }
    __syncthreads();

    const float* W = (g == 0) ? Wi : (g == 1) ? Wf : (g == 2) ? Wog : Wc;
    float bias = ((g == 0) ? bi : (g == 1) ? bf : (g == 2) ? bog : bc)[j];

    float acc[16];
#pragma unroll
    for (int pp = 0; pp < 16; ++pp) acc[pp] = bias;

#pragma unroll 4
    for (int k = 0; k < Ee; ++k) {
        float w = W[k * Hh + j];
#pragma unroll
        for (int pp = 0; pp < 16; ++pp) acc[pp] += xe[pp][k] * w;
    }
#pragma unroll
    for (int pp = 0; pp < 16; ++pp)
        g_xg[(p0 + pp) * 4 * Hh + tid] = acc[pp];
}

// ---------------- persistent fused recurrence (mma.sync GEMM) --------------
__global__ void __launch_bounds__(NTHR, 1)
k_persist(const int* __restrict__ x, const float* __restrict__ emb,
          const float* __restrict__ Wi, const float* __restrict__ Ui, const float* __restrict__ bi,
          const float* __restrict__ Wf, const float* __restrict__ Uf, const float* __restrict__ bf,
          const float* __restrict__ Wog, const float* __restrict__ Uog, const float* __restrict__ bog,
          const float* __restrict__ Wc, const float* __restrict__ Uc, const float* __restrict__ bc,
          const float* __restrict__ bo, float* __restrict__ out) {
    extern __shared__ float smf[];
    int tid = threadIdx.x, bid = blockIdx.x;
    int lane = tid & 31, wz = tid >> 5;
    const unsigned FULL = 0xFFFFFFFFu;
    bool iscell = (bid < 128);
    int j = bid;
    float* pred = out + PRED_OFF;
    int* tgt_s = (int*)(smf + SM_TGT);
    int* tok_s = (int*)(smf + SM_TOK);
    unsigned long long* wkey = (unsigned long long*)(smf + SM_WKEY);

    // one-time: cell blocks load their W/U column slice + bias into SMEM
    if (iscell) {
        for (int idx = tid; idx < 1024; idx += NTHR) {
            int g = idx >> 8, k = idx & 255;
            const float* W = (g == 0) ? Wi : (g == 1) ? Wf : (g == 2) ? Wog : Wc;
            const float* U = (g == 0) ? Ui : (g == 1) ? Uf : (g == 2) ? Uog : Uc;
            smf[SM_WSM + g * 257 + k] =
                (k < 128) ? W[k * Hh + j] : U[(k - 128) * Hh + j];
        }
        if (tid < 4) {
            const float* bv = (tid == 0) ? bi : (tid == 1) ? bf : (tid == 2) ? bog : bc;
            smf[SM_WSM + tid * 257 + 256] = bv[j];
        }
    }

    int v0, span;
    vspan(bid, v0, span);

    int gid = lane >> 2, tig = lane & 3;   // mma fragment coords

    // epilogue role: warps 0-7 teacher rows, 8-15 gen rows; v = (wz&7)*32+lane
    int ehalf = wz >> 3;
    int evl = (wz & 7) * 32 + lane;        // 0..255 (capacity >= span)
    bool eact = (evl < span);
    int ev = v0 + (eact ? evl : 0);

    for (int t = 0; t < Ss; ++t) {
        int nb = 1 - (t & 1);              // h_t buffer written by cell

        // ================= cell phase =================
        if (iscell) {
            if (t == 0) {
                for (int idx = tid; idx < RR * Hh; idx += NTHR) {
                    int k = idx & 127, r = idx >> 7;
                    smf[SM_HS + k * HS_STRIDE + r] = 0.0f;
                }
                if (tid < Bb) tok_s[tid] = 0;
            } else if (tid < Bb) {
                unsigned long long key = g_packmax[(t - 1) * Bb + tid];
                tok_s[tid] = (int)(0xFFFFFFFFu - (unsigned)(key & 0xFFFFFFFFull));
            }
            __syncthreads();
            for (int idx = tid; idx < Bb * Ee; idx += NTHR) {
                int r = idx >> 7, k = idx & 127;
                smf[SM_XE + r * 129 + k] = emb[tok_s[r] * Ee + k];
            }
            __syncthreads();

            if (tid < 256) {
                int g = tid >> 6, r = tid & 63;
                const float* wrow = smf + SM_WSM + g * 257;
                float a0 = 0.f, a1 = 0.f, a2 = 0.f, a3 = 0.f;
                if (r >= Bb) {
                    const float* xr = smf + SM_XE + (r - Bb) * 129;
#pragma unroll 8
                    for (int k = 0; k < 128; k += 4) {
                        a0 = fmaf(xr[k + 0], wrow[k + 0], a0);
                        a1 = fmaf(xr[k + 1], wrow[k + 1], a1);
                        a2 = fmaf(xr[k + 2], wrow[k + 2], a2);
                        a3 = fmaf(xr[k + 3], wrow[k + 3], a3);
                    }
                }
                const float* hc = smf + SM_HS + r;
#pragma unroll 8
                for (int k = 0; k < 128; k += 4) {
                    a0 = fmaf(hc[(k + 0) * HS_STRIDE], wrow[128 + k + 0], a0);
                    a1 = fmaf(hc[(k + 1) * HS_STRIDE], wrow[128 + k + 1], a1);
                    a2 = fmaf(hc[(k + 2) * HS_STRIDE], wrow[128 + k + 2], a2);
                    a3 = fmaf(hc[(k + 3) * HS_STRIDE], wrow[128 + k + 3], a3);
                }
                float base = (r < Bb)
                    ? g_xg[(t * Bb + r) * 4 * Hh + g * Hh + j]
                    : wrow[256];
                smf[SM_GS + g * 64 + r] = base + ((a0 + a1) + (a2 + a3));
            }
            __syncthreads();
            if (tid < RR) {
                int r = tid;
                float cp = (t == 0) ? 0.0f : g_c[r * Hh + j];
                float ig = sigm(smf[SM_GS + 0 * 64 + r]);
                float fg = sigm(smf[SM_GS + 1 * 64 + r]);
                float og = sigm(smf[SM_GS + 2 * 64 + r]);
                float cn = fg * cp + ig * tanhf(smf[SM_GS + 3 * 64 + r]);
                float hn = og * tanhf(cn);
                g_c[r * Hh + j] = cn;
                g_hbuf[nb][r * Hh + j] = hn;
            }
        } else if (bid == 128) {
            if (tid < RR) g_sumexp[t * RR + tid] = 0.0f;
            else if (tid < RR + Bb) g_packmax[t * Bb + (tid - RR)] = 0ull;
        } else if (bid == 129 && t > 0) {
            if (tid < Bb) {
                unsigned long long key = g_packmax[(t - 1) * Bb + tid];
                int tok = (int)(0xFFFFFFFFu - (unsigned)(key & 0xFFFFFFFFull));
                out[tid * Ss + (t - 1)] = (float)tok;
                float lg = ord2f((unsigned)(key >> 32));
                out[Bb * Ss + tid * Ss + (t - 1)] =
                    __expf(lg) / g_sumexp[(t - 1) * RR + Bb + tid];
            }
        }
        gbar(2 * t);

        // ================= GEMM phase (all blocks) =================
        const float* hsrc = g_hbuf[nb];

        // h_sT for next cell phase
        for (int idx = tid; idx < RR * Hh; idx += NTHR) {
            int k = idx & 127, r = idx >> 7;
            smf[SM_HS + k * HS_STRIDE + r] = hsrc[r * Hh + k];
        }
        // B = h split fp16 hi/lo pair-packed: hp[p][n], p = k-pair
        {
            unsigned* BH = (unsigned*)(smf + SM_BHI);
            unsigned* BL = (unsigned*)(smf + SM_BLO);
            for (int idx = tid; idx < 64 * 64; idx += NTHR) {
                int p = idx >> 6, n = idx & 63;
                float2 hv = *(const float2*)(hsrc + n * Hh + 2 * p);
                __half h0 = __float2half_rn(hv.x), h1 = __float2half_rn(hv.y);
                __half l0 = __float2half_rn(hv.x - __half2float(h0));
                __half l1 = __float2half_rn(hv.y - __half2float(h1));
                BH[p * HP_STRIDE + n] =
                    ((unsigned)__half_as_ushort(h1) << 16) | __half_as_ushort(h0);
                BL[p * HP_STRIDE + n] =
                    ((unsigned)__half_as_ushort(l1) << 16) | __half_as_ushort(l0);
            }
        }
        if (tid < Bb) tgt_s[tid] = x[tid * Ss + t];
        __syncthreads();

        // mma compute: warp wz handles m-tile wz (14 tiles cover span<=224)
        if (wz < 14) {
            int vA = v0 + wz * 16 + gid;
            int vAc  = (vA < Vv) ? vA : (Vv - 1);
            int vA8c = (vA + 8 < Vv) ? (vA + 8) : (Vv - 1);
            float acc[8][4];
#pragma unroll
            for (int nt = 0; nt < 8; ++nt) {
                acc[nt][0] = 0.f; acc[nt][1] = 0.f;
                acc[nt][2] = 0.f; acc[nt][3] = 0.f;
            }
            const unsigned* BHg = (const unsigned*)(smf + SM_BHI) + gid;
            const unsigned* BLg = (const unsigned*)(smf + SM_BLO) + gid;
#pragma unroll 1
            for (int k0 = 0; k0 < 8; ++k0) {
                int pA = k0 * 8 + tig;
                const unsigned* Wh = g_w16h + pA * Vv;
                const unsigned* Wl = g_w16l + pA * Vv;
                unsigned ah0 = Wh[vAc],          ah1 = Wh[vA8c];
                unsigned ah2 = Wh[4 * Vv + vAc], ah3 = Wh[4 * Vv + vA8c];
                unsigned al0 = Wl[vAc],          al1 = Wl[vA8c];
                unsigned al2 = Wl[4 * Vv + vAc], al3 = Wl[4 * Vv + vA8c];
                const unsigned* BHp = BHg + pA * HP_STRIDE;
                const unsigned* BLp = BLg + pA * HP_STRIDE;
#pragma unroll
                for (int nt = 0; nt < 8; ++nt) {
                    unsigned bh0 = BHp[nt * 8];
                    unsigned bh1 = BHp[4 * HP_STRIDE + nt * 8];
                    unsigned bl0 = BLp[nt * 8];
                    unsigned bl1 = BLp[4 * HP_STRIDE + nt * 8];
                    mma16816(acc[nt][0], acc[nt][1], acc[nt][2], acc[nt][3],
                             ah0, ah1, ah2, ah3, bh0, bh1);
                    mma16816(acc[nt][0], acc[nt][1], acc[nt][2], acc[nt][3],
                             ah0, ah1, ah2, ah3, bl0, bl1);
                    mma16816(acc[nt][0], acc[nt][1], acc[nt][2], acc[nt][3],
                             al0, al1, al2, al3, bh0, bh1);
                }
            }
            // write D staging: D_s[vloc][row], c0/c1 at (gid, 2tig..), c2/c3 at gid+8
#pragma unroll
            for (int nt = 0; nt < 8; ++nt) {
                int r0 = SM_DS + (wz * 16 + gid) * DS_STRIDE + nt * 8 + 2 * tig;
                smf[r0]     = acc[nt][0];
                smf[r0 + 1] = acc[nt][1];
                smf[r0 + 8 * DS_STRIDE]     = acc[nt][2];
                smf[r0 + 8 * DS_STRIDE + 1] = acc[nt][3];
            }
        }
        __syncthreads();

        // ---------------- epilogue (reads D_s) ----------------
        const float* Drow = smf + SM_DS + evl * DS_STRIDE + (ehalf ? 32 : 0);
        float bo_v = bo[ev];

        if (ehalf == 0) {
            // teacher rows 0..31
#pragma unroll 4
            for (int b = 0; b < 32; ++b) {
                float logit = Drow[b] + bo_v;
                float e = 0.0f;
                if (eact) {
                    pred[(b * Ss + t) * Vv + ev] = logit;
                    if (ev == tgt_s[b]) atomicAdd(&g_loss, logit);
                    e = __expf(logit);
                }
                e += __shfl_down_sync(FULL, e, 16);
                e += __shfl_down_sync(FULL, e, 8);
                e += __shfl_down_sync(FULL, e, 4);
                e += __shfl_down_sync(FULL, e, 2);
                e += __shfl_down_sync(FULL, e, 1);
                if (lane == 0) smf[SM_WSUM + wz * 64 + b] = e;
            }
        } else {
            // gen rows 32..63
#pragma unroll 4
            for (int n = 0; n < 32; ++n) {
                int r = Bb + n;
                float logit = Drow[n] + bo_v;
                float e = eact ? __expf(logit) : 0.0f;
                e += __shfl_down_sync(FULL, e, 16);
                e += __shfl_down_sync(FULL, e, 8);
                e += __shfl_down_sync(FULL, e, 4);
                e += __shfl_down_sync(FULL, e, 2);
                e += __shfl_down_sync(FULL, e, 1);
                if (lane == 0) smf[SM_WSUM + wz * 64 + r] = e;

                unsigned long long key = eact
                    ? (((unsigned long long)f2ord(logit) << 32) |
                       (unsigned long long)(0xFFFFFFFFu - (unsigned)ev))
                    : 0ull;
#pragma unroll
                for (int off = 16; off > 0; off >>= 1) {
                    unsigned long long o = __shfl_down_sync(FULL, key, off);
                    key = (o > key) ? o : key;
                }
                if (lane == 0) wkey[(wz - 8) * 32 + n] = key;
            }
        }
        __syncthreads();

        if (tid < Bb) {
            float s = 0.0f;
#pragma unroll
            for (int w = 0; w < 8; ++w) s += smf[SM_WSUM + w * 64 + tid];
            atomicAdd(&g_sumexp[t * RR + tid], s);
        } else if (tid < RR) {
            float s = 0.0f;
#pragma unroll
            for (int w = 8; w < 16; ++w) s += smf[SM_WSUM + w * 64 + tid];
            atomicAdd(&g_sumexp[t * RR + tid], s);
        } else if (tid < RR + Bb) {
            int gr = tid - RR;
            unsigned long long m = 0ull;
#pragma unroll
            for (int w = 0; w < 8; ++w) {
                unsigned long long k = wkey[w * 32 + gr];
                m = (k > m) ? k : m;
            }
            atomicMax(&g_packmax[t * Bb + gr], m);
        }
        gbar(2 * t + 1);
    }
}

// ---------------- epilogue 1: last gen outputs, loss, 1/sumexp -------------
__global__ void k_fin1(float* __restrict__ out) {
    __shared__ float red[1024];
    int tid = threadIdx.x;
    int t = tid >> 5, b = tid & 31;

    float se = g_sumexp[t * RR + b];
    red[tid] = logf(se);
    g_invse[b * Ss + t] = 1.0f / se;

    if (tid < Bb) {
        unsigned long long key = g_packmax[(Ss - 1) * Bb + tid];
        int tok = (int)(0xFFFFFFFFu - (unsigned)(key & 0xFFFFFFFFull));
        out[tid * Ss + (Ss - 1)] = (float)tok;
        float lg = ord2f((unsigned)(key >> 32));
        out[Bb * Ss + tid * Ss + (Ss - 1)] =
            __expf(lg) / g_sumexp[(Ss - 1) * RR + Bb + tid];
    }
    __syncthreads();
    for (int s = 512; s > 0; s >>= 1) {
        if (tid < s) red[tid] += red[tid + s];
        __syncthreads();
    }
    if (tid == 0)
        out[PRED_OFF + PRED_N] = (red[0] - g_loss) / (float)(Ss * Bb);
}

// ---------------- epilogue 2: logits -> probs (in place, bulk) -------------
__global__ void k_probs(float* __restrict__ out) {
    int i = blockIdx.x * blockDim.x + threadIdx.x;
    int row = i / (Vv / 4);
    float inv = g_invse[row];
    float4* p = ((float4*)(out + PRED_OFF)) + i;
    float4 l = *p;
    l.x = __expf(l.x) * inv;
    l.y = __expf(l.y) * inv;
    l.z = __expf(l.z) * inv;
    l.w = __expf(l.w) * inv;
    *p = l;
}

// ---------------- launch ---------------------------------------------------
extern "C" void kernel_launch(void* const* d_in, const int* in_sizes, int n_in,
                              void* d_out, int out_size) {
    const int*   x   = (const int*)d_in[0];
    const float* emb = (const float*)d_in[1];
    const float* Wi  = (const float*)d_in[2];
    const float* Ui  = (const float*)d_in[3];
    const float* bi  = (const float*)d_in[4];
    const float* Wf  = (const float*)d_in[5];
    const float* Uf  = (const float*)d_in[6];
    const float* bf  = (const float*)d_in[7];
    const float* Wog = (const float*)d_in[8];
    const float* Uog = (const float*)d_in[9];
    const float* bog = (const float*)d_in[10];
    const float* Wc  = (const float*)d_in[11];
    const float* Uc  = (const float*)d_in[12];
    const float* bc  = (const float*)d_in[13];
    const float* Wo  = (const float*)d_in[14];
    const float* bo  = (const float*)d_in[15];
    float* out = (float*)d_out;

    cudaFuncSetAttribute(k_persist,
                         cudaFuncAttributeMaxDynamicSharedMemorySize,
                         SMEM_BYTES);

    k_split<<<64 * Vv / 512, 512>>>(Wo);
    k_prologue<<<Ss * Bb / 16, 512>>>(x, emb, Wi, bi, Wf, bf, Wog, bog, Wc, bc);
    k_persist<<<NBLK, NTHR, SMEM_BYTES>>>(x, emb,
                                          Wi, Ui, bi, Wf, Uf, bf,
                                          Wog, Uog, bog, Wc, Uc, bc,
                                          bo, out);
    k_fin1<<<1, 1024>>>(out);
    k_probs<<<PRED_N / (256 * 4), 256>>>(out);
}

// round 12
// speedup vs baseline: 1.9749x; 1.1393x over previous
#include <cuda_runtime.h>
#include <cuda_fp16.h>
#include <cstdint>

// Problem dims
#define Vv 32000
#define Ee 128
#define Hh 128
#define Bb 32
#define Ss 32
#define RR 64                  // 64 fused rows: 0..31 teacher, 32..63 generation
#define NBLK 148               // persistent grid (1 block/SM, all resident)
#define NTHR 512
#define HS_STRIDE 68           // h_s row stride
#define HP_STRIDE 72           // packed-h row stride (conflict-free B loads)
#define DS_STRIDE 66           // D staging row stride

static const int PRED_OFF = 2048;           // gen_x[1024] + gen_o[1024]
static const int PRED_N   = Bb * Ss * Vv;   // 32,768,000

// ---------------- persistent device scratch (no allocations allowed) -------
__device__ float               g_hbuf[2][RR * Hh];      // double-buffered h
__device__ float               g_c[RR * Hh];
__device__ float               g_xg[Ss * Bb * 4 * Hh];  // teacher x-gates (with bias)
__device__ float               g_sumexp[Ss * RR];
__device__ unsigned long long  g_packmax[Ss * Bb];      // key = f2ord(e_max) || ~v
__device__ float               g_loss;                  // sum of logit at target
__device__ int                 g_bar[2 * Ss];           // grid barrier counters
__device__ unsigned            g_w16h[64 * Vv];         // Wo fp16-hi pairs, [p][v]
__device__ unsigned            g_w16l[64 * Vv];         // Wo fp16-lo pairs, [p][v]

// ---------------- shared-memory layout (float words) -----------------------
#define SM_HS    0                          // h_s[128][HS_STRIDE] (8704)
#define SM_DS    8704                       // D staging [256][DS_STRIDE] (16896)
#define SM_XE    25600                      // xe[32][129] gen embeddings (4128)
#define SM_BHI   29728                      // hp_hi[64][HP_STRIDE] (4608)
#define SM_BLO   34336                      // hp_lo (4608)
#define SM_WSM   38944                      // wsm[4][257] cell weights+bias (1028)
#define SM_GS    39972                      // gates (256)
#define SM_WSUM  40228                      // wsum[8][64] (512)
#define SM_WKEY  40740                      // wkey[8][32] ull (512 w, 8B-aligned)
#define SM_TGT   41252                      // tgt[32] ints
#define SM_TOK   41284                      // tok[32] ints
#define SM_FLOATS 41316
#define SMEM_BYTES (SM_FLOATS * 4)          // 165,264 B (< 227KB opt-in cap)

// ---------------- generic helpers ------------------------------------------
__device__ __forceinline__ float sigm(float x) { return 1.0f / (1.0f + __expf(-x)); }

__device__ __forceinline__ unsigned f2ord(float f) {
    unsigned u = __float_as_uint(f);
    return (u & 0x80000000u) ? ~u : (u | 0x80000000u);
}
__device__ __forceinline__ float ord2f(unsigned o) {
    return __uint_as_float((o & 0x80000000u) ? (o ^ 0x80000000u) : ~o);
}

// m16n8k16 f32.f16.f16.f32 (row.col), accumulate in place
__device__ __forceinline__ void mma16816(float& c0, float& c1, float& c2, float& c3,
                                         unsigned a0, unsigned a1, unsigned a2, unsigned a3,
                                         unsigned b0, unsigned b1) {
    asm volatile(
        "mma.sync.aligned.m16n8k16.row.col.f32.f16.f16.f32 "
        "{%0,%1,%2,%3}, {%4,%5,%6,%7}, {%8,%9}, {%0,%1,%2,%3};"
        : "+f"(c0), "+f"(c1), "+f"(c2), "+f"(c3)
        : "r"(a0), "r"(a1), "r"(a2), "r"(a3), "r"(b0), "r"(b1));
}

// grid-wide barrier: counter k, zeroed by prologue each launch
__device__ __forceinline__ void gbar(int k) {
    __syncthreads();
    if (threadIdx.x == 0) {
        __threadfence();
        atomicAdd(&g_bar[k], 1);
        while (*(volatile int*)&g_bar[k] < NBLK) { }
        __threadfence();
    }
    __syncthreads();
}

// v-span: 32000 = 32*217 + 116*216
__device__ __forceinline__ void vspan(int bid, int& v0, int& n) {
    if (bid < 32) { v0 = bid * 217; n = 217; }
    else          { v0 = 6944 + (bid - 32) * 216; n = 216; }
}

// ---------------- Wo fp16 split precompute ----------------------------------
__global__ void __launch_bounds__(512)
k_split(const float* __restrict__ Wo) {
    int idx = blockIdx.x * 512 + threadIdx.x;   // = p*Vv + v
    int p = idx / Vv, v = idx - p * Vv;
    float w0 = Wo[(2 * p) * Vv + v];
    float w1 = Wo[(2 * p + 1) * Vv + v];
    __half h0 = __float2half_rn(w0), h1 = __float2half_rn(w1);
    __half l0 = __float2half_rn(w0 - __half2float(h0));
    __half l1 = __float2half_rn(w1 - __half2float(h1));
    g_w16h[idx] = ((unsigned)__half_as_ushort(h1) << 16) | __half_as_ushort(h0);
    g_w16l[idx] = ((unsigned)__half_as_ushort(l1) << 16) | __half_as_ushort(l0);
}

// ---------------- prologue: teacher x-gates + barrier reset ----------------
__global__ void __launch_bounds__(512)
k_prologue(const int* __restrict__ x, const float* __restrict__ emb,
           const float* __restrict__ Wi, const float* __restrict__ bi,
           const float* __restrict__ Wf, const float* __restrict__ bf,
           const float* __restrict__ Wog, const float* __restrict__ bog,
           const float* __restrict__ Wc, const float* __restrict__ bc) {
    int p0 = blockIdx.x * 16;
    int tid = threadIdx.x;
    int g = tid >> 7, j = tid & 127;

    __shared__ int   tok_s[16];
    __shared__ float xe[16][Ee];

    if (blockIdx.x == 0) {
        if (tid < 2 * Ss) g_bar[tid] = 0;
        if (tid == 0) g_loss = 0.0f;
    }
    if (tid < 16) {
        int p = p0 + tid;
        int t = p >> 5, b = p & 31;
        tok_s[tid] = (t == 0) ? 0 : x[b * Ss + (t - 1)];
    }
    __syncthreads();
    for (int idx = tid; idx < 16 * Ee; idx += 512) {
        int pp = idx >> 7, kk = idx & 127;
        xe[pp][kk] = emb[tok_s[pp] * Ee + kk];
    }
    __syncthreads();

    const float* W = (g == 0) ? Wi : (g == 1) ? Wf : (g == 2) ? Wog : Wc;
    float bias = ((g == 0) ? bi : (g == 1) ? bf : (g == 2) ? bog : bc)[j];

    float acc[16];
#pragma unroll
    for (int pp = 0; pp < 16; ++pp) acc[pp] = bias;

#pragma unroll 4
    for (int k = 0; k < Ee; ++k) {
        float w = W[k * Hh + j];
#pragma unroll
        for (int pp = 0; pp < 16; ++pp) acc[pp] += xe[pp][k] * w;
    }
#pragma unroll
    for (int pp = 0; pp < 16; ++pp)
        g_xg[(p0 + pp) * 4 * Hh + tid] = acc[pp];
}

// ---------------- persistent fused recurrence (mma.sync GEMM) --------------
__global__ void __launch_bounds__(NTHR, 1)
k_persist(const int* __restrict__ x, const float* __restrict__ emb,
          const float* __restrict__ Wi, const float* __restrict__ Ui, const float* __restrict__ bi,
          const float* __restrict__ Wf, const float* __restrict__ Uf, const float* __restrict__ bf,
          const float* __restrict__ Wog, const float* __restrict__ Uog, const float* __restrict__ bog,
          const float* __restrict__ Wc, const float* __restrict__ Uc, const float* __restrict__ bc,
          const float* __restrict__ bo, float* __restrict__ out) {
    extern __shared__ float smf[];
    int tid = threadIdx.x, bid = blockIdx.x;
    int lane = tid & 31, wz = tid >> 5;
    bool iscell = (bid < 128);
    int j = bid;
    float* pred = out + PRED_OFF;
    int* tgt_s = (int*)(smf + SM_TGT);
    int* tok_s = (int*)(smf + SM_TOK);
    unsigned long long* wkey = (unsigned long long*)(smf + SM_WKEY);

    // one-time: cell blocks load their W/U column slice + bias into SMEM
    if (iscell) {
        for (int idx = tid; idx < 1024; idx += NTHR) {
            int g = idx >> 8, k = idx & 255;
            const float* W = (g == 0) ? Wi : (g == 1) ? Wf : (g == 2) ? Wog : Wc;
            const float* U = (g == 0) ? Ui : (g == 1) ? Uf : (g == 2) ? Uog : Uc;
            smf[SM_WSM + g * 257 + k] =
                (k < 128) ? W[k * Hh + j] : U[(k - 128) * Hh + j];
        }
        if (tid < 4) {
            const float* bv = (tid == 0) ? bi : (tid == 1) ? bf : (tid == 2) ? bog : bc;
            smf[SM_WSM + tid * 257 + 256] = bv[j];
        }
    }

    int v0, span;
    vspan(bid, v0, span);

    int gid = lane >> 2, tig = lane & 3;   // mma fragment coords

    // E1 role: warps 0-7 teacher rows, 8-15 gen rows; v = (wz&7)*32+lane
    int ehalf = wz >> 3;
    int evl = (wz & 7) * 32 + lane;        // 0..255
    bool eact = (evl < span);
    int ev = v0 + (eact ? evl : 0);

    // E0 (deferred prob write) role: b = tid>>4, chunk = tid&15
    int cb = tid >> 4, cch = tid & 15;

    // E2 role: r = tid>>3 (0..63), seg = tid&7 (28 cols each)
    int e2r = tid >> 3, e2s = tid & 7;

    for (int t = 0; t < Ss; ++t) {
        int nb = 1 - (t & 1);              // h_t buffer written by cell

        // ================= cell phase =================
        if (iscell) {
            if (t == 0) {
                for (int idx = tid; idx < RR * Hh; idx += NTHR) {
                    int k = idx & 127, r = idx >> 7;
                    smf[SM_HS + k * HS_STRIDE + r] = 0.0f;
                }
                if (tid < Bb) tok_s[tid] = 0;
            } else if (tid < Bb) {
                unsigned long long key = g_packmax[(t - 1) * Bb + tid];
                tok_s[tid] = (int)(0xFFFFFFFFu - (unsigned)(key & 0xFFFFFFFFull));
            }
            __syncthreads();
            for (int idx = tid; idx < Bb * Ee; idx += NTHR) {
                int r = idx >> 7, k = idx & 127;
                smf[SM_XE + r * 129 + k] = emb[tok_s[r] * Ee + k];
            }
            __syncthreads();

            if (tid < 256) {
                int g = tid >> 6, r = tid & 63;
                const float* wrow = smf + SM_WSM + g * 257;
                float a0 = 0.f, a1 = 0.f, a2 = 0.f, a3 = 0.f;
                if (r >= Bb) {
                    const float* xr = smf + SM_XE + (r - Bb) * 129;
#pragma unroll 8
                    for (int k = 0; k < 128; k += 4) {
                        a0 = fmaf(xr[k + 0], wrow[k + 0], a0);
                        a1 = fmaf(xr[k + 1], wrow[k + 1], a1);
                        a2 = fmaf(xr[k + 2], wrow[k + 2], a2);
                        a3 = fmaf(xr[k + 3], wrow[k + 3], a3);
                    }
                }
                const float* hc = smf + SM_HS + r;
#pragma unroll 8
                for (int k = 0; k < 128; k += 4) {
                    a0 = fmaf(hc[(k + 0) * HS_STRIDE], wrow[128 + k + 0], a0);
                    a1 = fmaf(hc[(k + 1) * HS_STRIDE], wrow[128 + k + 1], a1);
                    a2 = fmaf(hc[(k + 2) * HS_STRIDE], wrow[128 + k + 2], a2);
                    a3 = fmaf(hc[(k + 3) * HS_STRIDE], wrow[128 + k + 3], a3);
                }
                float base = (r < Bb)
                    ? g_xg[(t * Bb + r) * 4 * Hh + g * Hh + j]
                    : wrow[256];
                smf[SM_GS + g * 64 + r] = base + ((a0 + a1) + (a2 + a3));
            }
            __syncthreads();
            if (tid < RR) {
                int r = tid;
                float cp = (t == 0) ? 0.0f : g_c[r * Hh + j];
                float ig = sigm(smf[SM_GS + 0 * 64 + r]);
                float fg = sigm(smf[SM_GS + 1 * 64 + r]);
                float og = sigm(smf[SM_GS + 2 * 64 + r]);
                float cn = fg * cp + ig * tanhf(smf[SM_GS + 3 * 64 + r]);
                float hn = og * tanhf(cn);
                g_c[r * Hh + j] = cn;
                g_hbuf[nb][r * Hh + j] = hn;
            }
        } else if (bid == 128) {
            if (tid < RR) g_sumexp[t * RR + tid] = 0.0f;
            else if (tid < RR + Bb) g_packmax[t * Bb + (tid - RR)] = 0ull;
        } else if (bid == 129 && t > 0) {
            if (tid < Bb) {
                unsigned long long key = g_packmax[(t - 1) * Bb + tid];
                int tok = (int)(0xFFFFFFFFu - (unsigned)(key & 0xFFFFFFFFull));
                out[tid * Ss + (t - 1)] = (float)tok;
                float emax = ord2f((unsigned)(key >> 32));
                out[Bb * Ss + tid * Ss + (t - 1)] =
                    emax / g_sumexp[(t - 1) * RR + Bb + tid];
            }
        }
        gbar(2 * t);

        // ================= GEMM phase (all blocks) =================
        // E0: deferred prob write for step t-1 (reads old D_s e-values)
        if (t > 0) {
            float inv = __fdividef(1.0f, g_sumexp[(t - 1) * RR + cb]);
#pragma unroll 2
            for (int i = 0; i < 14; ++i) {
                int col = cch + 16 * i;     // 0..223
                if (col < span) {
                    float e = smf[SM_DS + col * DS_STRIDE + cb];
                    pred[(cb * Ss + (t - 1)) * Vv + v0 + col] = e * inv;
                }
            }
        }

        const float* hsrc = g_hbuf[nb];

        // h_sT for next cell phase
        for (int idx = tid; idx < RR * Hh; idx += NTHR) {
            int k = idx & 127, r = idx >> 7;
            smf[SM_HS + k * HS_STRIDE + r] = hsrc[r * Hh + k];
        }
        // B = h split fp16 hi/lo pair-packed: hp[p][n], p = k-pair
        {
            unsigned* BH = (unsigned*)(smf + SM_BHI);
            unsigned* BL = (unsigned*)(smf + SM_BLO);
            for (int idx = tid; idx < 64 * 64; idx += NTHR) {
                int p = idx >> 6, n = idx & 63;
                float2 hv = *(const float2*)(hsrc + n * Hh + 2 * p);
                __half h0 = __float2half_rn(hv.x), h1 = __float2half_rn(hv.y);
                __half l0 = __float2half_rn(hv.x - __half2float(h0));
                __half l1 = __float2half_rn(hv.y - __half2float(h1));
                BH[p * HP_STRIDE + n] =
                    ((unsigned)__half_as_ushort(h1) << 16) | __half_as_ushort(h0);
                BL[p * HP_STRIDE + n] =
                    ((unsigned)__half_as_ushort(l1) << 16) | __half_as_ushort(l0);
            }
        }
        if (tid < Bb) tgt_s[tid] = x[tid * Ss + t];
        __syncthreads();

        // mma compute: warp wz handles m-tile wz (14 tiles cover span<=224)
        // teacher n-tiles (nt 0..3): 2 passes; gen n-tiles (nt 4..7): 3 passes
        if (wz < 14) {
            int vA = v0 + wz * 16 + gid;
            int vAc  = (vA < Vv) ? vA : (Vv - 1);
            int vA8c = (vA + 8 < Vv) ? (vA + 8) : (Vv - 1);
            float acc[8][4];
#pragma unroll
            for (int nt = 0; nt < 8; ++nt) {
                acc[nt][0] = 0.f; acc[nt][1] = 0.f;
                acc[nt][2] = 0.f; acc[nt][3] = 0.f;
            }
            const unsigned* BHg = (const unsigned*)(smf + SM_BHI) + gid;
            const unsigned* BLg = (const unsigned*)(smf + SM_BLO) + gid;
#pragma unroll 1
            for (int k0 = 0; k0 < 8; ++k0) {
                int pA = k0 * 8 + tig;
                const unsigned* Wh = g_w16h + pA * Vv;
                const unsigned* Wl = g_w16l + pA * Vv;
                unsigned ah0 = Wh[vAc],          ah1 = Wh[vA8c];
                unsigned ah2 = Wh[4 * Vv + vAc], ah3 = Wh[4 * Vv + vA8c];
                unsigned al0 = Wl[vAc],          al1 = Wl[vA8c];
                unsigned al2 = Wl[4 * Vv + vAc], al3 = Wl[4 * Vv + vA8c];
                const unsigned* BHp = BHg + pA * HP_STRIDE;
                const unsigned* BLp = BLg + pA * HP_STRIDE;
#pragma unroll
                for (int nt = 0; nt < 8; ++nt) {
                    unsigned bh0 = BHp[nt * 8];
                    unsigned bh1 = BHp[4 * HP_STRIDE + nt * 8];
                    unsigned bl0 = BLp[nt * 8];
                    unsigned bl1 = BLp[4 * HP_STRIDE + nt * 8];
                    mma16816(acc[nt][0], acc[nt][1], acc[nt][2], acc[nt][3],
                             ah0, ah1, ah2, ah3, bh0, bh1);
                    mma16816(acc[nt][0], acc[nt][1], acc[nt][2], acc[nt][3],
                             ah0, ah1, ah2, ah3, bl0, bl1);
                    if (nt >= 4)
                        mma16816(acc[nt][0], acc[nt][1], acc[nt][2], acc[nt][3],
                                 al0, al1, al2, al3, bh0, bh1);
                }
            }
            // write D staging: D_s[vloc][row]
#pragma unroll
            for (int nt = 0; nt < 8; ++nt) {
                int r0 = SM_DS + (wz * 16 + gid) * DS_STRIDE + nt * 8 + 2 * tig;
                smf[r0]     = acc[nt][0];
                smf[r0 + 1] = acc[nt][1];
                smf[r0 + 8 * DS_STRIDE]     = acc[nt][2];
                smf[r0 + 8 * DS_STRIDE + 1] = acc[nt][3];
            }
        }
        __syncthreads();

        // ---------------- E1: logits -> e in place, loss ----------------
        {
            float bo_v = bo[ev];
            int rbase = ehalf ? 32 : 0;
            float* Drow = smf + SM_DS + evl * DS_STRIDE + rbase;
#pragma unroll 4
            for (int n = 0; n < 32; ++n) {
                float e = 0.0f;
                if (eact) {
                    float logit = Drow[n] + bo_v;
                    if (ehalf == 0 && ev == tgt_s[n]) atomicAdd(&g_loss, logit);
                    e = __expf(logit);
                }
                Drow[n] = e;
            }
        }
        __syncthreads();

        // ---------------- E2: segmented reductions from D_s --------------
        {
            // sumexp for row e2r, segment e2s (cols e2s*28 .. +27)
            const float* base = smf + SM_DS + e2r;
            float s = 0.0f;
            float emax = -1.0f; int cbest = 0;
            int c0 = e2s * 28;
#pragma unroll 7
            for (int i = 0; i < 28; ++i) {
                float e = base[(c0 + i) * DS_STRIDE];
                s += e;
                if (e2r >= Bb && e > emax) { emax = e; cbest = c0 + i; }
            }
            smf[SM_WSUM + e2s * 64 + e2r] = s;
            if (e2r >= Bb) {
                wkey[e2s * 32 + (e2r - Bb)] =
                    ((unsigned long long)f2ord(emax) << 32) |
                    (unsigned long long)(0xFFFFFFFFu - (unsigned)(v0 + cbest));
            }
        }
        __syncthreads();

        if (tid < RR) {
            float s = 0.0f;
#pragma unroll
            for (int w = 0; w < 8; ++w) s += smf[SM_WSUM + w * 64 + tid];
            atomicAdd(&g_sumexp[t * RR + tid], s);
        } else if (tid < RR + Bb) {
            int gr = tid - RR;
            unsigned long long m = 0ull;
#pragma unroll
            for (int w = 0; w < 8; ++w) {
                unsigned long long k = wkey[w * 32 + gr];
                m = (k > m) ? k : m;
            }
            atomicMax(&g_packmax[t * Bb + gr], m);
        }
        gbar(2 * t + 1);
    }

    // final flush: probs for t=31 (sumexp[31] final after last gbar)
    {
        float inv = __fdividef(1.0f, g_sumexp[(Ss - 1) * RR + cb]);
#pragma unroll 2
        for (int i = 0; i < 14; ++i) {
            int col = cch + 16 * i;
            if (col < span) {
                float e = smf[SM_DS + col * DS_STRIDE + cb];
                pred[(cb * Ss + (Ss - 1)) * Vv + v0 + col] = e * inv;
            }
        }
    }
}

// ---------------- epilogue: last gen outputs + loss -------------------------
__global__ void k_fin1(float* __restrict__ out) {
    __shared__ float red[1024];
    int tid = threadIdx.x;
    int t = tid >> 5, b = tid & 31;

    float se = g_sumexp[t * RR + b];
    red[tid] = logf(se);

    if (tid < Bb) {
        unsigned long long key = g_packmax[(Ss - 1) * Bb + tid];
        int tok = (int)(0xFFFFFFFFu - (unsigned)(key & 0xFFFFFFFFull));
        out[tid * Ss + (Ss - 1)] = (float)tok;
        float emax = ord2f((unsigned)(key >> 32));
        out[Bb * Ss + tid * Ss + (Ss - 1)] =
            emax / g_sumexp[(Ss - 1) * RR + Bb + tid];
    }
    __syncthreads();
    for (int s = 512; s > 0; s >>= 1) {
        if (tid < s) red[tid] += red[tid + s];
        __syncthreads();
    }
    if (tid == 0)
        out[PRED_OFF + PRED_N] = (red[0] - g_loss) / (float)(Ss * Bb);
}

// ---------------- launch ---------------------------------------------------
extern "C" void kernel_launch(void* const* d_in, const int* in_sizes, int n_in,
                              void* d_out, int out_size) {
    const int*   x   = (const int*)d_in[0];
    const float* emb = (const float*)d_in[1];
    const float* Wi  = (const float*)d_in[2];
    const float* Ui  = (const float*)d_in[3];
    const float* bi  = (const float*)d_in[4];
    const float* Wf  = (const float*)d_in[5];
    const float* Uf  = (const float*)d_in[6];
    const float* bf  = (const float*)d_in[7];
    const float* Wog = (const float*)d_in[8];
    const float* Uog = (const float*)d_in[9];
    const float* bog = (const float*)d_in[10];
    const float* Wc  = (const float*)d_in[11];
    const float* Uc  = (const float*)d_in[12];
    const float* bc  = (const float*)d_in[13];
    const float* Wo  = (const float*)d_in[14];
    const float* bo  = (const float*)d_in[15];
    float* out = (float*)d_out;

    cudaFuncSetAttribute(k_persist,
                         cudaFuncAttributeMaxDynamicSharedMemorySize,
                         SMEM_BYTES);

    k_split<<<64 * Vv / 512, 512>>>(Wo);
    k_prologue<<<Ss * Bb / 16, 512>>>(x, emb, Wi, bi, Wf, bf, Wog, bog, Wc, bc);
    k_persist<<<NBLK, NTHR, SMEM_BYTES>>>(x, emb,
                                          Wi, Ui, bi, Wf, Uf, bf,
                                          Wog, Uog, bog, Wc, Uc, bc,
                                          bo, out);
    k_fin1<<<1, 1024>>>(out);
}

// round 13
// speedup vs baseline: 2.0723x; 1.0493x over previous
#include <cuda_runtime.h>
#include <cuda_fp16.h>
#include <cstdint>

// Problem dims
#define Vv 32000
#define Ee 128
#define Hh 128
#define Bb 32
#define Ss 32
#define RR 64                  // 64 fused rows: 0..31 teacher, 32..63 generation
#define NBLK 148               // persistent grid (1 block/SM, all resident)
#define NTHR 512
#define HS_STRIDE 68           // h_s row stride
#define HP_STRIDE 72           // packed-h row stride (conflict-free B loads)
#define DS_STRIDE 66           // D staging row stride

static const int PRED_OFF = 2048;           // gen_x[1024] + gen_o[1024]
static const int PRED_N   = Bb * Ss * Vv;   // 32,768,000

// ---------------- persistent device scratch (no allocations allowed) -------
__device__ float               g_hbuf[2][RR * Hh];      // double-buffered h
__device__ float               g_c[RR * Hh];
__device__ float               g_xg[Ss * Bb * 4 * Hh];  // teacher x-gates (with bias)
__device__ float               g_sumexp[Ss * RR];
__device__ unsigned long long  g_packmax[Ss * Bb];      // key = f2ord(e_max) || ~v
__device__ float               g_loss;                  // sum of logit at target
__device__ int                 g_bar[2 * Ss];           // grid barrier counters
__device__ unsigned            g_w16h[64 * Vv];         // Wo fp16-hi pairs, [p][v]
__device__ unsigned            g_w16l[64 * Vv];         // Wo fp16-lo pairs, [p][v]

// ---------------- shared-memory layout (float words) -----------------------
#define SM_HS    0                          // h_s[128][HS_STRIDE] (8704)
#define SM_DS    8704                       // D staging [256][DS_STRIDE] (16896)
#define SM_XE    25600                      // xe[32][129] gen embeddings (4128)
#define SM_BHI   29728                      // hp_hi[64][HP_STRIDE] (4608)
#define SM_BLO   34336                      // hp_lo (4608)
#define SM_WSM   38944                      // wsm[4][257] cell weights+bias (1028)
#define SM_GS    39972                      // gates (256)
#define SM_WSUM  40228                      // wsum[8][64] (512)
#define SM_WKEY  40740                      // wkey[8][32] ull (512 w, 8B-aligned)
#define SM_TGT   41252                      // tgt[32] ints
#define SM_TOK   41284                      // tok[32] ints
#define SM_FLOATS 41316
#define SMEM_BYTES (SM_FLOATS * 4)          // 165,264 B (< 227KB opt-in cap)

// ---------------- generic helpers ------------------------------------------
__device__ __forceinline__ float sigm(float x) { return 1.0f / (1.0f + __expf(-x)); }

__device__ __forceinline__ unsigned f2ord(float f) {
    unsigned u = __float_as_uint(f);
    return (u & 0x80000000u) ? ~u : (u | 0x80000000u);
}
__device__ __forceinline__ float ord2f(unsigned o) {
    return __uint_as_float((o & 0x80000000u) ? (o ^ 0x80000000u) : ~o);
}

// m16n8k16 f32.f16.f16.f32 (row.col), accumulate in place
__device__ __forceinline__ void mma16816(float& c0, float& c1, float& c2, float& c3,
                                         unsigned a0, unsigned a1, unsigned a2, unsigned a3,
                                         unsigned b0, unsigned b1) {
    asm volatile(
        "mma.sync.aligned.m16n8k16.row.col.f32.f16.f16.f32 "
        "{%0,%1,%2,%3}, {%4,%5,%6,%7}, {%8,%9}, {%0,%1,%2,%3};"
        : "+f"(c0), "+f"(c1), "+f"(c2), "+f"(c3)
        : "r"(a0), "r"(a1), "r"(a2), "r"(a3), "r"(b0), "r"(b1));
}

// grid-wide barrier: counter k, zeroed by prologue each launch
__device__ __forceinline__ void gbar(int k) {
    __syncthreads();
    if (threadIdx.x == 0) {
        __threadfence();
        atomicAdd(&g_bar[k], 1);
        while (*(volatile int*)&g_bar[k] < NBLK) { }
        __threadfence();
    }
    __syncthreads();
}

// v-span: 32000 = 32*217 + 116*216
__device__ __forceinline__ void vspan(int bid, int& v0, int& n) {
    if (bid < 32) { v0 = bid * 217; n = 217; }
    else          { v0 = 6944 + (bid - 32) * 216; n = 216; }
}

// ---------------- Wo fp16 split precompute ----------------------------------
__global__ void __launch_bounds__(512)
k_split(const float* __restrict__ Wo) {
    int idx = blockIdx.x * 512 + threadIdx.x;   // = p*Vv + v
    int p = idx / Vv, v = idx - p * Vv;
    float w0 = Wo[(2 * p) * Vv + v];
    float w1 = Wo[(2 * p + 1) * Vv + v];
    __half h0 = __float2half_rn(w0), h1 = __float2half_rn(w1);
    __half l0 = __float2half_rn(w0 - __half2float(h0));
    __half l1 = __float2half_rn(w1 - __half2float(h1));
    g_w16h[idx] = ((unsigned)__half_as_ushort(h1) << 16) | __half_as_ushort(h0);
    g_w16l[idx] = ((unsigned)__half_as_ushort(l1) << 16) | __half_as_ushort(l0);
}

// ---------------- prologue: teacher x-gates + barrier reset ----------------
__global__ void __launch_bounds__(512)
k_prologue(const int* __restrict__ x, const float* __restrict__ emb,
           const float* __restrict__ Wi, const float* __restrict__ bi,
           const float* __restrict__ Wf, const float* __restrict__ bf,
           const float* __restrict__ Wog, const float* __restrict__ bog,
           const float* __restrict__ Wc, const float* __restrict__ bc) {
    int p0 = blockIdx.x * 16;
    int tid = threadIdx.x;
    int g = tid >> 7, j = tid & 127;

    __shared__ int   tok_s[16];
    __shared__ float xe[16][Ee];

    if (blockIdx.x == 0) {
        if (tid < 2 * Ss) g_bar[tid] = 0;
        if (tid == 0) g_loss = 0.0f;
    }
    if (tid < 16) {
        int p = p0 + tid;
        int t = p >> 5, b = p & 31;
        tok_s[tid] = (t == 0) ? 0 : x[b * Ss + (t - 1)];
    }
    __syncthreads();
    for (int idx = tid; idx < 16 * Ee; idx += 512) {
        int pp = idx >> 7, kk = idx & 127;
        xe[pp][kk] = emb[tok_s[pp] * Ee + kk];
    }
    __syncthreads();

    const float* W = (g == 0) ? Wi : (g == 1) ? Wf : (g == 2) ? Wog : Wc;
    float bias = ((g == 0) ? bi : (g == 1) ? bf : (g == 2) ? bog : bc)[j];

    float acc[16];
#pragma unroll
    for (int pp = 0; pp < 16; ++pp) acc[pp] = bias;

#pragma unroll 4
    for (int k = 0; k < Ee; ++k) {
        float w = W[k * Hh + j];
#pragma unroll
        for (int pp = 0; pp < 16; ++pp) acc[pp] += xe[pp][k] * w;
    }
#pragma unroll
    for (int pp = 0; pp < 16; ++pp)
        g_xg[(p0 + pp) * 4 * Hh + tid] = acc[pp];
}

// ---------------- persistent fused recurrence (mma.sync GEMM) --------------
__global__ void __launch_bounds__(NTHR, 1)
k_persist(const int* __restrict__ x, const float* __restrict__ emb,
          const float* __restrict__ Wi, const float* __restrict__ Ui, const float* __restrict__ bi,
          const float* __restrict__ Wf, const float* __restrict__ Uf, const float* __restrict__ bf,
          const float* __restrict__ Wog, const float* __restrict__ Uog, const float* __restrict__ bog,
          const float* __restrict__ Wc, const float* __restrict__ Uc, const float* __restrict__ bc,
          const float* __restrict__ bo, float* __restrict__ out) {
    extern __shared__ float smf[];
    int tid = threadIdx.x, bid = blockIdx.x;
    int lane = tid & 31, wz = tid >> 5;
    bool iscell = (bid < 128);
    int j = bid;
    float* pred = out + PRED_OFF;
    int* tgt_s = (int*)(smf + SM_TGT);
    int* tok_s = (int*)(smf + SM_TOK);
    unsigned long long* wkey = (unsigned long long*)(smf + SM_WKEY);

    // one-time: cell blocks load their W/U column slice + bias into SMEM
    if (iscell) {
        for (int idx = tid; idx < 1024; idx += NTHR) {
            int g = idx >> 8, k = idx & 255;
            const float* W = (g == 0) ? Wi : (g == 1) ? Wf : (g == 2) ? Wog : Wc;
            const float* U = (g == 0) ? Ui : (g == 1) ? Uf : (g == 2) ? Uog : Uc;
            smf[SM_WSM + g * 257 + k] =
                (k < 128) ? W[k * Hh + j] : U[(k - 128) * Hh + j];
        }
        if (tid < 4) {
            const float* bv = (tid == 0) ? bi : (tid == 1) ? bf : (tid == 2) ? bog : bc;
            smf[SM_WSM + tid * 257 + 256] = bv[j];
        }
    }

    int v0, span;
    vspan(bid, v0, span);

    int gid = lane >> 2, tig = lane & 3;   // mma fragment coords

    // one-time: persistent A-hi fragment cache (step-invariant Wo columns)
    int vA = v0 + wz * 16 + gid;
    int vAc  = (vA < Vv) ? vA : (Vv - 1);
    int vA8c = (vA + 8 < Vv) ? (vA + 8) : (Vv - 1);
    unsigned ahreg[8][4];
    if (wz < 14) {
#pragma unroll
        for (int k0 = 0; k0 < 8; ++k0) {
            const unsigned* Wh = g_w16h + (k0 * 8 + tig) * Vv;
            ahreg[k0][0] = Wh[vAc];
            ahreg[k0][1] = Wh[vA8c];
            ahreg[k0][2] = Wh[4 * Vv + vAc];
            ahreg[k0][3] = Wh[4 * Vv + vA8c];
        }
    }

    // E1 role: warps 0-7 teacher rows, 8-15 gen rows; v = (wz&7)*32+lane
    int ehalf = wz >> 3;
    int evl = (wz & 7) * 32 + lane;        // 0..255
    bool eact = (evl < span);
    int ev = v0 + (eact ? evl : 0);

    // E0 (deferred prob write) role: b = tid>>4, chunk = tid&15
    int cb = tid >> 4, cch = tid & 15;

    // E2 role: r = tid>>3 (0..63), seg = tid&7 (28 cols each)
    int e2r = tid >> 3, e2s = tid & 7;

    for (int t = 0; t < Ss; ++t) {
        int nb = 1 - (t & 1);              // h_t buffer written by cell

        // ================= cell phase =================
        if (iscell) {
            if (t == 0) {
                for (int idx = tid; idx < RR * Hh; idx += NTHR) {
                    int k = idx & 127, r = idx >> 7;
                    smf[SM_HS + k * HS_STRIDE + r] = 0.0f;
                }
                if (tid < Bb) tok_s[tid] = 0;
            } else if (tid < Bb) {
                unsigned long long key = g_packmax[(t - 1) * Bb + tid];
                tok_s[tid] = (int)(0xFFFFFFFFu - (unsigned)(key & 0xFFFFFFFFull));
            }
            __syncthreads();
            for (int idx = tid; idx < Bb * Ee; idx += NTHR) {
                int r = idx >> 7, k = idx & 127;
                smf[SM_XE + r * 129 + k] = emb[tok_s[r] * Ee + k];
            }
            __syncthreads();

            if (tid < 256) {
                int g = tid >> 6, r = tid & 63;
                const float* wrow = smf + SM_WSM + g * 257;
                float a0 = 0.f, a1 = 0.f, a2 = 0.f, a3 = 0.f;
                if (r >= Bb) {
                    const float* xr = smf + SM_XE + (r - Bb) * 129;
#pragma unroll 8
                    for (int k = 0; k < 128; k += 4) {
                        a0 = fmaf(xr[k + 0], wrow[k + 0], a0);
                        a1 = fmaf(xr[k + 1], wrow[k + 1], a1);
                        a2 = fmaf(xr[k + 2], wrow[k + 2], a2);
                        a3 = fmaf(xr[k + 3], wrow[k + 3], a3);
                    }
                }
                const float* hc = smf + SM_HS + r;
#pragma unroll 8
                for (int k = 0; k < 128; k += 4) {
                    a0 = fmaf(hc[(k + 0) * HS_STRIDE], wrow[128 + k + 0], a0);
                    a1 = fmaf(hc[(k + 1) * HS_STRIDE], wrow[128 + k + 1], a1);
                    a2 = fmaf(hc[(k + 2) * HS_STRIDE], wrow[128 + k + 2], a2);
                    a3 = fmaf(hc[(k + 3) * HS_STRIDE], wrow[128 + k + 3], a3);
                }
                float base = (r < Bb)
                    ? g_xg[(t * Bb + r) * 4 * Hh + g * Hh + j]
                    : wrow[256];
                smf[SM_GS + g * 64 + r] = base + ((a0 + a1) + (a2 + a3));
            }
            __syncthreads();
            if (tid < RR) {
                int r = tid;
                float cp = (t == 0) ? 0.0f : g_c[r * Hh + j];
                float ig = sigm(smf[SM_GS + 0 * 64 + r]);
                float fg = sigm(smf[SM_GS + 1 * 64 + r]);
                float og = sigm(smf[SM_GS + 2 * 64 + r]);
                float cn = fg * cp + ig * tanhf(smf[SM_GS + 3 * 64 + r]);
                float hn = og * tanhf(cn);
                g_c[r * Hh + j] = cn;
                g_hbuf[nb][r * Hh + j] = hn;
            }
        } else if (bid == 128) {
            if (tid < RR) g_sumexp[t * RR + tid] = 0.0f;
            else if (tid < RR + Bb) g_packmax[t * Bb + (tid - RR)] = 0ull;
        } else if (bid == 129 && t > 0) {
            if (tid < Bb) {
                unsigned long long key = g_packmax[(t - 1) * Bb + tid];
                int tok = (int)(0xFFFFFFFFu - (unsigned)(key & 0xFFFFFFFFull));
                out[tid * Ss + (t - 1)] = (float)tok;
                float emax = ord2f((unsigned)(key >> 32));
                out[Bb * Ss + tid * Ss + (t - 1)] =
                    emax / g_sumexp[(t - 1) * RR + Bb + tid];
            }
        }
        gbar(2 * t);

        // ================= GEMM phase (all blocks) =================
        // E0: deferred prob write for step t-1 (reads old D_s e-values)
        if (t > 0) {
            float inv = __fdividef(1.0f, g_sumexp[(t - 1) * RR + cb]);
#pragma unroll 2
            for (int i = 0; i < 14; ++i) {
                int col = cch + 16 * i;     // 0..223
                if (col < span) {
                    float e = smf[SM_DS + col * DS_STRIDE + cb];
                    pred[(cb * Ss + (t - 1)) * Vv + v0 + col] = e * inv;
                }
            }
        }

        const float* hsrc = g_hbuf[nb];

        // h_sT for next cell phase
        for (int idx = tid; idx < RR * Hh; idx += NTHR) {
            int k = idx & 127, r = idx >> 7;
            smf[SM_HS + k * HS_STRIDE + r] = hsrc[r * Hh + k];
        }
        // B = h split fp16 hi/lo pair-packed: hp[p][n], p = k-pair
        {
            unsigned* BH = (unsigned*)(smf + SM_BHI);
            unsigned* BL = (unsigned*)(smf + SM_BLO);
            for (int idx = tid; idx < 64 * 64; idx += NTHR) {
                int p = idx >> 6, n = idx & 63;
                float2 hv = *(const float2*)(hsrc + n * Hh + 2 * p);
                __half h0 = __float2half_rn(hv.x), h1 = __float2half_rn(hv.y);
                __half l0 = __float2half_rn(hv.x - __half2float(h0));
                __half l1 = __float2half_rn(hv.y - __half2float(h1));
                BH[p * HP_STRIDE + n] =
                    ((unsigned)__half_as_ushort(h1) << 16) | __half_as_ushort(h0);
                BL[p * HP_STRIDE + n] =
                    ((unsigned)__half_as_ushort(l1) << 16) | __half_as_ushort(l0);
            }
        }
        if (tid < Bb) tgt_s[tid] = x[tid * Ss + t];
        __syncthreads();

        // mma compute: warp wz handles m-tile wz (14 tiles cover span<=224)
        // A-hi from persistent regs; only A-lo (gen pass 3) loads per step.
        // teacher n-tiles (nt 0..3): 2 passes; gen n-tiles (nt 4..7): 3 passes
        if (wz < 14) {
            float acc[8][4];
#pragma unroll
            for (int nt = 0; nt < 8; ++nt) {
                acc[nt][0] = 0.f; acc[nt][1] = 0.f;
                acc[nt][2] = 0.f; acc[nt][3] = 0.f;
            }
            const unsigned* BHg = (const unsigned*)(smf + SM_BHI) + gid;
            const unsigned* BLg = (const unsigned*)(smf + SM_BLO) + gid;
#pragma unroll
            for (int k0 = 0; k0 < 8; ++k0) {
                int pA = k0 * 8 + tig;
                const unsigned* Wl = g_w16l + pA * Vv;
                unsigned al0 = Wl[vAc],          al1 = Wl[vA8c];
                unsigned al2 = Wl[4 * Vv + vAc], al3 = Wl[4 * Vv + vA8c];
                const unsigned* BHp = BHg + pA * HP_STRIDE;
                const unsigned* BLp = BLg + pA * HP_STRIDE;
#pragma unroll
                for (int nt = 0; nt < 8; ++nt) {
                    unsigned bh0 = BHp[nt * 8];
                    unsigned bh1 = BHp[4 * HP_STRIDE + nt * 8];
                    unsigned bl0 = BLp[nt * 8];
                    unsigned bl1 = BLp[4 * HP_STRIDE + nt * 8];
                    mma16816(acc[nt][0], acc[nt][1], acc[nt][2], acc[nt][3],
                             ahreg[k0][0], ahreg[k0][1], ahreg[k0][2], ahreg[k0][3],
                             bh0, bh1);
                    mma16816(acc[nt][0], acc[nt][1], acc[nt][2], acc[nt][3],
                             ahreg[k0][0], ahreg[k0][1], ahreg[k0][2], ahreg[k0][3],
                             bl0, bl1);
                    if (nt >= 4)
                        mma16816(acc[nt][0], acc[nt][1], acc[nt][2], acc[nt][3],
                                 al0, al1, al2, al3, bh0, bh1);
                }
            }
            // write D staging: D_s[vloc][row]
#pragma unroll
            for (int nt = 0; nt < 8; ++nt) {
                int r0 = SM_DS + (wz * 16 + gid) * DS_STRIDE + nt * 8 + 2 * tig;
                smf[r0]     = acc[nt][0];
                smf[r0 + 1] = acc[nt][1];
                smf[r0 + 8 * DS_STRIDE]     = acc[nt][2];
                smf[r0 + 8 * DS_STRIDE + 1] = acc[nt][3];
            }
        }
        __syncthreads();

        // ---------------- E1: logits -> e in place, loss ----------------
        {
            float bo_v = bo[ev];
            int rbase = ehalf ? 32 : 0;
            float* Drow = smf + SM_DS + evl * DS_STRIDE + rbase;
#pragma unroll 4
            for (int n = 0; n < 32; ++n) {
                float e = 0.0f;
                if (eact) {
                    float logit = Drow[n] + bo_v;
                    if (ehalf == 0 && ev == tgt_s[n]) atomicAdd(&g_loss, logit);
                    e = __expf(logit);
                }
                Drow[n] = e;
            }
        }
        __syncthreads();

        // ---------------- E2: segmented reductions from D_s --------------
        {
            const float* base = smf + SM_DS + e2r;
            float s = 0.0f;
            float emax = -1.0f; int cbest = 0;
            int c0 = e2s * 28;
#pragma unroll 7
            for (int i = 0; i < 28; ++i) {
                float e = base[(c0 + i) * DS_STRIDE];
                s += e;
                if (e2r >= Bb && e > emax) { emax = e; cbest = c0 + i; }
            }
            smf[SM_WSUM + e2s * 64 + e2r] = s;
            if (e2r >= Bb) {
                wkey[e2s * 32 + (e2r - Bb)] =
                    ((unsigned long long)f2ord(emax) << 32) |
                    (unsigned long long)(0xFFFFFFFFu - (unsigned)(v0 + cbest));
            }
        }
        __syncthreads();

        if (tid < RR) {
            float s = 0.0f;
#pragma unroll
            for (int w = 0; w < 8; ++w) s += smf[SM_WSUM + w * 64 + tid];
            atomicAdd(&g_sumexp[t * RR + tid], s);
        } else if (tid < RR + Bb) {
            int gr = tid - RR;
            unsigned long long m = 0ull;
#pragma unroll
            for (int w = 0; w < 8; ++w) {
                unsigned long long k = wkey[w * 32 + gr];
                m = (k > m) ? k : m;
            }
            atomicMax(&g_packmax[t * Bb + gr], m);
        }
        gbar(2 * t + 1);
    }

    // final flush: probs for t=31 (sumexp[31] final after last gbar)
    {
        float inv = __fdividef(1.0f, g_sumexp[(Ss - 1) * RR + cb]);
#pragma unroll 2
        for (int i = 0; i < 14; ++i) {
            int col = cch + 16 * i;
            if (col < span) {
                float e = smf[SM_DS + col * DS_STRIDE + cb];
                pred[(cb * Ss + (Ss - 1)) * Vv + v0 + col] = e * inv;
            }
        }
    }
}

// ---------------- epilogue: last gen outputs + loss -------------------------
__global__ void k_fin1(float* __restrict__ out) {
    __shared__ float red[1024];
    int tid = threadIdx.x;
    int t = tid >> 5, b = tid & 31;

    float se = g_sumexp[t * RR + b];
    red[tid] = logf(se);

    if (tid < Bb) {
        unsigned long long key = g_packmax[(Ss - 1) * Bb + tid];
        int tok = (int)(0xFFFFFFFFu - (unsigned)(key & 0xFFFFFFFFull));
        out[tid * Ss + (Ss - 1)] = (float)tok;
        float emax = ord2f((unsigned)(key >> 32));
        out[Bb * Ss + tid * Ss + (Ss - 1)] =
            emax / g_sumexp[(Ss - 1) * RR + Bb + tid];
    }
    __syncthreads();
    for (int s = 512; s > 0; s >>= 1) {
        if (tid < s) red[tid] += red[tid + s];
        __syncthreads();
    }
    if (tid == 0)
        out[PRED_OFF + PRED_N] = (red[0] - g_loss) / (float)(Ss * Bb);
}

// ---------------- launch ---------------------------------------------------
extern "C" void kernel_launch(void* const* d_in, const int* in_sizes, int n_in,
                              void* d_out, int out_size) {
    const int*   x   = (const int*)d_in[0];
    const float* emb = (const float*)d_in[1];
    const float* Wi  = (const float*)d_in[2];
    const float* Ui  = (const float*)d_in[3];
    const float* bi  = (const float*)d_in[4];
    const float* Wf  = (const float*)d_in[5];
    const float* Uf  = (const float*)d_in[6];
    const float* bf  = (const float*)d_in[7];
    const float* Wog = (const float*)d_in[8];
    const float* Uog = (const float*)d_in[9];
    const float* bog = (const float*)d_in[10];
    const float* Wc  = (const float*)d_in[11];
    const float* Uc  = (const float*)d_in[12];
    const float* bc  = (const float*)d_in[13];
    const float* Wo  = (const float*)d_in[14];
    const float* bo  = (const float*)d_in[15];
    float* out = (float*)d_out;

    cudaFuncSetAttribute(k_persist,
                         cudaFuncAttributeMaxDynamicSharedMemorySize,
                         SMEM_BYTES);

    k_split<<<64 * Vv / 512, 512>>>(Wo);
    k_prologue<<<Ss * Bb / 16, 512>>>(x, emb, Wi, bi, Wf, bf, Wog, bog, Wc, bc);
    k_persist<<<NBLK, NTHR, SMEM_BYTES>>>(x, emb,
                                          Wi, Ui, bi, Wf, Uf, bf,
                                          Wog, Uog, bog, Wc, Uc, bc,
                                          bo, out);
    k_fin1<<<1, 1024>>>(out);
}

// round 14
// speedup vs baseline: 2.3684x; 1.1429x over previous
#include <cuda_runtime.h>
#include <cuda_fp16.h>
#include <cstdint>

// Problem dims
#define Vv 32000
#define Ee 128
#define Hh 128
#define Bb 32
#define Ss 32
#define RR 64                  // 64 fused rows: 0..31 teacher, 32..63 generation
#define NBLK 148               // persistent grid (1 block/SM, all resident)
#define NTHR 512
#define HS_STRIDE 68           // h_s row stride
#define HP2_STRIDE 68          // packed-B uint2 row stride (conflict-free 8B loads)
#define DS_STRIDE 66           // D staging row stride

static const int PRED_OFF = 2048;           // gen_x[1024] + gen_o[1024]
static const int PRED_N   = Bb * Ss * Vv;   // 32,768,000

// ---------------- persistent device scratch (no allocations allowed) -------
__device__ float               g_hbuf[2][RR * Hh];      // double-buffered h
__device__ float               g_c[RR * Hh];
__device__ float               g_xg[Ss * Bb * 4 * Hh];  // teacher x-gates (with bias)
__device__ float               g_sumexp[Ss * RR];
__device__ unsigned long long  g_packmax[Ss * Bb];      // key = f2ord(e_max) || ~v
__device__ float               g_loss;                  // sum of logit at target
__device__ int                 g_bar[2 * Ss];           // grid barrier counters
__device__ unsigned            g_w16h[64 * Vv];         // Wo fp16-hi pairs, [p][v]
__device__ unsigned            g_w16l[64 * Vv];         // Wo fp16-lo pairs, [p][v]

// ---------------- shared-memory layout (float words) -----------------------
#define SM_HS    0                          // h_s[128][HS_STRIDE] (8704)
#define SM_DS    8704                       // D staging [256][DS_STRIDE] (16896)
#define SM_XE    25600                      // xe[32][129] gen embeddings (4128)
#define SM_BH2   29728                      // B-hi uint2[32][HP2_STRIDE] (4352 w)
#define SM_BL2   34080                      // B-lo uint2[32][HP2_STRIDE] (4352 w)
#define SM_WSM   38432                      // wsm[4][257] cell weights+bias (1028)
#define SM_PART  39460                      // cell k-split partials [2][256] (512)
#define SM_GS    39972                      // gates (256)
#define SM_WSUM  40228                      // wsum[8][64] (512)
#define SM_WKEY  40740                      // wkey[8][32] ull (512 w, 8B-aligned)
#define SM_TGT   41252                      // tgt[32] ints
#define SM_TOK   41284                      // tok[32] ints
#define SM_FLOATS 41316
#define SMEM_BYTES (SM_FLOATS * 4)          // 165,264 B (< 227KB opt-in cap)

// ---------------- generic helpers ------------------------------------------
__device__ __forceinline__ float sigm(float x) { return 1.0f / (1.0f + __expf(-x)); }

__device__ __forceinline__ unsigned f2ord(float f) {
    unsigned u = __float_as_uint(f);
    return (u & 0x80000000u) ? ~u : (u | 0x80000000u);
}
__device__ __forceinline__ float ord2f(unsigned o) {
    return __uint_as_float((o & 0x80000000u) ? (o ^ 0x80000000u) : ~o);
}

// m16n8k16 f32.f16.f16.f32 (row.col), accumulate in place
__device__ __forceinline__ void mma16816(float& c0, float& c1, float& c2, float& c3,
                                         unsigned a0, unsigned a1, unsigned a2, unsigned a3,
                                         unsigned b0, unsigned b1) {
    asm volatile(
        "mma.sync.aligned.m16n8k16.row.col.f32.f16.f16.f32 "
        "{%0,%1,%2,%3}, {%4,%5,%6,%7}, {%8,%9}, {%0,%1,%2,%3};"
        : "+f"(c0), "+f"(c1), "+f"(c2), "+f"(c3)
        : "r"(a0), "r"(a1), "r"(a2), "r"(a3), "r"(b0), "r"(b1));
}

// grid-wide barrier: counter k, zeroed by prologue each launch
__device__ __forceinline__ void gbar(int k) {
    __syncthreads();
    if (threadIdx.x == 0) {
        __threadfence();
        atomicAdd(&g_bar[k], 1);
        while (*(volatile int*)&g_bar[k] < NBLK) { }
        __threadfence();
    }
    __syncthreads();
}

// v-span: 32000 = 32*217 + 116*216
__device__ __forceinline__ void vspan(int bid, int& v0, int& n) {
    if (bid < 32) { v0 = bid * 217; n = 217; }
    else          { v0 = 6944 + (bid - 32) * 216; n = 216; }
}

// pack float2 -> fp16 hi & lo residual words
__device__ __forceinline__ void split16(float x0, float x1, unsigned& hi, unsigned& lo) {
    __half h0 = __float2half_rn(x0), h1 = __float2half_rn(x1);
    __half l0 = __float2half_rn(x0 - __half2float(h0));
    __half l1 = __float2half_rn(x1 - __half2float(h1));
    hi = ((unsigned)__half_as_ushort(h1) << 16) | __half_as_ushort(h0);
    lo = ((unsigned)__half_as_ushort(l1) << 16) | __half_as_ushort(l0);
}

// ---------------- Wo fp16 split precompute ----------------------------------
__global__ void __launch_bounds__(512)
k_split(const float* __restrict__ Wo) {
    int idx = blockIdx.x * 512 + threadIdx.x;   // = p*Vv + v
    int p = idx / Vv, v = idx - p * Vv;
    float w0 = Wo[(2 * p) * Vv + v];
    float w1 = Wo[(2 * p + 1) * Vv + v];
    unsigned hi, lo;
    split16(w0, w1, hi, lo);
    g_w16h[idx] = hi;
    g_w16l[idx] = lo;
}

// ---------------- prologue: teacher x-gates + barrier reset ----------------
__global__ void __launch_bounds__(512)
k_prologue(const int* __restrict__ x, const float* __restrict__ emb,
           const float* __restrict__ Wi, const float* __restrict__ bi,
           const float* __restrict__ Wf, const float* __restrict__ bf,
           const float* __restrict__ Wog, const float* __restrict__ bog,
           const float* __restrict__ Wc, const float* __restrict__ bc) {
    int p0 = blockIdx.x * 16;
    int tid = threadIdx.x;
    int g = tid >> 7, j = tid & 127;

    __shared__ int   tok_s[16];
    __shared__ float xe[16][Ee];

    if (blockIdx.x == 0) {
        if (tid < 2 * Ss) g_bar[tid] = 0;
        if (tid == 0) g_loss = 0.0f;
    }
    if (tid < 16) {
        int p = p0 + tid;
        int t = p >> 5, b = p & 31;
        tok_s[tid] = (t == 0) ? 0 : x[b * Ss + (t - 1)];
    }
    __syncthreads();
    for (int idx = tid; idx < 16 * Ee; idx += 512) {
        int pp = idx >> 7, kk = idx & 127;
        xe[pp][kk] = emb[tok_s[pp] * Ee + kk];
    }
    __syncthreads();

    const float* W = (g == 0) ? Wi : (g == 1) ? Wf : (g == 2) ? Wog : Wc;
    float bias = ((g == 0) ? bi : (g == 1) ? bf : (g == 2) ? bog : bc)[j];

    float acc[16];
#pragma unroll
    for (int pp = 0; pp < 16; ++pp) acc[pp] = bias;

#pragma unroll 4
    for (int k = 0; k < Ee; ++k) {
        float w = W[k * Hh + j];
#pragma unroll
        for (int pp = 0; pp < 16; ++pp) acc[pp] += xe[pp][k] * w;
    }
#pragma unroll
    for (int pp = 0; pp < 16; ++pp)
        g_xg[(p0 + pp) * 4 * Hh + tid] = acc[pp];
}

// ---------------- persistent fused recurrence (mma.sync GEMM) --------------
__global__ void __launch_bounds__(NTHR, 1)
k_persist(const int* __restrict__ x, const float* __restrict__ emb,
          const float* __restrict__ Wi, const float* __restrict__ Ui, const float* __restrict__ bi,
          const float* __restrict__ Wf, const float* __restrict__ Uf, const float* __restrict__ bf,
          const float* __restrict__ Wog, const float* __restrict__ Uog, const float* __restrict__ bog,
          const float* __restrict__ Wc, const float* __restrict__ Uc, const float* __restrict__ bc,
          const float* __restrict__ bo, float* __restrict__ out) {
    extern __shared__ float smf[];
    int tid = threadIdx.x, bid = blockIdx.x;
    int lane = tid & 31, wz = tid >> 5;
    bool iscell = (bid < 128);
    int j = bid;
    float* pred = out + PRED_OFF;
    int* tgt_s = (int*)(smf + SM_TGT);
    int* tok_s = (int*)(smf + SM_TOK);
    unsigned long long* wkey = (unsigned long long*)(smf + SM_WKEY);
    uint2* BH2 = (uint2*)(smf + SM_BH2);
    uint2* BL2 = (uint2*)(smf + SM_BL2);

    // one-time: cell blocks load their W/U column slice + bias into SMEM
    if (iscell) {
        for (int idx = tid; idx < 1024; idx += NTHR) {
            int g = idx >> 8, k = idx & 255;
            const float* W = (g == 0) ? Wi : (g == 1) ? Wf : (g == 2) ? Wog : Wc;
            const float* U = (g == 0) ? Ui : (g == 1) ? Uf : (g == 2) ? Uog : Uc;
            smf[SM_WSM + g * 257 + k] =
                (k < 128) ? W[k * Hh + j] : U[(k - 128) * Hh + j];
        }
        if (tid < 4) {
            const float* bv = (tid == 0) ? bi : (tid == 1) ? bf : (tid == 2) ? bog : bc;
            smf[SM_WSM + tid * 257 + 256] = bv[j];
        }
    }

    int v0, span;
    vspan(bid, v0, span);

    int gid = lane >> 2, tig = lane & 3;   // mma fragment coords

    // one-time: persistent A-hi fragment cache + bo (step-invariant)
    int vA = v0 + wz * 16 + gid;           // true v for c0/c1; vA+8 for c2/c3
    int vAc  = (vA < Vv) ? vA : (Vv - 1);
    int vA8c = (vA + 8 < Vv) ? (vA + 8) : (Vv - 1);
    unsigned ahreg[8][4];
    float bov0 = 0.f, bov8 = 0.f;
    if (wz < 14) {
#pragma unroll
        for (int k0 = 0; k0 < 8; ++k0) {
            const unsigned* Wh = g_w16h + (k0 * 8 + tig) * Vv;
            ahreg[k0][0] = Wh[vAc];
            ahreg[k0][1] = Wh[vA8c];
            ahreg[k0][2] = Wh[4 * Vv + vAc];
            ahreg[k0][3] = Wh[4 * Vv + vA8c];
        }
        bov0 = bo[vAc];
        bov8 = bo[vA8c];
    }

    // cell k-split role: row cr, gate cg, k-half chf
    int cr = tid & 63;
    int cq = tid >> 6;                     // 0..7
    int cg = cq & 3, chf = cq >> 2;

    // E0 (deferred prob write) role: b = tid>>4, chunk = tid&15
    int cb = tid >> 4, cch = tid & 15;

    // E2 role: r = tid>>3 (0..63), seg = tid&7 (28 cols each)
    int e2r = tid >> 3, e2s = tid & 7;

    for (int t = 0; t < Ss; ++t) {
        int nb = 1 - (t & 1);              // h_t buffer written by cell

        // ================= cell phase =================
        if (iscell) {
            if (t == 0) {
                for (int idx = tid; idx < RR * Hh; idx += NTHR) {
                    int k = idx & 127, r = idx >> 7;
                    smf[SM_HS + k * HS_STRIDE + r] = 0.0f;
                }
                if (tid < Bb) tok_s[tid] = 0;
            } else if (tid < Bb) {
                unsigned long long key = g_packmax[(t - 1) * Bb + tid];
                tok_s[tid] = (int)(0xFFFFFFFFu - (unsigned)(key & 0xFFFFFFFFull));
            }
            __syncthreads();
            for (int idx = tid; idx < Bb * Ee; idx += NTHR) {
                int r = idx >> 7, k = idx & 127;
                smf[SM_XE + r * 129 + k] = emb[tok_s[r] * Ee + k];
            }
            __syncthreads();

            // k-split gate compute: all 512 threads
            {
                const float* wrow = smf + SM_WSM + cg * 257;
                float a0 = 0.f, a1 = 0.f, a2 = 0.f, a3 = 0.f;
                if (cr < Bb) {
                    // teacher: U half [chf*64, +64)
                    int kb = chf * 64;
                    const float* hc = smf + SM_HS + cr;
#pragma unroll 8
                    for (int kk = 0; kk < 64; kk += 4) {
                        int k = kb + kk;
                        a0 = fmaf(hc[(k + 0) * HS_STRIDE], wrow[128 + k + 0], a0);
                        a1 = fmaf(hc[(k + 1) * HS_STRIDE], wrow[128 + k + 1], a1);
                        a2 = fmaf(hc[(k + 2) * HS_STRIDE], wrow[128 + k + 2], a2);
                        a3 = fmaf(hc[(k + 3) * HS_STRIDE], wrow[128 + k + 3], a3);
                    }
                } else if (chf == 0) {
                    // gen: W half (x embedding)
                    const float* xr = smf + SM_XE + (cr - Bb) * 129;
#pragma unroll 8
                    for (int k = 0; k < 128; k += 4) {
                        a0 = fmaf(xr[k + 0], wrow[k + 0], a0);
                        a1 = fmaf(xr[k + 1], wrow[k + 1], a1);
                        a2 = fmaf(xr[k + 2], wrow[k + 2], a2);
                        a3 = fmaf(xr[k + 3], wrow[k + 3], a3);
                    }
                } else {
                    // gen: U half (h recurrence)
                    const float* hc = smf + SM_HS + cr;
#pragma unroll 8
                    for (int k = 0; k < 128; k += 4) {
                        a0 = fmaf(hc[(k + 0) * HS_STRIDE], wrow[128 + k + 0], a0);
                        a1 = fmaf(hc[(k + 1) * HS_STRIDE], wrow[128 + k + 1], a1);
                        a2 = fmaf(hc[(k + 2) * HS_STRIDE], wrow[128 + k + 2], a2);
                        a3 = fmaf(hc[(k + 3) * HS_STRIDE], wrow[128 + k + 3], a3);
                    }
                }
                smf[SM_PART + chf * 256 + cg * 64 + cr] = (a0 + a1) + (a2 + a3);
            }
            __syncthreads();
            if (tid < 256) {
                int g = tid >> 6, r = tid & 63;
                float base = (r < Bb)
                    ? g_xg[(t * Bb + r) * 4 * Hh + g * Hh + j]
                    : smf[SM_WSM + g * 257 + 256];
                smf[SM_GS + tid] = base + smf[SM_PART + tid] + smf[SM_PART + 256 + tid];
            }
            __syncthreads();
            if (tid < RR) {
                int r = tid;
                float cp = (t == 0) ? 0.0f : g_c[r * Hh + j];
                float ig = sigm(smf[SM_GS + 0 * 64 + r]);
                float fg = sigm(smf[SM_GS + 1 * 64 + r]);
                float og = sigm(smf[SM_GS + 2 * 64 + r]);
                float cn = fg * cp + ig * tanhf(smf[SM_GS + 3 * 64 + r]);
                float hn = og * tanhf(cn);
                g_c[r * Hh + j] = cn;
                g_hbuf[nb][r * Hh + j] = hn;
            }
        } else if (bid == 128) {
            if (tid < RR) g_sumexp[t * RR + tid] = 0.0f;
            else if (tid < RR + Bb) g_packmax[t * Bb + (tid - RR)] = 0ull;
        } else if (bid == 129 && t > 0) {
            if (tid < Bb) {
                unsigned long long key = g_packmax[(t - 1) * Bb + tid];
                int tok = (int)(0xFFFFFFFFu - (unsigned)(key & 0xFFFFFFFFull));
                out[tid * Ss + (t - 1)] = (float)tok;
                float emax = ord2f((unsigned)(key >> 32));
                out[Bb * Ss + tid * Ss + (t - 1)] =
                    emax / g_sumexp[(t - 1) * RR + Bb + tid];
            }
        }
        gbar(2 * t);

        // ================= GEMM phase (all blocks) =================
        // E0: deferred prob write for step t-1 (reads old D_s e-values)
        if (t > 0) {
            float inv = __fdividef(1.0f, g_sumexp[(t - 1) * RR + cb]);
#pragma unroll 2
            for (int i = 0; i < 14; ++i) {
                int col = cch + 16 * i;     // 0..223
                if (col < span) {
                    float e = smf[SM_DS + col * DS_STRIDE + cb];
                    pred[(cb * Ss + (t - 1)) * Vv + v0 + col] = e * inv;
                }
            }
        }

        const float* hsrc = g_hbuf[nb];

        // h_sT for next cell phase
        for (int idx = tid; idx < RR * Hh; idx += NTHR) {
            int k = idx & 127, r = idx >> 7;
            smf[SM_HS + k * HS_STRIDE + r] = hsrc[r * Hh + k];
        }
        // B staging: pair-packed uint2 (hp[p], hp[p+4]) per (q = k0*4+tig, n)
        for (int idx = tid; idx < 32 * 64; idx += NTHR) {
            int q = idx >> 6, n = idx & 63;
            int p_lo = (q >> 2) * 8 + (q & 3);     // k0*8 + tig
            int p_hi = p_lo + 4;
            float2 hv0 = *(const float2*)(hsrc + n * Hh + 2 * p_lo);
            float2 hv1 = *(const float2*)(hsrc + n * Hh + 2 * p_hi);
            unsigned hiw0, low0, hiw1, low1;
            split16(hv0.x, hv0.y, hiw0, low0);
            split16(hv1.x, hv1.y, hiw1, low1);
            BH2[q * HP2_STRIDE + n] = make_uint2(hiw0, hiw1);
            BL2[q * HP2_STRIDE + n] = make_uint2(low0, low1);
        }
        if (tid < Bb) tgt_s[tid] = x[tid * Ss + t];
        __syncthreads();

        // mma compute + merged E1: warp wz handles m-tile wz (14 tiles)
        // A-hi persistent regs; A-lo loads per step (gen pass 3 only).
        // teacher n-tiles (nt 0..3): 2 passes; gen n-tiles (nt 4..7): 3 passes
        if (wz < 14) {
            float acc[8][4];
#pragma unroll
            for (int nt = 0; nt < 8; ++nt) {
                acc[nt][0] = 0.f; acc[nt][1] = 0.f;
                acc[nt][2] = 0.f; acc[nt][3] = 0.f;
            }
#pragma unroll
            for (int k0 = 0; k0 < 8; ++k0) {
                int pA = k0 * 8 + tig;
                const unsigned* Wl = g_w16l + pA * Vv;
                unsigned al0 = Wl[vAc],          al1 = Wl[vA8c];
                unsigned al2 = Wl[4 * Vv + vAc], al3 = Wl[4 * Vv + vA8c];
                const uint2* BHq = BH2 + (k0 * 4 + tig) * HP2_STRIDE + gid;
                const uint2* BLq = BL2 + (k0 * 4 + tig) * HP2_STRIDE + gid;
#pragma unroll
                for (int nt = 0; nt < 8; ++nt) {
                    uint2 bh = BHq[nt * 8];
                    uint2 bl = BLq[nt * 8];
                    mma16816(acc[nt][0], acc[nt][1], acc[nt][2], acc[nt][3],
                             ahreg[k0][0], ahreg[k0][1], ahreg[k0][2], ahreg[k0][3],
                             bh.x, bh.y);
                    mma16816(acc[nt][0], acc[nt][1], acc[nt][2], acc[nt][3],
                             ahreg[k0][0], ahreg[k0][1], ahreg[k0][2], ahreg[k0][3],
                             bl.x, bl.y);
                    if (nt >= 4)
                        mma16816(acc[nt][0], acc[nt][1], acc[nt][2], acc[nt][3],
                                 al0, al1, al2, al3, bh.x, bh.y);
                }
            }
            // merged E1: bias add, loss check, exp, store e-values to D_s
            int vloc0 = wz * 16 + gid;
            bool a0ok = (vloc0 < span), a8ok = (vloc0 + 8 < span);
#pragma unroll
            for (int nt = 0; nt < 8; ++nt) {
                int row0 = nt * 8 + 2 * tig;
                float l0 = acc[nt][0] + bov0, l1 = acc[nt][1] + bov0;
                float l2 = acc[nt][2] + bov8, l3 = acc[nt][3] + bov8;
                if (nt < 4) {   // teacher rows: loss at target
                    if (a0ok && vA == tgt_s[row0])         atomicAdd(&g_loss, l0);
                    if (a0ok && vA == tgt_s[row0 + 1])     atomicAdd(&g_loss, l1);
                    if (a8ok && vA + 8 == tgt_s[row0])     atomicAdd(&g_loss, l2);
                    if (a8ok && vA + 8 == tgt_s[row0 + 1]) atomicAdd(&g_loss, l3);
                }
                int r0 = SM_DS + vloc0 * DS_STRIDE + row0;
                smf[r0]     = a0ok ? __expf(l0) : 0.0f;
                smf[r0 + 1] = a0ok ? __expf(l1) : 0.0f;
                smf[r0 + 8 * DS_STRIDE]     = a8ok ? __expf(l2) : 0.0f;
                smf[r0 + 8 * DS_STRIDE + 1] = a8ok ? __expf(l3) : 0.0f;
            }
        }
        __syncthreads();

        // ---------------- E2: segmented reductions from D_s --------------
        {
            const float* base = smf + SM_DS + e2r;
            float s = 0.0f;
            float emax = -1.0f; int cbest = 0;
            int c0 = e2s * 28;
#pragma unroll 7
            for (int i = 0; i < 28; ++i) {
                float e = base[(c0 + i) * DS_STRIDE];
                s += e;
                if (e2r >= Bb && e > emax) { emax = e; cbest = c0 + i; }
            }
            smf[SM_WSUM + e2s * 64 + e2r] = s;
            if (e2r >= Bb) {
                wkey[e2s * 32 + (e2r - Bb)] =
                    ((unsigned long long)f2ord(emax) << 32) |
                    (unsigned long long)(0xFFFFFFFFu - (unsigned)(v0 + cbest));
            }
        }
        __syncthreads();

        if (tid < RR) {
            float s = 0.0f;
#pragma unroll
            for (int w = 0; w < 8; ++w) s += smf[SM_WSUM + w * 64 + tid];
            atomicAdd(&g_sumexp[t * RR + tid], s);
        } else if (tid < RR + Bb) {
            int gr = tid - RR;
            unsigned long long m = 0ull;
#pragma unroll
            for (int w = 0; w < 8; ++w) {
                unsigned long long k = wkey[w * 32 + gr];
                m = (k > m) ? k : m;
            }
            atomicMax(&g_packmax[t * Bb + gr], m);
        }
        gbar(2 * t + 1);
    }

    // final flush: probs for t=31 (sumexp[31] final after last gbar)
    {
        float inv = __fdividef(1.0f, g_sumexp[(Ss - 1) * RR + cb]);
#pragma unroll 2
        for (int i = 0; i < 14; ++i) {
            int col = cch + 16 * i;
            if (col < span) {
                float e = smf[SM_DS + col * DS_STRIDE + cb];
                pred[(cb * Ss + (Ss - 1)) * Vv + v0 + col] = e * inv;
            }
        }
    }
}

// ---------------- epilogue: last gen outputs + loss -------------------------
__global__ void k_fin1(float* __restrict__ out) {
    __shared__ float red[1024];
    int tid = threadIdx.x;
    int t = tid >> 5, b = tid & 31;

    float se = g_sumexp[t * RR + b];
    red[tid] = logf(se);

    if (tid < Bb) {
        unsigned long long key = g_packmax[(Ss - 1) * Bb + tid];
        int tok = (int)(0xFFFFFFFFu - (unsigned)(key & 0xFFFFFFFFull));
        out[tid * Ss + (Ss - 1)] = (float)tok;
        float emax = ord2f((unsigned)(key >> 32));
        out[Bb * Ss + tid * Ss + (Ss - 1)] =
            emax / g_sumexp[(Ss - 1) * RR + Bb + tid];
    }
    __syncthreads();
    for (int s = 512; s > 0; s >>= 1) {
        if (tid < s) red[tid] += red[tid + s];
        __syncthreads();
    }
    if (tid == 0)
        out[PRED_OFF + PRED_N] = (red[0] - g_loss) / (float)(Ss * Bb);
}

// ---------------- launch ---------------------------------------------------
extern "C" void kernel_launch(void* const* d_in, const int* in_sizes, int n_in,
                              void* d_out, int out_size) {
    const int*   x   = (const int*)d_in[0];
    const float* emb = (const float*)d_in[1];
    const float* Wi  = (const float*)d_in[2];
    const float* Ui  = (const float*)d_in[3];
    const float* bi  = (const float*)d_in[4];
    const float* Wf  = (const float*)d_in[5];
    const float* Uf  = (const float*)d_in[6];
    const float* bf  = (const float*)d_in[7];
    const float* Wog = (const float*)d_in[8];
    const float* Uog = (const float*)d_in[9];
    const float* bog = (const float*)d_in[10];
    const float* Wc  = (const float*)d_in[11];
    const float* Uc  = (const float*)d_in[12];
    const float* bc  = (const float*)d_in[13];
    const float* Wo  = (const float*)d_in[14];
    const float* bo  = (const float*)d_in[15];
    float* out = (float*)d_out;

    cudaFuncSetAttribute(k_persist,
                         cudaFuncAttributeMaxDynamicSharedMemorySize,
                         SMEM_BYTES);

    k_split<<<64 * Vv / 512, 512>>>(Wo);
    k_prologue<<<Ss * Bb / 16, 512>>>(x, emb, Wi, bi, Wf, bf, Wog, bog, Wc, bc);
    k_persist<<<NBLK, NTHR, SMEM_BYTES>>>(x, emb,
                                          Wi, Ui, bi, Wf, Uf, bf,
                                          Wog, Uog, bog, Wc, Uc, bc,
                                          bo, out);
    k_fin1<<<1, 1024>>>(out);
}

// round 15
// speedup vs baseline: 2.4762x; 1.0455x over previous
#include <cuda_runtime.h>
#include <cuda_fp16.h>
#include <cstdint>

// Problem dims
#define Vv 32000
#define Ee 128
#define Hh 128
#define Bb 32
#define Ss 32
#define RR 64                  // 64 fused rows: 0..31 teacher, 32..63 generation
#define NBLK 148               // persistent grid (1 block/SM, all resident)
#define NTHR 512
#define HS_STRIDE 68           // h_s row stride
#define HP2_STRIDE 68          // packed-B uint2 row stride (conflict-free 8B loads)
#define DS_STRIDE 66           // D staging row stride

static const int PRED_OFF = 2048;           // gen_x[1024] + gen_o[1024]
static const int PRED_N   = Bb * Ss * Vv;   // 32,768,000

// ---------------- persistent device scratch (no allocations allowed) -------
__device__ float               g_hbuf[2][RR * Hh];      // double-buffered h
__device__ float               g_c[RR * Hh];
__device__ float               g_xg[Ss * Bb * 4 * Hh];  // teacher x-gates (with bias)
__device__ float               g_sumexp[Ss * RR];
__device__ unsigned long long  g_packmax[Ss * Bb];      // key = f2ord(e_max) || ~v
__device__ float               g_loss;                  // sum of logit at target
__device__ int                 g_bar[2 * Ss];           // grid barrier counters
__device__ unsigned            g_w16h[64 * Vv];         // Wo fp16-hi pairs, [p][v]
__device__ unsigned            g_w16l[64 * Vv];         // Wo fp16-lo pairs, [p][v]

// ---------------- shared-memory layout (float words) -----------------------
#define SM_HS    0                          // h_s[128][HS_STRIDE] (8704)
#define SM_DS    8704                       // D staging [256][DS_STRIDE] (16896)
#define SM_XE    25600                      // xe[32][129] gen embeddings (4128)
#define SM_BH2   29728                      // B-hi uint2[32][HP2_STRIDE] (4352 w)
#define SM_BL2   34080                      // B-lo uint2[32][HP2_STRIDE] (4352 w)
#define SM_WSM   38432                      // wsm[4][257] cell weights+bias (1028)
#define SM_PART  39460                      // cell k-split partials (512)
#define SM_GS    39972                      // gates (256)
#define SM_WSUM  40228                      // wsum[8][64] (512)
#define SM_WKEY  40740                      // wkey[8][32] ull (512 w, 8B-aligned)
#define SM_TGT   41252                      // tgt[32] ints
#define SM_TOK   41284                      // tok[32] ints
#define SM_FLOATS 41316
#define SMEM_BYTES (SM_FLOATS * 4)          // 165,264 B (< 227KB opt-in cap)

// ---------------- generic helpers ------------------------------------------
__device__ __forceinline__ float sigm(float x) { return 1.0f / (1.0f + __expf(-x)); }

__device__ __forceinline__ unsigned f2ord(float f) {
    unsigned u = __float_as_uint(f);
    return (u & 0x80000000u) ? ~u : (u | 0x80000000u);
}
__device__ __forceinline__ float ord2f(unsigned o) {
    return __uint_as_float((o & 0x80000000u) ? (o ^ 0x80000000u) : ~o);
}

// m16n8k16 f32.f16.f16.f32 (row.col), accumulate in place
__device__ __forceinline__ void mma16816(float& c0, float& c1, float& c2, float& c3,
                                         unsigned a0, unsigned a1, unsigned a2, unsigned a3,
                                         unsigned b0, unsigned b1) {
    asm volatile(
        "mma.sync.aligned.m16n8k16.row.col.f32.f16.f16.f32 "
        "{%0,%1,%2,%3}, {%4,%5,%6,%7}, {%8,%9}, {%0,%1,%2,%3};"
        : "+f"(c0), "+f"(c1), "+f"(c2), "+f"(c3)
        : "r"(a0), "r"(a1), "r"(a2), "r"(a3), "r"(b0), "r"(b1));
}

// grid-wide barrier: counter k, zeroed by prologue each launch
__device__ __forceinline__ void gbar(int k) {
    __syncthreads();
    if (threadIdx.x == 0) {
        __threadfence();
        atomicAdd(&g_bar[k], 1);
        while (*(volatile int*)&g_bar[k] < NBLK) { }
        __threadfence();
    }
    __syncthreads();
}

// v-span: 32000 = 32*217 + 116*216
__device__ __forceinline__ void vspan(int bid, int& v0, int& n) {
    if (bid < 32) { v0 = bid * 217; n = 217; }
    else          { v0 = 6944 + (bid - 32) * 216; n = 216; }
}

// pack float2 -> fp16 hi & lo residual words
__device__ __forceinline__ void split16(float x0, float x1, unsigned& hi, unsigned& lo) {
    __half h0 = __float2half_rn(x0), h1 = __float2half_rn(x1);
    __half l0 = __float2half_rn(x0 - __half2float(h0));
    __half l1 = __float2half_rn(x1 - __half2float(h1));
    hi = ((unsigned)__half_as_ushort(h1) << 16) | __half_as_ushort(h0);
    lo = ((unsigned)__half_as_ushort(l1) << 16) | __half_as_ushort(l0);
}

// ---------------- Wo fp16 split precompute ----------------------------------
__global__ void __launch_bounds__(512)
k_split(const float* __restrict__ Wo) {
    int idx = blockIdx.x * 512 + threadIdx.x;   // = p*Vv + v
    int p = idx / Vv, v = idx - p * Vv;
    float w0 = Wo[(2 * p) * Vv + v];
    float w1 = Wo[(2 * p + 1) * Vv + v];
    unsigned hi, lo;
    split16(w0, w1, hi, lo);
    g_w16h[idx] = hi;
    g_w16l[idx] = lo;
}

// ---------------- prologue: teacher x-gates + barrier reset ----------------
__global__ void __launch_bounds__(512)
k_prologue(const int* __restrict__ x, const float* __restrict__ emb,
           const float* __restrict__ Wi, const float* __restrict__ bi,
           const float* __restrict__ Wf, const float* __restrict__ bf,
           const float* __restrict__ Wog, const float* __restrict__ bog,
           const float* __restrict__ Wc, const float* __restrict__ bc) {
    int p0 = blockIdx.x * 16;
    int tid = threadIdx.x;
    int g = tid >> 7, j = tid & 127;

    __shared__ int   tok_s[16];
    __shared__ float xe[16][Ee];

    if (blockIdx.x == 0) {
        if (tid < 2 * Ss) g_bar[tid] = 0;
        if (tid == 0) g_loss = 0.0f;
    }
    if (tid < 16) {
        int p = p0 + tid;
        int t = p >> 5, b = p & 31;
        tok_s[tid] = (t == 0) ? 0 : x[b * Ss + (t - 1)];
    }
    __syncthreads();
    for (int idx = tid; idx < 16 * Ee; idx += 512) {
        int pp = idx >> 7, kk = idx & 127;
        xe[pp][kk] = emb[tok_s[pp] * Ee + kk];
    }
    __syncthreads();

    const float* W = (g == 0) ? Wi : (g == 1) ? Wf : (g == 2) ? Wog : Wc;
    float bias = ((g == 0) ? bi : (g == 1) ? bf : (g == 2) ? bog : bc)[j];

    float acc[16];
#pragma unroll
    for (int pp = 0; pp < 16; ++pp) acc[pp] = bias;

#pragma unroll 4
    for (int k = 0; k < Ee; ++k) {
        float w = W[k * Hh + j];
#pragma unroll
        for (int pp = 0; pp < 16; ++pp) acc[pp] += xe[pp][k] * w;
    }
#pragma unroll
    for (int pp = 0; pp < 16; ++pp)
        g_xg[(p0 + pp) * 4 * Hh + tid] = acc[pp];
}

// ---------------- persistent fused recurrence (mma.sync GEMM) --------------
__global__ void __launch_bounds__(NTHR, 1)
k_persist(const int* __restrict__ x, const float* __restrict__ emb,
          const float* __restrict__ Wi, const float* __restrict__ Ui, const float* __restrict__ bi,
          const float* __restrict__ Wf, const float* __restrict__ Uf, const float* __restrict__ bf,
          const float* __restrict__ Wog, const float* __restrict__ Uog, const float* __restrict__ bog,
          const float* __restrict__ Wc, const float* __restrict__ Uc, const float* __restrict__ bc,
          const float* __restrict__ bo, float* __restrict__ out) {
    extern __shared__ float smf[];
    int tid = threadIdx.x, bid = blockIdx.x;
    int lane = tid & 31, wz = tid >> 5;
    bool iscell = (bid < 128);
    int j = bid;
    float* pred = out + PRED_OFF;
    int* tgt_s = (int*)(smf + SM_TGT);
    int* tok_s = (int*)(smf + SM_TOK);
    unsigned long long* wkey = (unsigned long long*)(smf + SM_WKEY);
    uint2* BH2 = (uint2*)(smf + SM_BH2);
    uint2* BL2 = (uint2*)(smf + SM_BL2);

    // one-time: cell blocks load their W/U column slice + bias into SMEM
    if (iscell) {
        for (int idx = tid; idx < 1024; idx += NTHR) {
            int g = idx >> 8, k = idx & 255;
            const float* W = (g == 0) ? Wi : (g == 1) ? Wf : (g == 2) ? Wog : Wc;
            const float* U = (g == 0) ? Ui : (g == 1) ? Uf : (g == 2) ? Uog : Uc;
            smf[SM_WSM + g * 257 + k] =
                (k < 128) ? W[k * Hh + j] : U[(k - 128) * Hh + j];
        }
        if (tid < 4) {
            const float* bv = (tid == 0) ? bi : (tid == 1) ? bf : (tid == 2) ? bog : bc;
            smf[SM_WSM + tid * 257 + 256] = bv[j];
        }
    }

    int v0, span;
    vspan(bid, v0, span);

    int gid = lane >> 2, tig = lane & 3;   // mma fragment coords

    // one-time: persistent A-hi fragment cache + bo (step-invariant)
    int vA = v0 + wz * 16 + gid;           // true v for c0/c1; vA+8 for c2/c3
    int vAc  = (vA < Vv) ? vA : (Vv - 1);
    int vA8c = (vA + 8 < Vv) ? (vA + 8) : (Vv - 1);
    unsigned ahreg[8][4];
    float bov0 = 0.f, bov8 = 0.f;
    if (wz < 14) {
#pragma unroll
        for (int k0 = 0; k0 < 8; ++k0) {
            const unsigned* Wh = g_w16h + (k0 * 8 + tig) * Vv;
            ahreg[k0][0] = Wh[vAc];
            ahreg[k0][1] = Wh[vA8c];
            ahreg[k0][2] = Wh[4 * Vv + vAc];
            ahreg[k0][3] = Wh[4 * Vv + vA8c];
        }
        bov0 = bo[vAc];
        bov8 = bo[vA8c];
    }

    // t==0 full-cell role (old mapping): row cr, gate cg, k-half chf
    int cr = tid & 63;
    int cq = tid >> 6;
    int cg0 = cq & 3, chf = cq >> 2;

    // gen-cell role (t>=1): row gr (0..31 -> 32+gr), gate gg, k-quarter gkq
    int gr = tid & 31, gg = (tid >> 5) & 3, gkq = tid >> 7;

    // E0 (deferred prob write) role: b = tid>>4, chunk = tid&15
    int cb = tid >> 4, cch = tid & 15;

    // E2 role: r = tid>>3 (0..63), seg = tid&7 (28 cols each)
    int e2r = tid >> 3, e2s = tid & 7;

    for (int t = 0; t < Ss; ++t) {
        int nb = 1 - (t & 1);              // h_t buffer written for step t

        // ================= cell phase =================
        // E0: deferred prob write for step t-1 (all blocks; D_s + sumexp final)
        if (t > 0) {
            float inv = __fdividef(1.0f, g_sumexp[(t - 1) * RR + cb]);
#pragma unroll 2
            for (int i = 0; i < 14; ++i) {
                int col = cch + 16 * i;     // 0..223
                if (col < span) {
                    float e = smf[SM_DS + col * DS_STRIDE + cb];
                    pred[(cb * Ss + (t - 1)) * Vv + v0 + col] = e * inv;
                }
            }
        }

        if (iscell) {
            if (t == 0) {
                // full cell (teacher + gen), h0 = 0
                for (int idx = tid; idx < RR * Hh; idx += NTHR) {
                    int k = idx & 127, r = idx >> 7;
                    smf[SM_HS + k * HS_STRIDE + r] = 0.0f;
                }
                if (tid < Bb) tok_s[tid] = 0;
                __syncthreads();
                for (int idx = tid; idx < Bb * Ee; idx += NTHR) {
                    int r = idx >> 7, k = idx & 127;
                    smf[SM_XE + r * 129 + k] = emb[tok_s[r] * Ee + k];
                }
                __syncthreads();
                {
                    const float* wrow = smf + SM_WSM + cg0 * 257;
                    float a0 = 0.f, a1 = 0.f, a2 = 0.f, a3 = 0.f;
                    if (cr >= Bb && chf == 0) {
                        const float* xr = smf + SM_XE + (cr - Bb) * 129;
#pragma unroll 8
                        for (int k = 0; k < 128; k += 4) {
                            a0 = fmaf(xr[k + 0], wrow[k + 0], a0);
                            a1 = fmaf(xr[k + 1], wrow[k + 1], a1);
                            a2 = fmaf(xr[k + 2], wrow[k + 2], a2);
                            a3 = fmaf(xr[k + 3], wrow[k + 3], a3);
                        }
                    }
                    smf[SM_PART + chf * 256 + cg0 * 64 + cr] = (a0 + a1) + (a2 + a3);
                }
                __syncthreads();
                if (tid < 256) {
                    int g = tid >> 6, r = tid & 63;
                    float base = (r < Bb)
                        ? g_xg[(t * Bb + r) * 4 * Hh + g * Hh + j]
                        : smf[SM_WSM + g * 257 + 256];
                    smf[SM_GS + tid] = base + smf[SM_PART + tid] + smf[SM_PART + 256 + tid];
                }
                __syncthreads();
                if (tid < RR) {
                    int r = tid;
                    float ig = sigm(smf[SM_GS + 0 * 64 + r]);
                    float og = sigm(smf[SM_GS + 2 * 64 + r]);
                    float cn = ig * tanhf(smf[SM_GS + 3 * 64 + r]);   // f*c0 = 0
                    float hn = og * tanhf(cn);
                    g_c[r * Hh + j] = cn;
                    g_hbuf[nb][r * Hh + j] = hn;
                }
            } else {
                // gen-only cell: teacher h/c(t) already written during GEMM(t-1)
                if (tid < Bb) {
                    unsigned long long key = g_packmax[(t - 1) * Bb + tid];
                    tok_s[tid] = (int)(0xFFFFFFFFu - (unsigned)(key & 0xFFFFFFFFull));
                }
                __syncthreads();
                for (int idx = tid; idx < Bb * Ee; idx += NTHR) {
                    int r = idx >> 7, k = idx & 127;
                    smf[SM_XE + r * 129 + k] = emb[tok_s[r] * Ee + k];
                }
                __syncthreads();
                // 512-thread 4-quarter k-split over 256 combined k (W then U)
                {
                    const float* wrow = smf + SM_WSM + gg * 257;
                    float a0 = 0.f, a1 = 0.f, a2 = 0.f, a3 = 0.f;
                    if (gkq < 2) {
                        const float* xr = smf + SM_XE + gr * 129 + gkq * 64;
                        const float* wr = wrow + gkq * 64;
#pragma unroll 8
                        for (int k = 0; k < 64; k += 4) {
                            a0 = fmaf(xr[k + 0], wr[k + 0], a0);
                            a1 = fmaf(xr[k + 1], wr[k + 1], a1);
                            a2 = fmaf(xr[k + 2], wr[k + 2], a2);
                            a3 = fmaf(xr[k + 3], wr[k + 3], a3);
                        }
                    } else {
                        int kb = (gkq - 2) * 64;
                        const float* hc = smf + SM_HS + (Bb + gr);
                        const float* wr = wrow + 128 + kb;
#pragma unroll 8
                        for (int k = 0; k < 64; k += 4) {
                            a0 = fmaf(hc[(kb + k + 0) * HS_STRIDE], wr[k + 0], a0);
                            a1 = fmaf(hc[(kb + k + 1) * HS_STRIDE], wr[k + 1], a1);
                            a2 = fmaf(hc[(kb + k + 2) * HS_STRIDE], wr[k + 2], a2);
                            a3 = fmaf(hc[(kb + k + 3) * HS_STRIDE], wr[k + 3], a3);
                        }
                    }
                    smf[SM_PART + gkq * 128 + gg * 32 + gr] = (a0 + a1) + (a2 + a3);
                }
                __syncthreads();
                if (tid < 128) {
                    int g = tid >> 5, r = tid & 31;
                    float s = smf[SM_WSM + g * 257 + 256]
                            + smf[SM_PART + 0 * 128 + g * 32 + r]
                            + smf[SM_PART + 1 * 128 + g * 32 + r]
                            + smf[SM_PART + 2 * 128 + g * 32 + r]
                            + smf[SM_PART + 3 * 128 + g * 32 + r];
                    smf[SM_GS + g * 64 + Bb + r] = s;
                }
                __syncthreads();
                if (tid < Bb) {
                    int r = Bb + tid;
                    float cp = g_c[r * Hh + j];
                    float ig = sigm(smf[SM_GS + 0 * 64 + r]);
                    float fg = sigm(smf[SM_GS + 1 * 64 + r]);
                    float og = sigm(smf[SM_GS + 2 * 64 + r]);
                    float cn = fg * cp + ig * tanhf(smf[SM_GS + 3 * 64 + r]);
                    float hn = og * tanhf(cn);
                    g_c[r * Hh + j] = cn;
                    g_hbuf[nb][r * Hh + j] = hn;
                }
            }
        } else if (bid == 128) {
            if (tid < RR) g_sumexp[t * RR + tid] = 0.0f;
            else if (tid < RR + Bb) g_packmax[t * Bb + (tid - RR)] = 0ull;
        } else if (bid == 129 && t > 0) {
            if (tid < Bb) {
                unsigned long long key = g_packmax[(t - 1) * Bb + tid];
                int tok = (int)(0xFFFFFFFFu - (unsigned)(key & 0xFFFFFFFFull));
                out[tid * Ss + (t - 1)] = (float)tok;
                float emax = ord2f((unsigned)(key >> 32));
                out[Bb * Ss + tid * Ss + (t - 1)] =
                    emax / g_sumexp[(t - 1) * RR + Bb + tid];
            }
        }
        gbar(2 * t);

        // ================= GEMM phase (all blocks) =================
        const float* hsrc = g_hbuf[nb];

        // h_sT for next cell/teacher phase (cell blocks only use it)
        if (iscell) {
            for (int idx = tid; idx < RR * Hh; idx += NTHR) {
                int k = idx & 127, r = idx >> 7;
                smf[SM_HS + k * HS_STRIDE + r] = hsrc[r * Hh + k];
            }
        }
        // B staging: pair-packed uint2 (hp[p], hp[p+4]) per (q = k0*4+tig, n)
        for (int idx = tid; idx < 32 * 64; idx += NTHR) {
            int q = idx >> 6, n = idx & 63;
            int p_lo = (q >> 2) * 8 + (q & 3);     // k0*8 + tig
            int p_hi = p_lo + 4;
            float2 hv0 = *(const float2*)(hsrc + n * Hh + 2 * p_lo);
            float2 hv1 = *(const float2*)(hsrc + n * Hh + 2 * p_hi);
            unsigned hiw0, low0, hiw1, low1;
            split16(hv0.x, hv0.y, hiw0, low0);
            split16(hv1.x, hv1.y, hiw1, low1);
            BH2[q * HP2_STRIDE + n] = make_uint2(hiw0, hiw1);
            BL2[q * HP2_STRIDE + n] = make_uint2(low0, low1);
        }
        if (tid < Bb) tgt_s[tid] = x[tid * Ss + t];
        __syncthreads();

        // mma compute + merged E1: warps 0..13. teacher-cell(t+1): warps 14-15.
        if (wz < 14) {
            float acc[8][4];
#pragma unroll
            for (int nt = 0; nt < 8; ++nt) {
                acc[nt][0] = 0.f; acc[nt][1] = 0.f;
                acc[nt][2] = 0.f; acc[nt][3] = 0.f;
            }
#pragma unroll
            for (int k0 = 0; k0 < 8; ++k0) {
                int pA = k0 * 8 + tig;
                const unsigned* Wl = g_w16l + pA * Vv;
                unsigned al0 = Wl[vAc],          al1 = Wl[vA8c];
                unsigned al2 = Wl[4 * Vv + vAc], al3 = Wl[4 * Vv + vA8c];
                const uint2* BHq = BH2 + (k0 * 4 + tig) * HP2_STRIDE + gid;
                const uint2* BLq = BL2 + (k0 * 4 + tig) * HP2_STRIDE + gid;
#pragma unroll
                for (int nt = 0; nt < 8; ++nt) {
                    uint2 bh = BHq[nt * 8];
                    uint2 bl = BLq[nt * 8];
                    mma16816(acc[nt][0], acc[nt][1], acc[nt][2], acc[nt][3],
                             ahreg[k0][0], ahreg[k0][1], ahreg[k0][2], ahreg[k0][3],
                             bh.x, bh.y);
                    mma16816(acc[nt][0], acc[nt][1], acc[nt][2], acc[nt][3],
                             ahreg[k0][0], ahreg[k0][1], ahreg[k0][2], ahreg[k0][3],
                             bl.x, bl.y);
                    if (nt >= 4)
                        mma16816(acc[nt][0], acc[nt][1], acc[nt][2], acc[nt][3],
                                 al0, al1, al2, al3, bh.x, bh.y);
                }
            }
            // merged E1: bias add, loss check, exp, store e-values to D_s
            int vloc0 = wz * 16 + gid;
            bool a0ok = (vloc0 < span), a8ok = (vloc0 + 8 < span);
#pragma unroll
            for (int nt = 0; nt < 8; ++nt) {
                int row0 = nt * 8 + 2 * tig;
                float l0 = acc[nt][0] + bov0, l1 = acc[nt][1] + bov0;
                float l2 = acc[nt][2] + bov8, l3 = acc[nt][3] + bov8;
                if (nt < 4) {   // teacher rows: loss at target
                    if (a0ok && vA == tgt_s[row0])         atomicAdd(&g_loss, l0);
                    if (a0ok && vA == tgt_s[row0 + 1])     atomicAdd(&g_loss, l1);
                    if (a8ok && vA + 8 == tgt_s[row0])     atomicAdd(&g_loss, l2);
                    if (a8ok && vA + 8 == tgt_s[row0 + 1]) atomicAdd(&g_loss, l3);
                }
                int r0 = SM_DS + vloc0 * DS_STRIDE + row0;
                smf[r0]     = a0ok ? __expf(l0) : 0.0f;
                smf[r0 + 1] = a0ok ? __expf(l1) : 0.0f;
                smf[r0 + 8 * DS_STRIDE]     = a8ok ? __expf(l2) : 0.0f;
                smf[r0 + 8 * DS_STRIDE + 1] = a8ok ? __expf(l3) : 0.0f;
            }
        } else if (iscell && t < Ss - 1) {
            // teacher-cell(t+1) on warps 14-15: full 128-k dots from h_s(t)
            int q = tid - 448;             // 0..63
            int g = q & 3;
            int r0 = q >> 2;               // 0..15
            const float* wrow = smf + SM_WSM + g * 257 + 128;
#pragma unroll
            for (int half = 0; half < 2; ++half) {
                int r = r0 + half * 16;
                const float* hc = smf + SM_HS + r;
                float a0 = 0.f, a1 = 0.f, a2 = 0.f, a3 = 0.f;
#pragma unroll 8
                for (int k = 0; k < 128; k += 4) {
                    a0 = fmaf(hc[(k + 0) * HS_STRIDE], wrow[k + 0], a0);
                    a1 = fmaf(hc[(k + 1) * HS_STRIDE], wrow[k + 1], a1);
                    a2 = fmaf(hc[(k + 2) * HS_STRIDE], wrow[k + 2], a2);
                    a3 = fmaf(hc[(k + 3) * HS_STRIDE], wrow[k + 3], a3);
                }
                float base = g_xg[((t + 1) * Bb + r) * 4 * Hh + g * Hh + j];
                smf[SM_GS + g * 64 + r] = base + ((a0 + a1) + (a2 + a3));
            }
            asm volatile("bar.sync 1, 64;" ::: "memory");
            if (q < Bb) {
                int r = q;
                float cp = g_c[r * Hh + j];
                float ig = sigm(smf[SM_GS + 0 * 64 + r]);
                float fg = sigm(smf[SM_GS + 1 * 64 + r]);
                float og = sigm(smf[SM_GS + 2 * 64 + r]);
                float cn = fg * cp + ig * tanhf(smf[SM_GS + 3 * 64 + r]);
                float hn = og * tanhf(cn);
                g_c[r * Hh + j] = cn;
                g_hbuf[t & 1][r * Hh + j] = hn;    // buffer for step t+1
            }
        }
        __syncthreads();

        // ---------------- E2: segmented reductions from D_s --------------
        {
            const float* base = smf + SM_DS + e2r;
            float s = 0.0f;
            float emax = -1.0f; int cbest = 0;
            int c0 = e2s * 28;
#pragma unroll 7
            for (int i = 0; i < 28; ++i) {
                float e = base[(c0 + i) * DS_STRIDE];
                s += e;
                if (e2r >= Bb && e > emax) { emax = e; cbest = c0 + i; }
            }
            smf[SM_WSUM + e2s * 64 + e2r] = s;
            if (e2r >= Bb) {
                wkey[e2s * 32 + (e2r - Bb)] =
                    ((unsigned long long)f2ord(emax) << 32) |
                    (unsigned long long)(0xFFFFFFFFu - (unsigned)(v0 + cbest));
            }
        }
        __syncthreads();

        if (tid < RR) {
            float s = 0.0f;
#pragma unroll
            for (int w = 0; w < 8; ++w) s += smf[SM_WSUM + w * 64 + tid];
            atomicAdd(&g_sumexp[t * RR + tid], s);
        } else if (tid < RR + Bb) {
            int gr2 = tid - RR;
            unsigned long long m = 0ull;
#pragma unroll
            for (int w = 0; w < 8; ++w) {
                unsigned long long k = wkey[w * 32 + gr2];
                m = (k > m) ? k : m;
            }
            atomicMax(&g_packmax[t * Bb + gr2], m);
        }
        gbar(2 * t + 1);
    }

    // final flush: probs for t=31 (sumexp[31] final after last gbar)
    {
        float inv = __fdividef(1.0f, g_sumexp[(Ss - 1) * RR + cb]);
#pragma unroll 2
        for (int i = 0; i < 14; ++i) {
            int col = cch + 16 * i;
            if (col < span) {
                float e = smf[SM_DS + col * DS_STRIDE + cb];
                pred[(cb * Ss + (Ss - 1)) * Vv + v0 + col] = e * inv;
            }
        }
    }
}

// ---------------- epilogue: last gen outputs + loss -------------------------
__global__ void k_fin1(float* __restrict__ out) {
    __shared__ float red[1024];
    int tid = threadIdx.x;
    int t = tid >> 5, b = tid & 31;

    float se = g_sumexp[t * RR + b];
    red[tid] = logf(se);

    if (tid < Bb) {
        unsigned long long key = g_packmax[(Ss - 1) * Bb + tid];
        int tok = (int)(0xFFFFFFFFu - (unsigned)(key & 0xFFFFFFFFull));
        out[tid * Ss + (Ss - 1)] = (float)tok;
        float emax = ord2f((unsigned)(key >> 32));
        out[Bb * Ss + tid * Ss + (Ss - 1)] =
            emax / g_sumexp[(Ss - 1) * RR + Bb + tid];
    }
    __syncthreads();
    for (int s = 512; s > 0; s >>= 1) {
        if (tid < s) red[tid] += red[tid + s];
        __syncthreads();
    }
    if (tid == 0)
        out[PRED_OFF + PRED_N] = (red[0] - g_loss) / (float)(Ss * Bb);
}

// ---------------- launch ---------------------------------------------------
extern "C" void kernel_launch(void* const* d_in, const int* in_sizes, int n_in,
                              void* d_out, int out_size) {
    const int*   x   = (const int*)d_in[0];
    const float* emb = (const float*)d_in[1];
    const float* Wi  = (const float*)d_in[2];
    const float* Ui  = (const float*)d_in[3];
    const float* bi  = (const float*)d_in[4];
    const float* Wf  = (const float*)d_in[5];
    const float* Uf  = (const float*)d_in[6];
    const float* bf  = (const float*)d_in[7];
    const float* Wog = (const float*)d_in[8];
    const float* Uog = (const float*)d_in[9];
    const float* bog = (const float*)d_in[10];
    const float* Wc  = (const float*)d_in[11];
    const float* Uc  = (const float*)d_in[12];
    const float* bc  = (const float*)d_in[13];
    const float* Wo  = (const float*)d_in[14];
    const float* bo  = (const float*)d_in[15];
    float* out = (float*)d_out;

    cudaFuncSetAttribute(k_persist,
                         cudaFuncAttributeMaxDynamicSharedMemorySize,
                         SMEM_BYTES);

    k_split<<<64 * Vv / 512, 512>>>(Wo);
    k_prologue<<<Ss * Bb / 16, 512>>>(x, emb, Wi, bi, Wf, bf, Wog, bog, Wc, bc);
    k_persist<<<NBLK, NTHR, SMEM_BYTES>>>(x, emb,
                                          Wi, Ui, bi, Wf, Uf, bf,
                                          Wog, Uog, bog, Wc, Uc, bc,
                                          bo, out);
    k_fin1<<<1, 1024>>>(out);
}

// round 16
// speedup vs baseline: 2.6277x; 1.0612x over previous
#include <cuda_runtime.h>
#include <cuda_fp16.h>
#include <cstdint>

// Problem dims
#define Vv 32000
#define Ee 128
#define Hh 128
#define Bb 32
#define Ss 32
#define RR 64                  // 64 fused rows: 0..31 teacher, 32..63 generation
#define NBLK 148               // persistent grid (1 block/SM, all resident)
#define NTHR 512
#define HS_STRIDE 68           // h_s row stride
#define HP2_STRIDE 68          // packed-B uint2 row stride (conflict-free 8B loads)
#define DS_STRIDE 66           // D staging row stride

static const int PRED_OFF = 2048;           // gen_x[1024] + gen_o[1024]
static const int PRED_N   = Bb * Ss * Vv;   // 32,768,000

// ---------------- persistent device scratch (no allocations allowed) -------
__device__ float               g_hbuf[2][RR * Hh];      // double-buffered h
__device__ float               g_c[RR * Hh];
__device__ float               g_xg[Ss * Bb * 4 * Hh];  // teacher x-gates (with bias)
__device__ float               g_sumexp[Ss * RR];
__device__ unsigned long long  g_packmax[Ss * Bb];      // key = f2ord(e_max) || ~v
__device__ float               g_loss;                  // sum of logit at target
__device__ int                 g_bar[2 * Ss];           // grid barrier counters

// ---------------- shared-memory layout (float words) -----------------------
#define SM_HS    0                          // h_s[128][HS_STRIDE] (8704)
#define SM_DS    8704                       // D staging [256][DS_STRIDE] (16896)
#define SM_XE    25600                      // xe[32][129] gen embeddings (4128)
#define SM_BH2   29728                      // B-hi uint2[32][HP2_STRIDE] (4352 w)
#define SM_BL2   34080                      // B-lo uint2[32][HP2_STRIDE] (4352 w)
#define SM_WSM   38432                      // wsm[4][257] cell weights+bias (1028)
#define SM_PART  39460                      // cell k-split partials / fin red (512)
#define SM_GS    39972                      // gates (256)
#define SM_WSUM  40228                      // wsum[8][64] (512)
#define SM_WKEY  40740                      // wkey[8][32] ull (512 w, 8B-aligned)
#define SM_TGT   41252                      // tgt[32] ints
#define SM_TOK   41284                      // tok[32] ints
#define SM_FLOATS 41316
#define SMEM_BYTES (SM_FLOATS * 4)          // 165,264 B (< 227KB opt-in cap)

// ---------------- generic helpers ------------------------------------------
__device__ __forceinline__ float sigm(float x) { return 1.0f / (1.0f + __expf(-x)); }

__device__ __forceinline__ unsigned f2ord(float f) {
    unsigned u = __float_as_uint(f);
    return (u & 0x80000000u) ? ~u : (u | 0x80000000u);
}
__device__ __forceinline__ float ord2f(unsigned o) {
    return __uint_as_float((o & 0x80000000u) ? (o ^ 0x80000000u) : ~o);
}

// m16n8k16 f32.f16.f16.f32 (row.col), accumulate in place
__device__ __forceinline__ void mma16816(float& c0, float& c1, float& c2, float& c3,
                                         unsigned a0, unsigned a1, unsigned a2, unsigned a3,
                                         unsigned b0, unsigned b1) {
    asm volatile(
        "mma.sync.aligned.m16n8k16.row.col.f32.f16.f16.f32 "
        "{%0,%1,%2,%3}, {%4,%5,%6,%7}, {%8,%9}, {%0,%1,%2,%3};"
        : "+f"(c0), "+f"(c1), "+f"(c2), "+f"(c3)
        : "r"(a0), "r"(a1), "r"(a2), "r"(a3), "r"(b0), "r"(b1));
}

// grid-wide barrier: counter k, zeroed by prologue each launch
__device__ __forceinline__ void gbar(int k) {
    __syncthreads();
    if (threadIdx.x == 0) {
        __threadfence();
        atomicAdd(&g_bar[k], 1);
        while (*(volatile int*)&g_bar[k] < NBLK) { }
        __threadfence();
    }
    __syncthreads();
}

// v-span: 32000 = 32*217 + 116*216
__device__ __forceinline__ void vspan(int bid, int& v0, int& n) {
    if (bid < 32) { v0 = bid * 217; n = 217; }
    else          { v0 = 6944 + (bid - 32) * 216; n = 216; }
}

// pack float2 -> fp16 hi & lo residual words
__device__ __forceinline__ void split16(float x0, float x1, unsigned& hi, unsigned& lo) {
    __half h0 = __float2half_rn(x0), h1 = __float2half_rn(x1);
    __half l0 = __float2half_rn(x0 - __half2float(h0));
    __half l1 = __float2half_rn(x1 - __half2float(h1));
    hi = ((unsigned)__half_as_ushort(h1) << 16) | __half_as_ushort(h0);
    lo = ((unsigned)__half_as_ushort(l1) << 16) | __half_as_ushort(l0);
}

// ---------------- prologue: teacher x-gates + barrier reset ----------------
__global__ void __launch_bounds__(512)
k_prologue(const int* __restrict__ x, const float* __restrict__ emb,
           const float* __restrict__ Wi, const float* __restrict__ bi,
           const float* __restrict__ Wf, const float* __restrict__ bf,
           const float* __restrict__ Wog, const float* __restrict__ bog,
           const float* __restrict__ Wc, const float* __restrict__ bc) {
    int p0 = blockIdx.x * 16;
    int tid = threadIdx.x;
    int g = tid >> 7, j = tid & 127;

    __shared__ int   tok_s[16];
    __shared__ float xe[16][Ee];

    if (blockIdx.x == 0) {
        if (tid < 2 * Ss) g_bar[tid] = 0;
        if (tid == 0) g_loss = 0.0f;
    }
    if (tid < 16) {
        int p = p0 + tid;
        int t = p >> 5, b = p & 31;
        tok_s[tid] = (t == 0) ? 0 : x[b * Ss + (t - 1)];
    }
    __syncthreads();
    for (int idx = tid; idx < 16 * Ee; idx += 512) {
        int pp = idx >> 7, kk = idx & 127;
        xe[pp][kk] = emb[tok_s[pp] * Ee + kk];
    }
    __syncthreads();

    const float* W = (g == 0) ? Wi : (g == 1) ? Wf : (g == 2) ? Wog : Wc;
    float bias = ((g == 0) ? bi : (g == 1) ? bf : (g == 2) ? bog : bc)[j];

    float acc[16];
#pragma unroll
    for (int pp = 0; pp < 16; ++pp) acc[pp] = bias;

#pragma unroll 4
    for (int k = 0; k < Ee; ++k) {
        float w = W[k * Hh + j];
#pragma unroll
        for (int pp = 0; pp < 16; ++pp) acc[pp] += xe[pp][k] * w;
    }
#pragma unroll
    for (int pp = 0; pp < 16; ++pp)
        g_xg[(p0 + pp) * 4 * Hh + tid] = acc[pp];
}

// ---------------- persistent fused recurrence (mma.sync GEMM) --------------
__global__ void __launch_bounds__(NTHR, 1)
k_persist(const int* __restrict__ x, const float* __restrict__ emb,
          const float* __restrict__ Wi, const float* __restrict__ Ui, const float* __restrict__ bi,
          const float* __restrict__ Wf, const float* __restrict__ Uf, const float* __restrict__ bf,
          const float* __restrict__ Wog, const float* __restrict__ Uog, const float* __restrict__ bog,
          const float* __restrict__ Wc, const float* __restrict__ Uc, const float* __restrict__ bc,
          const float* __restrict__ Wo, const float* __restrict__ bo,
          float* __restrict__ out) {
    extern __shared__ float smf[];
    int tid = threadIdx.x, bid = blockIdx.x;
    int lane = tid & 31, wz = tid >> 5;
    bool iscell = (bid < 128);
    int j = bid;
    float* pred = out + PRED_OFF;
    int* tgt_s = (int*)(smf + SM_TGT);
    int* tok_s = (int*)(smf + SM_TOK);
    unsigned long long* wkey = (unsigned long long*)(smf + SM_WKEY);
    uint2* BH2 = (uint2*)(smf + SM_BH2);
    uint2* BL2 = (uint2*)(smf + SM_BL2);

    // one-time: cell blocks load their W/U column slice + bias into SMEM
    if (iscell) {
        for (int idx = tid; idx < 1024; idx += NTHR) {
            int g = idx >> 8, k = idx & 255;
            const float* W = (g == 0) ? Wi : (g == 1) ? Wf : (g == 2) ? Wog : Wc;
            const float* U = (g == 0) ? Ui : (g == 1) ? Uf : (g == 2) ? Uog : Uc;
            smf[SM_WSM + g * 257 + k] =
                (k < 128) ? W[k * Hh + j] : U[(k - 128) * Hh + j];
        }
        if (tid < 4) {
            const float* bv = (tid == 0) ? bi : (tid == 1) ? bf : (tid == 2) ? bog : bc;
            smf[SM_WSM + tid * 257 + 256] = bv[j];
        }
    }

    int v0, span;
    vspan(bid, v0, span);

    int gid = lane >> 2, tig = lane & 3;   // mma fragment coords

    // one-time: persistent A-hi AND A-lo fragment caches + bo (step-invariant),
    // split from fp32 Wo directly (no precompute kernel, no per-step A loads)
    int vA = v0 + wz * 16 + gid;           // true v for c0/c1; vA+8 for c2/c3
    int vAc  = (vA < Vv) ? vA : (Vv - 1);
    int vA8c = (vA + 8 < Vv) ? (vA + 8) : (Vv - 1);
    unsigned ahreg[8][4], alreg[8][4];
    float bov0 = 0.f, bov8 = 0.f;
    if (wz < 14) {
#pragma unroll
        for (int k0 = 0; k0 < 8; ++k0) {
            int p = k0 * 8 + tig;
            split16(Wo[(2 * p) * Vv + vAc],        Wo[(2 * p + 1) * Vv + vAc],
                    ahreg[k0][0], alreg[k0][0]);
            split16(Wo[(2 * p) * Vv + vA8c],       Wo[(2 * p + 1) * Vv + vA8c],
                    ahreg[k0][1], alreg[k0][1]);
            split16(Wo[(2 * (p + 4)) * Vv + vAc],  Wo[(2 * (p + 4) + 1) * Vv + vAc],
                    ahreg[k0][2], alreg[k0][2]);
            split16(Wo[(2 * (p + 4)) * Vv + vA8c], Wo[(2 * (p + 4) + 1) * Vv + vA8c],
                    ahreg[k0][3], alreg[k0][3]);
        }
        bov0 = bo[vAc];
        bov8 = bo[vA8c];
    }

    // t==0 full-cell role (old mapping): row cr, gate cg, k-half chf
    int cr = tid & 63;
    int cq = tid >> 6;
    int cg0 = cq & 3, chf = cq >> 2;

    // gen-cell role (t>=1): row gr (0..31 -> 32+gr), gate gg, k-quarter gkq
    int gr = tid & 31, gg = (tid >> 5) & 3, gkq = tid >> 7;

    // E0 (deferred prob write) role: b = tid>>4, chunk = tid&15
    int cb = tid >> 4, cch = tid & 15;

    // E2 role: r = tid>>3 (0..63), seg = tid&7 (28 cols each)
    int e2r = tid >> 3, e2s = tid & 7;

    for (int t = 0; t < Ss; ++t) {
        int nb = 1 - (t & 1);              // h_t buffer written for step t

        // ================= cell phase =================
        // E0: deferred prob write for step t-1 (all blocks; D_s + sumexp final)
        if (t > 0) {
            float inv = __fdividef(1.0f, g_sumexp[(t - 1) * RR + cb]);
#pragma unroll 2
            for (int i = 0; i < 14; ++i) {
                int col = cch + 16 * i;     // 0..223
                if (col < span) {
                    float e = smf[SM_DS + col * DS_STRIDE + cb];
                    pred[(cb * Ss + (t - 1)) * Vv + v0 + col] = e * inv;
                }
            }
        }

        if (iscell) {
            if (t == 0) {
                // full cell (teacher + gen), h0 = 0
                for (int idx = tid; idx < RR * Hh; idx += NTHR) {
                    int k = idx & 127, r = idx >> 7;
                    smf[SM_HS + k * HS_STRIDE + r] = 0.0f;
                }
                if (tid < Bb) tok_s[tid] = 0;
                __syncthreads();
                for (int idx = tid; idx < Bb * Ee; idx += NTHR) {
                    int r = idx >> 7, k = idx & 127;
                    smf[SM_XE + r * 129 + k] = emb[tok_s[r] * Ee + k];
                }
                __syncthreads();
                {
                    const float* wrow = smf + SM_WSM + cg0 * 257;
                    float a0 = 0.f, a1 = 0.f, a2 = 0.f, a3 = 0.f;
                    if (cr >= Bb && chf == 0) {
                        const float* xr = smf + SM_XE + (cr - Bb) * 129;
#pragma unroll 8
                        for (int k = 0; k < 128; k += 4) {
                            a0 = fmaf(xr[k + 0], wrow[k + 0], a0);
                            a1 = fmaf(xr[k + 1], wrow[k + 1], a1);
                            a2 = fmaf(xr[k + 2], wrow[k + 2], a2);
                            a3 = fmaf(xr[k + 3], wrow[k + 3], a3);
                        }
                    }
                    smf[SM_PART + chf * 256 + cg0 * 64 + cr] = (a0 + a1) + (a2 + a3);
                }
                __syncthreads();
                if (tid < 256) {
                    int g = tid >> 6, r = tid & 63;
                    float base = (r < Bb)
                        ? g_xg[(t * Bb + r) * 4 * Hh + g * Hh + j]
                        : smf[SM_WSM + g * 257 + 256];
                    smf[SM_GS + tid] = base + smf[SM_PART + tid] + smf[SM_PART + 256 + tid];
                }
                __syncthreads();
                if (tid < RR) {
                    int r = tid;
                    float ig = sigm(smf[SM_GS + 0 * 64 + r]);
                    float og = sigm(smf[SM_GS + 2 * 64 + r]);
                    float cn = ig * tanhf(smf[SM_GS + 3 * 64 + r]);   // f*c0 = 0
                    float hn = og * tanhf(cn);
                    g_c[r * Hh + j] = cn;
                    g_hbuf[nb][r * Hh + j] = hn;
                }
            } else {
                // gen-only cell: teacher h/c(t) already written during GEMM(t-1)
                if (tid < Bb) {
                    unsigned long long key = g_packmax[(t - 1) * Bb + tid];
                    tok_s[tid] = (int)(0xFFFFFFFFu - (unsigned)(key & 0xFFFFFFFFull));
                }
                __syncthreads();
                for (int idx = tid; idx < Bb * Ee; idx += NTHR) {
                    int r = idx >> 7, k = idx & 127;
                    smf[SM_XE + r * 129 + k] = emb[tok_s[r] * Ee + k];
                }
                __syncthreads();
                // 512-thread 4-quarter k-split over 256 combined k (W then U)
                {
                    const float* wrow = smf + SM_WSM + gg * 257;
                    float a0 = 0.f, a1 = 0.f, a2 = 0.f, a3 = 0.f;
                    if (gkq < 2) {
                        const float* xr = smf + SM_XE + gr * 129 + gkq * 64;
                        const float* wr = wrow + gkq * 64;
#pragma unroll 8
                        for (int k = 0; k < 64; k += 4) {
                            a0 = fmaf(xr[k + 0], wr[k + 0], a0);
                            a1 = fmaf(xr[k + 1], wr[k + 1], a1);
                            a2 = fmaf(xr[k + 2], wr[k + 2], a2);
                            a3 = fmaf(xr[k + 3], wr[k + 3], a3);
                        }
                    } else {
                        int kb = (gkq - 2) * 64;
                        const float* hc = smf + SM_HS + (Bb + gr);
                        const float* wr = wrow + 128 + kb;
#pragma unroll 8
                        for (int k = 0; k < 64; k += 4) {
                            a0 = fmaf(hc[(kb + k + 0) * HS_STRIDE], wr[k + 0], a0);
                            a1 = fmaf(hc[(kb + k + 1) * HS_STRIDE], wr[k + 1], a1);
                            a2 = fmaf(hc[(kb + k + 2) * HS_STRIDE], wr[k + 2], a2);
                            a3 = fmaf(hc[(kb + k + 3) * HS_STRIDE], wr[k + 3], a3);
                        }
                    }
                    smf[SM_PART + gkq * 128 + gg * 32 + gr] = (a0 + a1) + (a2 + a3);
                }
                __syncthreads();
                if (tid < 128) {
                    int g = tid >> 5, r = tid & 31;
                    float s = smf[SM_WSM + g * 257 + 256]
                            + smf[SM_PART + 0 * 128 + g * 32 + r]
                            + smf[SM_PART + 1 * 128 + g * 32 + r]
                            + smf[SM_PART + 2 * 128 + g * 32 + r]
                            + smf[SM_PART + 3 * 128 + g * 32 + r];
                    smf[SM_GS + g * 64 + Bb + r] = s;
                }
                __syncthreads();
                if (tid < Bb) {
                    int r = Bb + tid;
                    float cp = g_c[r * Hh + j];
                    float ig = sigm(smf[SM_GS + 0 * 64 + r]);
                    float fg = sigm(smf[SM_GS + 1 * 64 + r]);
                    float og = sigm(smf[SM_GS + 2 * 64 + r]);
                    float cn = fg * cp + ig * tanhf(smf[SM_GS + 3 * 64 + r]);
                    float hn = og * tanhf(cn);
                    g_c[r * Hh + j] = cn;
                    g_hbuf[nb][r * Hh + j] = hn;
                }
            }
        } else if (bid == 128) {
            if (tid < RR) g_sumexp[t * RR + tid] = 0.0f;
            else if (tid < RR + Bb) g_packmax[t * Bb + (tid - RR)] = 0ull;
        } else if (bid == 129 && t > 0) {
            if (tid < Bb) {
                unsigned long long key = g_packmax[(t - 1) * Bb + tid];
                int tok = (int)(0xFFFFFFFFu - (unsigned)(key & 0xFFFFFFFFull));
                out[tid * Ss + (t - 1)] = (float)tok;
                float emax = ord2f((unsigned)(key >> 32));
                out[Bb * Ss + tid * Ss + (t - 1)] =
                    emax / g_sumexp[(t - 1) * RR + Bb + tid];
            }
        }
        gbar(2 * t);

        // ================= GEMM phase (all blocks) =================
        const float* hsrc = g_hbuf[nb];

        // h_sT for next cell/teacher phase (cell blocks only use it)
        if (iscell) {
            for (int idx = tid; idx < RR * Hh; idx += NTHR) {
                int k = idx & 127, r = idx >> 7;
                smf[SM_HS + k * HS_STRIDE + r] = hsrc[r * Hh + k];
            }
        }
        // B staging: pair-packed uint2 (hp[p], hp[p+4]) per (q = k0*4+tig, n)
        for (int idx = tid; idx < 32 * 64; idx += NTHR) {
            int q = idx >> 6, n = idx & 63;
            int p_lo = (q >> 2) * 8 + (q & 3);     // k0*8 + tig
            int p_hi = p_lo + 4;
            float2 hv0 = *(const float2*)(hsrc + n * Hh + 2 * p_lo);
            float2 hv1 = *(const float2*)(hsrc + n * Hh + 2 * p_hi);
            unsigned hiw0, low0, hiw1, low1;
            split16(hv0.x, hv0.y, hiw0, low0);
            split16(hv1.x, hv1.y, hiw1, low1);
            BH2[q * HP2_STRIDE + n] = make_uint2(hiw0, hiw1);
            BL2[q * HP2_STRIDE + n] = make_uint2(low0, low1);
        }
        if (tid < Bb) tgt_s[tid] = x[tid * Ss + t];
        __syncthreads();

        // mma compute + merged E1: warps 0..13. teacher-cell(t+1): warps 14-15.
        if (wz < 14) {
            float acc[8][4];
#pragma unroll
            for (int nt = 0; nt < 8; ++nt) {
                acc[nt][0] = 0.f; acc[nt][1] = 0.f;
                acc[nt][2] = 0.f; acc[nt][3] = 0.f;
            }
#pragma unroll
            for (int k0 = 0; k0 < 8; ++k0) {
                const uint2* BHq = BH2 + (k0 * 4 + tig) * HP2_STRIDE + gid;
                const uint2* BLq = BL2 + (k0 * 4 + tig) * HP2_STRIDE + gid;
#pragma unroll
                for (int nt = 0; nt < 8; ++nt) {
                    uint2 bh = BHq[nt * 8];
                    uint2 bl = BLq[nt * 8];
                    mma16816(acc[nt][0], acc[nt][1], acc[nt][2], acc[nt][3],
                             ahreg[k0][0], ahreg[k0][1], ahreg[k0][2], ahreg[k0][3],
                             bh.x, bh.y);
                    mma16816(acc[nt][0], acc[nt][1], acc[nt][2], acc[nt][3],
                             ahreg[k0][0], ahreg[k0][1], ahreg[k0][2], ahreg[k0][3],
                             bl.x, bl.y);
                    if (nt >= 4)
                        mma16816(acc[nt][0], acc[nt][1], acc[nt][2], acc[nt][3],
                                 alreg[k0][0], alreg[k0][1], alreg[k0][2], alreg[k0][3],
                                 bh.x, bh.y);
                }
            }
            // merged E1: bias add, loss check, exp, store e-values to D_s
            int vloc0 = wz * 16 + gid;
            bool a0ok = (vloc0 < span), a8ok = (vloc0 + 8 < span);
#pragma unroll
            for (int nt = 0; nt < 8; ++nt) {
                int row0 = nt * 8 + 2 * tig;
                float l0 = acc[nt][0] + bov0, l1 = acc[nt][1] + bov0;
                float l2 = acc[nt][2] + bov8, l3 = acc[nt][3] + bov8;
                if (nt < 4) {   // teacher rows: loss at target
                    if (a0ok && vA == tgt_s[row0])         atomicAdd(&g_loss, l0);
                    if (a0ok && vA == tgt_s[row0 + 1])     atomicAdd(&g_loss, l1);
                    if (a8ok && vA + 8 == tgt_s[row0])     atomicAdd(&g_loss, l2);
                    if (a8ok && vA + 8 == tgt_s[row0 + 1]) atomicAdd(&g_loss, l3);
                }
                int r0 = SM_DS + vloc0 * DS_STRIDE + row0;
                smf[r0]     = a0ok ? __expf(l0) : 0.0f;
                smf[r0 + 1] = a0ok ? __expf(l1) : 0.0f;
                smf[r0 + 8 * DS_STRIDE]     = a8ok ? __expf(l2) : 0.0f;
                smf[r0 + 8 * DS_STRIDE + 1] = a8ok ? __expf(l3) : 0.0f;
            }
        } else if (iscell && t < Ss - 1) {
            // teacher-cell(t+1) on warps 14-15: full 128-k dots from h_s(t)
            int q = tid - 448;             // 0..63
            int g = q & 3;
            int r0 = q >> 2;               // 0..15
            const float* wrow = smf + SM_WSM + g * 257 + 128;
#pragma unroll
            for (int half = 0; half < 2; ++half) {
                int r = r0 + half * 16;
                const float* hc = smf + SM_HS + r;
                float a0 = 0.f, a1 = 0.f, a2 = 0.f, a3 = 0.f;
#pragma unroll 8
                for (int k = 0; k < 128; k += 4) {
                    a0 = fmaf(hc[(k + 0) * HS_STRIDE], wrow[k + 0], a0);
                    a1 = fmaf(hc[(k + 1) * HS_STRIDE], wrow[k + 1], a1);
                    a2 = fmaf(hc[(k + 2) * HS_STRIDE], wrow[k + 2], a2);
                    a3 = fmaf(hc[(k + 3) * HS_STRIDE], wrow[k + 3], a3);
                }
                float base = g_xg[((t + 1) * Bb + r) * 4 * Hh + g * Hh + j];
                smf[SM_GS + g * 64 + r] = base + ((a0 + a1) + (a2 + a3));
            }
            asm volatile("bar.sync 1, 64;" ::: "memory");
            if (q < Bb) {
                int r = q;
                float cp = g_c[r * Hh + j];
                float ig = sigm(smf[SM_GS + 0 * 64 + r]);
                float fg = sigm(smf[SM_GS + 1 * 64 + r]);
                float og = sigm(smf[SM_GS + 2 * 64 + r]);
                float cn = fg * cp + ig * tanhf(smf[SM_GS + 3 * 64 + r]);
                float hn = og * tanhf(cn);
                g_c[r * Hh + j] = cn;
                g_hbuf[t & 1][r * Hh + j] = hn;    // buffer for step t+1
            }
        }
        __syncthreads();

        // ---------------- E2: segmented reductions from D_s --------------
        {
            const float* base = smf + SM_DS + e2r;
            float s = 0.0f;
            float emax = -1.0f; int cbest = 0;
            int c0 = e2s * 28;
#pragma unroll 7
            for (int i = 0; i < 28; ++i) {
                float e = base[(c0 + i) * DS_STRIDE];
                s += e;
                if (e2r >= Bb && e > emax) { emax = e; cbest = c0 + i; }
            }
            smf[SM_WSUM + e2s * 64 + e2r] = s;
            if (e2r >= Bb) {
                wkey[e2s * 32 + (e2r - Bb)] =
                    ((unsigned long long)f2ord(emax) << 32) |
                    (unsigned long long)(0xFFFFFFFFu - (unsigned)(v0 + cbest));
            }
        }
        __syncthreads();

        if (tid < RR) {
            float s = 0.0f;
#pragma unroll
            for (int w = 0; w < 8; ++w) s += smf[SM_WSUM + w * 64 + tid];
            atomicAdd(&g_sumexp[t * RR + tid], s);
        } else if (tid < RR + Bb) {
            int gr2 = tid - RR;
            unsigned long long m = 0ull;
#pragma unroll
            for (int w = 0; w < 8; ++w) {
                unsigned long long k = wkey[w * 32 + gr2];
                m = (k > m) ? k : m;
            }
            atomicMax(&g_packmax[t * Bb + gr2], m);
        }
        gbar(2 * t + 1);
    }

    // final flush: probs for t=31 (sumexp[31] final after last gbar)
    {
        float inv = __fdividef(1.0f, g_sumexp[(Ss - 1) * RR + cb]);
#pragma unroll 2
        for (int i = 0; i < 14; ++i) {
            int col = cch + 16 * i;
            if (col < span) {
                float e = smf[SM_DS + col * DS_STRIDE + cb];
                pred[(cb * Ss + (Ss - 1)) * Vv + v0 + col] = e * inv;
            }
        }
    }

    // folded fin: block 128 computes last gen outputs + pretrain loss
    if (bid == 128) {
        __syncthreads();
        float ls = 0.0f;
#pragma unroll
        for (int q = 0; q < 2; ++q) {
            int idx = tid + q * 512;          // 0..1023 = t*32 + b (teacher rows)
            int tt = idx >> 5, b = idx & 31;
            ls += logf(g_sumexp[tt * RR + b]);
        }
        smf[SM_PART + tid] = ls;
        __syncthreads();
        for (int s = 256; s > 0; s >>= 1) {
            if (tid < s) smf[SM_PART + tid] += smf[SM_PART + tid + s];
            __syncthreads();
        }
        if (tid < Bb) {
            unsigned long long key = g_packmax[(Ss - 1) * Bb + tid];
            int tok = (int)(0xFFFFFFFFu - (unsigned)(key & 0xFFFFFFFFull));
            out[tid * Ss + (Ss - 1)] = (float)tok;
            float emax = ord2f((unsigned)(key >> 32));
            out[Bb * Ss + tid * Ss + (Ss - 1)] =
                emax / g_sumexp[(Ss - 1) * RR + Bb + tid];
        }
        if (tid == 0)
            out[PRED_OFF + PRED_N] = (smf[SM_PART] - g_loss) / (float)(Ss * Bb);
    }
}

// ---------------- launch ---------------------------------------------------
extern "C" void kernel_launch(void* const* d_in, const int* in_sizes, int n_in,
                              void* d_out, int out_size) {
    const int*   x   = (const int*)d_in[0];
    const float* emb = (const float*)d_in[1];
    const float* Wi  = (const float*)d_in[2];
    const float* Ui  = (const float*)d_in[3];
    const float* bi  = (const float*)d_in[4];
    const float* Wf  = (const float*)d_in[5];
    const float* Uf  = (const float*)d_in[6];
    const float* bf  = (const float*)d_in[7];
    const float* Wog = (const float*)d_in[8];
    const float* Uog = (const float*)d_in[9];
    const float* bog = (const float*)d_in[10];
    const float* Wc  = (const float*)d_in[11];
    const float* Uc  = (const float*)d_in[12];
    const float* bc  = (const float*)d_in[13];
    const float* Wo  = (const float*)d_in[14];
    const float* bo  = (const float*)d_in[15];
    float* out = (float*)d_out;

    cudaFuncSetAttribute(k_persist,
                         cudaFuncAttributeMaxDynamicSharedMemorySize,
                         SMEM_BYTES);

    k_prologue<<<Ss * Bb / 16, 512>>>(x, emb, Wi, bi, Wf, bf, Wog, bog, Wc, bc);
    k_persist<<<NBLK, NTHR, SMEM_BYTES>>>(x, emb,
                                          Wi, Ui, bi, Wf, Uf, bf,
                                          Wog, Uog, bog, Wc, Uc, bc,
                                          Wo, bo, out);
}

// round 17
// speedup vs baseline: 2.7914x; 1.0623x over previous
#include <cuda_runtime.h>
#include <cuda_fp16.h>
#include <cstdint>

// Problem dims
#define Vv 32000
#define Ee 128
#define Hh 128
#define Bb 32
#define Ss 32
#define RR 64                  // 64 fused rows: 0..31 teacher, 32..63 generation
#define NBLK 148               // persistent grid (1 block/SM, all resident)
#define NTHR 512
#define HS_STRIDE 68           // h_s row stride
#define HP2_STRIDE 68          // packed-B uint2 row stride (conflict-free 8B loads)
#define DS_STRIDE 66           // D staging row stride

static const int PRED_OFF = 2048;           // gen_x[1024] + gen_o[1024]
static const int PRED_N   = Bb * Ss * Vv;   // 32,768,000

// ---------------- persistent device scratch (no allocations allowed) -------
__device__ float               g_hbuf[2][RR * Hh];      // double-buffered h
__device__ float               g_c[RR * Hh];
__device__ float               g_xg[Ss * Bb * 4 * Hh];  // teacher x-gates (with bias)
__device__ float               g_sumexp[Ss * RR];
__device__ unsigned long long  g_packmax[Ss * Bb];      // key = f2ord(e_max) || ~v
__device__ float               g_loss;                  // sum of logit at target
__device__ int                 g_bar[2 * Ss];           // grid barrier counters

// ---------------- shared-memory layout (float words) -----------------------
#define SM_HS    0                          // h_s[128][HS_STRIDE] (8704)
#define SM_DS    8704                       // D staging [256][DS_STRIDE] (16896)
#define SM_XE    25600                      // xe[32][129] gen embeddings (4128)
#define SM_BH2   29728                      // B-hi uint2[32][HP2_STRIDE] (4352 w)
#define SM_BL2   34080                      // B-lo uint2[32][HP2_STRIDE] (4352 w)
#define SM_WSM   38432                      // wsm[4][257] cell weights+bias (1028)
#define SM_PART  39460                      // cell k-split partials / fin red (512)
#define SM_GS    39972                      // gates (256)
#define SM_WSUM  40228                      // wsum[8][64] (512)
#define SM_WKEY  40740                      // wkey[8][32] ull (512 w, 8B-aligned)
#define SM_TGT   41252                      // tgt[32] ints
#define SM_TOK   41284                      // tok[32] ints
#define SM_FLOATS 41316
#define SMEM_BYTES (SM_FLOATS * 4)          // 165,264 B (< 227KB opt-in cap)

// ---------------- generic helpers ------------------------------------------
__device__ __forceinline__ float sigm(float x) { return 1.0f / (1.0f + __expf(-x)); }

__device__ __forceinline__ unsigned f2ord(float f) {
    unsigned u = __float_as_uint(f);
    return (u & 0x80000000u) ? ~u : (u | 0x80000000u);
}
__device__ __forceinline__ float ord2f(unsigned o) {
    return __uint_as_float((o & 0x80000000u) ? (o ^ 0x80000000u) : ~o);
}

// m16n8k16 f32.f16.f16.f32 (row.col), accumulate in place
__device__ __forceinline__ void mma16816(float& c0, float& c1, float& c2, float& c3,
                                         unsigned a0, unsigned a1, unsigned a2, unsigned a3,
                                         unsigned b0, unsigned b1) {
    asm volatile(
        "mma.sync.aligned.m16n8k16.row.col.f32.f16.f16.f32 "
        "{%0,%1,%2,%3}, {%4,%5,%6,%7}, {%8,%9}, {%0,%1,%2,%3};"
        : "+f"(c0), "+f"(c1), "+f"(c2), "+f"(c3)
        : "r"(a0), "r"(a1), "r"(a2), "r"(a3), "r"(b0), "r"(b1));
}

// grid-wide barrier: counter k, zeroed by prologue each launch
__device__ __forceinline__ void gbar(int k) {
    __syncthreads();
    if (threadIdx.x == 0) {
        __threadfence();
        atomicAdd(&g_bar[k], 1);
        while (*(volatile int*)&g_bar[k] < NBLK) { }
        __threadfence();
    }
    __syncthreads();
}

// v-span: 32000 = 32*217 + 116*216
__device__ __forceinline__ void vspan(int bid, int& v0, int& n) {
    if (bid < 32) { v0 = bid * 217; n = 217; }
    else          { v0 = 6944 + (bid - 32) * 216; n = 216; }
}

// pack float2 -> fp16 hi & lo residual words
__device__ __forceinline__ void split16(float x0, float x1, unsigned& hi, unsigned& lo) {
    __half h0 = __float2half_rn(x0), h1 = __float2half_rn(x1);
    __half l0 = __float2half_rn(x0 - __half2float(h0));
    __half l1 = __float2half_rn(x1 - __half2float(h1));
    hi = ((unsigned)__half_as_ushort(h1) << 16) | __half_as_ushort(h0);
    lo = ((unsigned)__half_as_ushort(l1) << 16) | __half_as_ushort(l0);
}

// ---------------- prologue: teacher x-gates + barrier reset ----------------
__global__ void __launch_bounds__(512)
k_prologue(const int* __restrict__ x, const float* __restrict__ emb,
           const float* __restrict__ Wi, const float* __restrict__ bi,
           const float* __restrict__ Wf, const float* __restrict__ bf,
           const float* __restrict__ Wog, const float* __restrict__ bog,
           const float* __restrict__ Wc, const float* __restrict__ bc) {
    int p0 = blockIdx.x * 16;
    int tid = threadIdx.x;
    int g = tid >> 7, j = tid & 127;

    __shared__ int   tok_s[16];
    __shared__ float xe[16][Ee];

    if (blockIdx.x == 0) {
        if (tid < 2 * Ss) g_bar[tid] = 0;
        if (tid == 0) g_loss = 0.0f;
    }
    if (tid < 16) {
        int p = p0 + tid;
        int t = p >> 5, b = p & 31;
        tok_s[tid] = (t == 0) ? 0 : x[b * Ss + (t - 1)];
    }
    __syncthreads();
    for (int idx = tid; idx < 16 * Ee; idx += 512) {
        int pp = idx >> 7, kk = idx & 127;
        xe[pp][kk] = emb[tok_s[pp] * Ee + kk];
    }
    __syncthreads();

    const float* W = (g == 0) ? Wi : (g == 1) ? Wf : (g == 2) ? Wog : Wc;
    float bias = ((g == 0) ? bi : (g == 1) ? bf : (g == 2) ? bog : bc)[j];

    float acc[16];
#pragma unroll
    for (int pp = 0; pp < 16; ++pp) acc[pp] = bias;

#pragma unroll 4
    for (int k = 0; k < Ee; ++k) {
        float w = W[k * Hh + j];
#pragma unroll
        for (int pp = 0; pp < 16; ++pp) acc[pp] += xe[pp][k] * w;
    }
#pragma unroll
    for (int pp = 0; pp < 16; ++pp)
        g_xg[(p0 + pp) * 4 * Hh + tid] = acc[pp];
}

// ---------------- persistent fused recurrence (mma.sync GEMM) --------------
__global__ void __launch_bounds__(NTHR, 1)
k_persist(const int* __restrict__ x, const float* __restrict__ emb,
          const float* __restrict__ Wi, const float* __restrict__ Ui, const float* __restrict__ bi,
          const float* __restrict__ Wf, const float* __restrict__ Uf, const float* __restrict__ bf,
          const float* __restrict__ Wog, const float* __restrict__ Uog, const float* __restrict__ bog,
          const float* __restrict__ Wc, const float* __restrict__ Uc, const float* __restrict__ bc,
          const float* __restrict__ Wo, const float* __restrict__ bo,
          float* __restrict__ out) {
    extern __shared__ float smf[];
    int tid = threadIdx.x, bid = blockIdx.x;
    int lane = tid & 31, wz = tid >> 5;
    bool iscell = (bid < 128);
    int j = bid;
    float* pred = out + PRED_OFF;
    int* tgt_s = (int*)(smf + SM_TGT);
    int* tok_s = (int*)(smf + SM_TOK);
    unsigned long long* wkey = (unsigned long long*)(smf + SM_WKEY);
    uint2* BH2 = (uint2*)(smf + SM_BH2);
    uint2* BL2 = (uint2*)(smf + SM_BL2);

    // one-time: cell blocks load their W/U column slice + bias into SMEM
    if (iscell) {
        for (int idx = tid; idx < 1024; idx += NTHR) {
            int g = idx >> 8, k = idx & 255;
            const float* W = (g == 0) ? Wi : (g == 1) ? Wf : (g == 2) ? Wog : Wc;
            const float* U = (g == 0) ? Ui : (g == 1) ? Uf : (g == 2) ? Uog : Uc;
            smf[SM_WSM + g * 257 + k] =
                (k < 128) ? W[k * Hh + j] : U[(k - 128) * Hh + j];
        }
        if (tid < 4) {
            const float* bv = (tid == 0) ? bi : (tid == 1) ? bf : (tid == 2) ? bog : bc;
            smf[SM_WSM + tid * 257 + 256] = bv[j];
        }
    }

    int v0, span;
    vspan(bid, v0, span);

    int gid = lane >> 2, tig = lane & 3;   // mma fragment coords

    // one-time: persistent A-hi AND A-lo fragment caches + bo (step-invariant),
    // split from fp32 Wo directly (no precompute kernel, no per-step A loads)
    int vA = v0 + wz * 16 + gid;           // true v for c0/c1; vA+8 for c2/c3
    int vAc  = (vA < Vv) ? vA : (Vv - 1);
    int vA8c = (vA + 8 < Vv) ? (vA + 8) : (Vv - 1);
    unsigned ahreg[8][4], alreg[8][4];
    float bov0 = 0.f, bov8 = 0.f;
    if (wz < 14) {
#pragma unroll
        for (int k0 = 0; k0 < 8; ++k0) {
            int p = k0 * 8 + tig;
            split16(Wo[(2 * p) * Vv + vAc],        Wo[(2 * p + 1) * Vv + vAc],
                    ahreg[k0][0], alreg[k0][0]);
            split16(Wo[(2 * p) * Vv + vA8c],       Wo[(2 * p + 1) * Vv + vA8c],
                    ahreg[k0][1], alreg[k0][1]);
            split16(Wo[(2 * (p + 4)) * Vv + vAc],  Wo[(2 * (p + 4) + 1) * Vv + vAc],
                    ahreg[k0][2], alreg[k0][2]);
            split16(Wo[(2 * (p + 4)) * Vv + vA8c], Wo[(2 * (p + 4) + 1) * Vv + vA8c],
                    ahreg[k0][3], alreg[k0][3]);
        }
        bov0 = bo[vAc];
        bov8 = bo[vA8c];
    }

    // t==0 full-cell role (old mapping): row cr, gate cg, k-half chf
    int cr = tid & 63;
    int cq = tid >> 6;
    int cg0 = cq & 3, chf = cq >> 2;

    // gen-cell role (t>=1): row gr (0..31 -> 32+gr), gate gg, k-quarter gkq
    int gr = tid & 31, gg = (tid >> 5) & 3, gkq = tid >> 7;

    // E0 (deferred prob write) role: b = tid>>4, chunk = tid&15
    int cb = tid >> 4, cch = tid & 15;

    // E2 role (conflict-free): row = tid&63, segment = tid>>6, col = seg + 8*i
    int e2r = tid & 63, e2s = tid >> 6;

    for (int t = 0; t < Ss; ++t) {
        int nb = 1 - (t & 1);              // h_t buffer written for step t

        // ================= cell phase =================
        // E0: deferred prob write for step t-1 (all blocks; D_s + sumexp final)
        if (t > 0) {
            float inv = __fdividef(1.0f, g_sumexp[(t - 1) * RR + cb]);
#pragma unroll 2
            for (int i = 0; i < 14; ++i) {
                int col = cch + 16 * i;     // 0..223
                if (col < span) {
                    float e = smf[SM_DS + col * DS_STRIDE + cb];
                    pred[(cb * Ss + (t - 1)) * Vv + v0 + col] = e * inv;
                }
            }
        }

        if (iscell) {
            if (t == 0) {
                // full cell (teacher + gen), h0 = 0
                for (int idx = tid; idx < RR * Hh; idx += NTHR) {
                    int k = idx & 127, r = idx >> 7;
                    smf[SM_HS + k * HS_STRIDE + r] = 0.0f;
                }
                if (tid < Bb) tok_s[tid] = 0;
                __syncthreads();
                for (int idx = tid; idx < Bb * Ee; idx += NTHR) {
                    int r = idx >> 7, k = idx & 127;
                    smf[SM_XE + r * 129 + k] = emb[tok_s[r] * Ee + k];
                }
                __syncthreads();
                {
                    const float* wrow = smf + SM_WSM + cg0 * 257;
                    float a0 = 0.f, a1 = 0.f, a2 = 0.f, a3 = 0.f;
                    if (cr >= Bb && chf == 0) {
                        const float* xr = smf + SM_XE + (cr - Bb) * 129;
#pragma unroll 8
                        for (int k = 0; k < 128; k += 4) {
                            a0 = fmaf(xr[k + 0], wrow[k + 0], a0);
                            a1 = fmaf(xr[k + 1], wrow[k + 1], a1);
                            a2 = fmaf(xr[k + 2], wrow[k + 2], a2);
                            a3 = fmaf(xr[k + 3], wrow[k + 3], a3);
                        }
                    }
                    smf[SM_PART + chf * 256 + cg0 * 64 + cr] = (a0 + a1) + (a2 + a3);
                }
                __syncthreads();
                if (tid < 256) {
                    int g = tid >> 6, r = tid & 63;
                    float base = (r < Bb)
                        ? g_xg[(t * Bb + r) * 4 * Hh + g * Hh + j]
                        : smf[SM_WSM + g * 257 + 256];
                    smf[SM_GS + tid] = base + smf[SM_PART + tid] + smf[SM_PART + 256 + tid];
                }
                __syncthreads();
                if (tid < RR) {
                    int r = tid;
                    float ig = sigm(smf[SM_GS + 0 * 64 + r]);
                    float og = sigm(smf[SM_GS + 2 * 64 + r]);
                    float cn = ig * tanhf(smf[SM_GS + 3 * 64 + r]);   // f*c0 = 0
                    float hn = og * tanhf(cn);
                    g_c[r * Hh + j] = cn;
                    g_hbuf[nb][r * Hh + j] = hn;
                }
            } else {
                // gen-only cell: teacher h/c(t) already written during GEMM(t-1)
                if (tid < Bb) {
                    unsigned long long key = g_packmax[(t - 1) * Bb + tid];
                    tok_s[tid] = (int)(0xFFFFFFFFu - (unsigned)(key & 0xFFFFFFFFull));
                }
                __syncthreads();
                for (int idx = tid; idx < Bb * Ee; idx += NTHR) {
                    int r = idx >> 7, k = idx & 127;
                    smf[SM_XE + r * 129 + k] = emb[tok_s[r] * Ee + k];
                }
                __syncthreads();
                // 512-thread 4-quarter k-split over 256 combined k (W then U)
                {
                    const float* wrow = smf + SM_WSM + gg * 257;
                    float a0 = 0.f, a1 = 0.f, a2 = 0.f, a3 = 0.f;
                    if (gkq < 2) {
                        const float* xr = smf + SM_XE + gr * 129 + gkq * 64;
                        const float* wr = wrow + gkq * 64;
#pragma unroll 8
                        for (int k = 0; k < 64; k += 4) {
                            a0 = fmaf(xr[k + 0], wr[k + 0], a0);
                            a1 = fmaf(xr[k + 1], wr[k + 1], a1);
                            a2 = fmaf(xr[k + 2], wr[k + 2], a2);
                            a3 = fmaf(xr[k + 3], wr[k + 3], a3);
                        }
                    } else {
                        int kb = (gkq - 2) * 64;
                        const float* hc = smf + SM_HS + (Bb + gr);
                        const float* wr = wrow + 128 + kb;
#pragma unroll 8
                        for (int k = 0; k < 64; k += 4) {
                            a0 = fmaf(hc[(kb + k + 0) * HS_STRIDE], wr[k + 0], a0);
                            a1 = fmaf(hc[(kb + k + 1) * HS_STRIDE], wr[k + 1], a1);
                            a2 = fmaf(hc[(kb + k + 2) * HS_STRIDE], wr[k + 2], a2);
                            a3 = fmaf(hc[(kb + k + 3) * HS_STRIDE], wr[k + 3], a3);
                        }
                    }
                    smf[SM_PART + gkq * 128 + gg * 32 + gr] = (a0 + a1) + (a2 + a3);
                }
                __syncthreads();
                if (tid < 128) {
                    int g = tid >> 5, r = tid & 31;
                    float s = smf[SM_WSM + g * 257 + 256]
                            + smf[SM_PART + 0 * 128 + g * 32 + r]
                            + smf[SM_PART + 1 * 128 + g * 32 + r]
                            + smf[SM_PART + 2 * 128 + g * 32 + r]
                            + smf[SM_PART + 3 * 128 + g * 32 + r];
                    smf[SM_GS + g * 64 + Bb + r] = s;
                }
                __syncthreads();
                if (tid < Bb) {
                    int r = Bb + tid;
                    float cp = g_c[r * Hh + j];
                    float ig = sigm(smf[SM_GS + 0 * 64 + r]);
                    float fg = sigm(smf[SM_GS + 1 * 64 + r]);
                    float og = sigm(smf[SM_GS + 2 * 64 + r]);
                    float cn = fg * cp + ig * tanhf(smf[SM_GS + 3 * 64 + r]);
                    float hn = og * tanhf(cn);
                    g_c[r * Hh + j] = cn;
                    g_hbuf[nb][r * Hh + j] = hn;
                }
            }
        } else if (bid == 128) {
            if (tid < RR) g_sumexp[t * RR + tid] = 0.0f;
            else if (tid < RR + Bb) g_packmax[t * Bb + (tid - RR)] = 0ull;
        } else if (bid == 129 && t > 0) {
            if (tid < Bb) {
                unsigned long long key = g_packmax[(t - 1) * Bb + tid];
                int tok = (int)(0xFFFFFFFFu - (unsigned)(key & 0xFFFFFFFFull));
                out[tid * Ss + (t - 1)] = (float)tok;
                float emax = ord2f((unsigned)(key >> 32));
                out[Bb * Ss + tid * Ss + (t - 1)] =
                    emax / g_sumexp[(t - 1) * RR + Bb + tid];
            }
        }
        gbar(2 * t);

        // ================= GEMM phase (all blocks) =================
        const float* hsrc = g_hbuf[nb];

        // fused staging: single read of h produces packed-B (all blocks)
        // and transposed h_s (cell blocks only, for next cell/teacher phase)
        for (int idx = tid; idx < 32 * 64; idx += NTHR) {
            int q = idx >> 6, n = idx & 63;
            int p_lo = (q >> 2) * 8 + (q & 3);     // k0*8 + tig
            int p_hi = p_lo + 4;
            float2 hv0 = *(const float2*)(hsrc + n * Hh + 2 * p_lo);
            float2 hv1 = *(const float2*)(hsrc + n * Hh + 2 * p_hi);
            unsigned hiw0, low0, hiw1, low1;
            split16(hv0.x, hv0.y, hiw0, low0);
            split16(hv1.x, hv1.y, hiw1, low1);
            BH2[q * HP2_STRIDE + n] = make_uint2(hiw0, hiw1);
            BL2[q * HP2_STRIDE + n] = make_uint2(low0, low1);
            if (iscell) {
                smf[SM_HS + (2 * p_lo) * HS_STRIDE + n]     = hv0.x;
                smf[SM_HS + (2 * p_lo + 1) * HS_STRIDE + n] = hv0.y;
                smf[SM_HS + (2 * p_hi) * HS_STRIDE + n]     = hv1.x;
                smf[SM_HS + (2 * p_hi + 1) * HS_STRIDE + n] = hv1.y;
            }
        }
        if (tid < Bb) tgt_s[tid] = x[tid * Ss + t];
        __syncthreads();

        // mma compute + merged E1: warps 0..13. teacher-cell(t+1): warps 14-15.
        if (wz < 14) {
            float acc[8][4];
#pragma unroll
            for (int nt = 0; nt < 8; ++nt) {
                acc[nt][0] = 0.f; acc[nt][1] = 0.f;
                acc[nt][2] = 0.f; acc[nt][3] = 0.f;
            }
#pragma unroll
            for (int k0 = 0; k0 < 8; ++k0) {
                const uint2* BHq = BH2 + (k0 * 4 + tig) * HP2_STRIDE + gid;
                const uint2* BLq = BL2 + (k0 * 4 + tig) * HP2_STRIDE + gid;
#pragma unroll
                for (int nt = 0; nt < 8; ++nt) {
                    uint2 bh = BHq[nt * 8];
                    uint2 bl = BLq[nt * 8];
                    mma16816(acc[nt][0], acc[nt][1], acc[nt][2], acc[nt][3],
                             ahreg[k0][0], ahreg[k0][1], ahreg[k0][2], ahreg[k0][3],
                             bh.x, bh.y);
                    mma16816(acc[nt][0], acc[nt][1], acc[nt][2], acc[nt][3],
                             ahreg[k0][0], ahreg[k0][1], ahreg[k0][2], ahreg[k0][3],
                             bl.x, bl.y);
                    if (nt >= 4)
                        mma16816(acc[nt][0], acc[nt][1], acc[nt][2], acc[nt][3],
                                 alreg[k0][0], alreg[k0][1], alreg[k0][2], alreg[k0][3],
                                 bh.x, bh.y);
                }
            }
            // merged E1: bias add, loss check, exp, store e-values to D_s
            int vloc0 = wz * 16 + gid;
            bool a0ok = (vloc0 < span), a8ok = (vloc0 + 8 < span);
#pragma unroll
            for (int nt = 0; nt < 8; ++nt) {
                int row0 = nt * 8 + 2 * tig;
                float l0 = acc[nt][0] + bov0, l1 = acc[nt][1] + bov0;
                float l2 = acc[nt][2] + bov8, l3 = acc[nt][3] + bov8;
                if (nt < 4) {   // teacher rows: loss at target
                    if (a0ok && vA == tgt_s[row0])         atomicAdd(&g_loss, l0);
                    if (a0ok && vA == tgt_s[row0 + 1])     atomicAdd(&g_loss, l1);
                    if (a8ok && vA + 8 == tgt_s[row0])     atomicAdd(&g_loss, l2);
                    if (a8ok && vA + 8 == tgt_s[row0 + 1]) atomicAdd(&g_loss, l3);
                }
                int r0 = SM_DS + vloc0 * DS_STRIDE + row0;
                smf[r0]     = a0ok ? __expf(l0) : 0.0f;
                smf[r0 + 1] = a0ok ? __expf(l1) : 0.0f;
                smf[r0 + 8 * DS_STRIDE]     = a8ok ? __expf(l2) : 0.0f;
                smf[r0 + 8 * DS_STRIDE + 1] = a8ok ? __expf(l3) : 0.0f;
            }
        } else if (iscell && t < Ss - 1) {
            // teacher-cell(t+1) on warps 14-15: full 128-k dots from h_s(t)
            int q = tid - 448;             // 0..63
            int g = q & 3;
            int r0 = q >> 2;               // 0..15
            const float* wrow = smf + SM_WSM + g * 257 + 128;
#pragma unroll
            for (int half = 0; half < 2; ++half) {
                int r = r0 + half * 16;
                const float* hc = smf + SM_HS + r;
                float a0 = 0.f, a1 = 0.f, a2 = 0.f, a3 = 0.f;
#pragma unroll 8
                for (int k = 0; k < 128; k += 4) {
                    a0 = fmaf(hc[(k + 0) * HS_STRIDE], wrow[k + 0], a0);
                    a1 = fmaf(hc[(k + 1) * HS_STRIDE], wrow[k + 1], a1);
                    a2 = fmaf(hc[(k + 2) * HS_STRIDE], wrow[k + 2], a2);
                    a3 = fmaf(hc[(k + 3) * HS_STRIDE], wrow[k + 3], a3);
                }
                float base = g_xg[((t + 1) * Bb + r) * 4 * Hh + g * Hh + j];
                smf[SM_GS + g * 64 + r] = base + ((a0 + a1) + (a2 + a3));
            }
            asm volatile("bar.sync 1, 64;" ::: "memory");
            if (q < Bb) {
                int r = q;
                float cp = g_c[r * Hh + j];
                float ig = sigm(smf[SM_GS + 0 * 64 + r]);
                float fg = sigm(smf[SM_GS + 1 * 64 + r]);
                float og = sigm(smf[SM_GS + 2 * 64 + r]);
                float cn = fg * cp + ig * tanhf(smf[SM_GS + 3 * 64 + r]);
                float hn = og * tanhf(cn);
                g_c[r * Hh + j] = cn;
                g_hbuf[t & 1][r * Hh + j] = hn;    // buffer for step t+1
            }
        }
        __syncthreads();

        // ---------------- E2: segmented reductions from D_s --------------
        // row = tid&63, segment = tid>>6, cols = seg + 8*i (conflict-free)
        {
            const float* base = smf + SM_DS + e2r;
            float s = 0.0f;
            float emax = -1.0f; int cbest = 0;
#pragma unroll 7
            for (int i = 0; i < 28; ++i) {
                int col = e2s + 8 * i;
                float e = base[col * DS_STRIDE];
                s += e;
                if (e2r >= Bb && e > emax) { emax = e; cbest = col; }
            }
            smf[SM_WSUM + e2s * 64 + e2r] = s;
            if (e2r >= Bb) {
                wkey[e2s * 32 + (e2r - Bb)] =
                    ((unsigned long long)f2ord(emax) << 32) |
                    (unsigned long long)(0xFFFFFFFFu - (unsigned)(v0 + cbest));
            }
        }
        __syncthreads();

        if (tid < RR) {
            float s = 0.0f;
#pragma unroll
            for (int w = 0; w < 8; ++w) s += smf[SM_WSUM + w * 64 + tid];
            atomicAdd(&g_sumexp[t * RR + tid], s);
        } else if (tid < RR + Bb) {
            int gr2 = tid - RR;
            unsigned long long m = 0ull;
#pragma unroll
            for (int w = 0; w < 8; ++w) {
                unsigned long long k = wkey[w * 32 + gr2];
                m = (k > m) ? k : m;
            }
            atomicMax(&g_packmax[t * Bb + gr2], m);
        }
        gbar(2 * t + 1);
    }

    // final flush: probs for t=31 (sumexp[31] final after last gbar)
    {
        float inv = __fdividef(1.0f, g_sumexp[(Ss - 1) * RR + cb]);
#pragma unroll 2
        for (int i = 0; i < 14; ++i) {
            int col = cch + 16 * i;
            if (col < span) {
                float e = smf[SM_DS + col * DS_STRIDE + cb];
                pred[(cb * Ss + (Ss - 1)) * Vv + v0 + col] = e * inv;
            }
        }
    }

    // folded fin: block 128 computes last gen outputs + pretrain loss
    if (bid == 128) {
        __syncthreads();
        float ls = 0.0f;
#pragma unroll
        for (int q = 0; q < 2; ++q) {
            int idx = tid + q * 512;          // 0..1023 = t*32 + b (teacher rows)
            int tt = idx >> 5, b = idx & 31;
            ls += logf(g_sumexp[tt * RR + b]);
        }
        smf[SM_PART + tid] = ls;
        __syncthreads();
        for (int s = 256; s > 0; s >>= 1) {
            if (tid < s) smf[SM_PART + tid] += smf[SM_PART + tid + s];
            __syncthreads();
        }
        if (tid < Bb) {
            unsigned long long key = g_packmax[(Ss - 1) * Bb + tid];
            int tok = (int)(0xFFFFFFFFu - (unsigned)(key & 0xFFFFFFFFull));
            out[tid * Ss + (Ss - 1)] = (float)tok;
            float emax = ord2f((unsigned)(key >> 32));
            out[Bb * Ss + tid * Ss + (Ss - 1)] =
                emax / g_sumexp[(Ss - 1) * RR + Bb + tid];
        }
        if (tid == 0)
            out[PRED_OFF + PRED_N] = (smf[SM_PART] - g_loss) / (float)(Ss * Bb);
    }
}

// ---------------- launch ---------------------------------------------------
extern "C" void kernel_launch(void* const* d_in, const int* in_sizes, int n_in,
                              void* d_out, int out_size) {
    const int*   x   = (const int*)d_in[0];
    const float* emb = (const float*)d_in[1];
    const float* Wi  = (const float*)d_in[2];
    const float* Ui  = (const float*)d_in[3];
    const float* bi  = (const float*)d_in[4];
    const float* Wf  = (const float*)d_in[5];
    const float* Uf  = (const float*)d_in[6];
    const float* bf  = (const float*)d_in[7];
    const float* Wog = (const float*)d_in[8];
    const float* Uog = (const float*)d_in[9];
    const float* bog = (const float*)d_in[10];
    const float* Wc  = (const float*)d_in[11];
    const float* Uc  = (const float*)d_in[12];
    const float* bc  = (const float*)d_in[13];
    const float* Wo  = (const float*)d_in[14];
    const float* bo  = (const float*)d_in[15];
    float* out = (float*)d_out;

    cudaFuncSetAttribute(k_persist,
                         cudaFuncAttributeMaxDynamicSharedMemorySize,
                         SMEM_BYTES);

    k_prologue<<<Ss * Bb / 16, 512>>>(x, emb, Wi, bi, Wf, bf, Wog, bog, Wc, bc);
    k_persist<<<NBLK, NTHR, SMEM_BYTES>>>(x, emb,
                                          Wi, Ui, bi, Wf, Uf, bf,
                                          Wog, Uog, bog, Wc, Uc, bc,
                                          Wo, bo, out);
}